// round 7
// baseline (speedup 1.0000x reference)
#include <cuda_runtime.h>
#include <cuda_fp16.h>
#include <math.h>
#include <stdint.h>

#define BB 8
#define SS 2048
#define DD 512
#define FF_ 2048
#define HH 8
#define DH 64
#define TOPQ 39
#define NROWS (BB*SS)   /* 16384 */

// ---------------- static scratch ----------------
__device__ float g_xn  [NROWS*DD];
__device__ float g_x2  [NROWS*DD];
__device__ float g_kv  [NROWS*2*DD];
__device__ float g_cs  [BB*DD];
__device__ float g_cspart[16*BB*DD];
__device__ float g_sp  [BB*SS];
__device__ int   g_tidx[BB*TOPQ];
__device__ float g_qs  [BB*TOPQ*DD];
__device__ float g_ctxp[4*BB*TOPQ*DD];
__device__ float g_aout[BB*TOPQ*DD];
__device__ float g_scores[(size_t)BB*HH*TOPQ*SS];
// fp16 operand copies
__device__ __half g_xn16 [NROWS*DD];
__device__ __half g_xn2h [NROWS*DD];
__device__ __half g_h1h  [(size_t)NROWS*FF_];
__device__ __half g_wkv16[2*DD*DD];
__device__ __half g_w1h  [FF_*DD];
__device__ __half g_w2h  [DD*FF_];

// ---------------- helpers ----------------
__device__ __forceinline__ uint32_t s2u(const void* p) {
    uint32_t a;
    asm("{ .reg .u64 t; cvta.to.shared.u64 t, %1; cvt.u32.u64 %0, t; }" : "=r"(a) : "l"(p));
    return a;
}
__device__ __forceinline__ void mma_f16(float* d, const uint32_t* a, const uint32_t* b) {
    asm volatile("mma.sync.aligned.m16n8k16.row.col.f32.f16.f16.f32 "
        "{%0,%1,%2,%3}, {%4,%5,%6,%7}, {%8,%9}, {%0,%1,%2,%3};"
        : "+f"(d[0]), "+f"(d[1]), "+f"(d[2]), "+f"(d[3])
        : "r"(a[0]), "r"(a[1]), "r"(a[2]), "r"(a[3]), "r"(b[0]), "r"(b[1]));
}
__device__ __forceinline__ void ldsm4(uint32_t* r, uint32_t addr) {
    asm volatile("ldmatrix.sync.aligned.m8n8.x4.shared.b16 {%0,%1,%2,%3}, [%4];"
        : "=r"(r[0]), "=r"(r[1]), "=r"(r[2]), "=r"(r[3]) : "r"(addr));
}
__device__ __forceinline__ void cpa16(uint32_t dst, const void* src) {
    asm volatile("cp.async.cg.shared.global [%0], [%1], 16;" :: "r"(dst), "l"(src));
}
__device__ __forceinline__ void cpcommit() {
    asm volatile("cp.async.commit_group;" ::: "memory");
}
template<int N> __device__ __forceinline__ void cpwait() {
    asm volatile("cp.async.wait_group %0;" :: "n"(N) : "memory");
}
__device__ __forceinline__ float gelu_f(float x) {
    return 0.5f * x * (1.0f + erff(x * 0.7071067811865476f));
}

// ====================================================================
// fp16 GEMM, fp16 operands in gmem, 4-stage cp.async pipeline.
// (unchanged from R6 — held constant so the ncu capture is attributable)
// ====================================================================
#define HG_SMEM (4*16384)

template<int EPI, typename OutT>   // EPI: 0=none, 1=gelu, 2=+res
__global__ __launch_bounds__(256, 2) void hgemm(
    const __half* __restrict__ A, const __half* __restrict__ W,
    const float* __restrict__ bias, const float* __restrict__ res,
    OutT* __restrict__ C, int N, int K)
{
    extern __shared__ __align__(16) char smh[];
    const int tid  = threadIdx.x;
    const int lane = tid & 31;
    const int wid  = tid >> 5;
    const int wm   = wid >> 2;
    const int wn   = wid & 3;
    const int bm = blockIdx.y * 128;
    const int bn = blockIdx.x * 128;
    const uint32_t sb = s2u(smh);

    const __half* Ab = A + (size_t)bm * K;
    const __half* Wb = W + (size_t)bn * K;

    const int crow0 = tid >> 2;
    const int cunit = tid & 3;

    auto ISSUE = [&](int buf, int kbase) {
        uint32_t base = sb + buf * 16384;
        #pragma unroll
        for (int i = 0; i < 2; i++) {
            int row = crow0 + i * 64;
            uint32_t off = row*64 + ((cunit ^ (row&3))*16);
            cpa16(base + off,        Ab + (size_t)row*K + kbase + cunit*8);
            cpa16(base + 8192 + off, Wb + (size_t)row*K + kbase + cunit*8);
        }
        cpcommit();
    };

    float acc[4][4][4];
    #pragma unroll
    for (int a = 0; a < 4; a++)
        #pragma unroll
        for (int b = 0; b < 4; b++)
            #pragma unroll
            for (int c = 0; c < 4; c++) acc[a][b][c] = 0.f;

    const int nk = K >> 5;
    const int lm = lane >> 3;
    const int lr = lane & 7;

    ISSUE(0, 0);
    ISSUE(1, 32);
    ISSUE(2, 64);

    for (int kt = 0; kt < nk; kt++) {
        cpwait<2>();
        __syncthreads();
        if (kt + 3 < nk) ISSUE((kt + 3) & 3, (kt + 3) << 5);
        else             cpcommit();

        int buf = kt & 3;
        uint32_t Abase = sb + buf*16384;
        uint32_t Bbase = Abase + 8192;
        #pragma unroll
        for (int s = 0; s < 2; s++) {
            uint32_t af[4][4];
            #pragma unroll
            for (int mt = 0; mt < 4; mt++) {
                int row = wm*64 + mt*16 + (lm&1)*8 + lr;
                int unit = s*2 + (lm>>1);
                ldsm4(af[mt], Abase + row*64 + ((unit ^ (row&3))*16));
            }
            uint32_t bf[4][2];
            #pragma unroll
            for (int np = 0; np < 2; np++) {
                int nr = wn*32 + (np*2 + (lm>>1))*8 + lr;
                int unit = s*2 + (lm&1);
                uint32_t r[4];
                ldsm4(r, Bbase + nr*64 + ((unit ^ (nr&3))*16));
                bf[np*2][0] = r[0]; bf[np*2][1] = r[1];
                bf[np*2+1][0] = r[2]; bf[np*2+1][1] = r[3];
            }
            #pragma unroll
            for (int mt = 0; mt < 4; mt++)
                #pragma unroll
                for (int nt = 0; nt < 4; nt++)
                    mma_f16(acc[mt][nt], af[mt], bf[nt]);
        }
    }

    const int g = lane >> 2, t = lane & 3;
    #pragma unroll
    for (int mt = 0; mt < 4; mt++) {
        int row0 = bm + wm*64 + mt*16 + g;
        #pragma unroll
        for (int nt = 0; nt < 4; nt++) {
            int col = bn + wn*32 + nt*8 + 2*t;
            float b0 = bias[col], b1 = bias[col+1];
            float v0 = acc[mt][nt][0] + b0;
            float v1 = acc[mt][nt][1] + b1;
            float v2 = acc[mt][nt][2] + b0;
            float v3 = acc[mt][nt][3] + b1;
            if (EPI == 1) {
                v0 = gelu_f(v0); v1 = gelu_f(v1); v2 = gelu_f(v2); v3 = gelu_f(v3);
            }
            if (EPI == 2) {
                const float* r0 = res + (size_t)row0*N + col;
                const float* r1 = res + (size_t)(row0+8)*N + col;
                v0 += r0[0]; v1 += r0[1]; v2 += r1[0]; v3 += r1[1];
            }
            if constexpr (sizeof(OutT) == 2) {
                *(__half2*)&C[(size_t)row0*N + col]     = __floats2half2_rn(v0, v1);
                *(__half2*)&C[(size_t)(row0+8)*N + col] = __floats2half2_rn(v2, v3);
            } else {
                *(float2*)&C[(size_t)row0*N + col]     = make_float2(v0, v1);
                *(float2*)&C[(size_t)(row0+8)*N + col] = make_float2(v2, v3);
            }
        }
    }
}

// ---------------- fp32 -> fp16 bulk convert ----------------
__global__ void f2h_kernel(const float* __restrict__ src, __half* __restrict__ dst, int n4)
{
    int i = blockIdx.x * 256 + threadIdx.x;
    if (i < n4) {
        float4 v = ((const float4*)src)[i];
        ((__half2*)dst)[2*i]   = __floats2half2_rn(v.x, v.y);
        ((__half2*)dst)[2*i+1] = __floats2half2_rn(v.z, v.w);
    }
}

// ---------------- layernorm1: warp per row ----------------
__global__ __launch_bounds__(256) void lnw_kernel(const float* __restrict__ x,
        const float* __restrict__ g, const float* __restrict__ bb,
        float* __restrict__ out, __half* __restrict__ out16)
{
    int row  = blockIdx.x * 8 + (threadIdx.x >> 5);
    int lane = threadIdx.x & 31;
    const float4* xr = (const float4*)x + (size_t)row*(DD/4);
    float4 v[4];
    #pragma unroll
    for (int j = 0; j < 4; j++) v[j] = xr[lane + 32*j];
    float s = 0.f;
    #pragma unroll
    for (int j = 0; j < 4; j++) s += v[j].x + v[j].y + v[j].z + v[j].w;
    #pragma unroll
    for (int o = 16; o > 0; o >>= 1) s += __shfl_xor_sync(0xffffffffu, s, o);
    float mean = s * (1.0f/DD);
    float q = 0.f;
    #pragma unroll
    for (int j = 0; j < 4; j++) {
        float a = v[j].x-mean, b = v[j].y-mean, c = v[j].z-mean, d = v[j].w-mean;
        q += a*a + b*b + c*c + d*d;
    }
    #pragma unroll
    for (int o = 16; o > 0; o >>= 1) q += __shfl_xor_sync(0xffffffffu, q, o);
    float inv = rsqrtf(q * (1.0f/DD) + 1e-5f);
    #pragma unroll
    for (int j = 0; j < 4; j++) {
        float4 gg = ((const float4*)g)[lane + 32*j];
        float4 bv = ((const float4*)bb)[lane + 32*j];
        float4 o4 = make_float4(
            (v[j].x-mean)*inv*gg.x + bv.x, (v[j].y-mean)*inv*gg.y + bv.y,
            (v[j].z-mean)*inv*gg.z + bv.z, (v[j].w-mean)*inv*gg.w + bv.w);
        if (out) ((float4*)out)[(size_t)row*(DD/4) + lane + 32*j] = o4;
        if (out16) {
            int base = (int)(lane + 32*j);
            ((__half2*)(out16 + (size_t)row*DD))[2*base]   = __floats2half2_rn(o4.x, o4.y);
            ((__half2*)(out16 + (size_t)row*DD))[2*base+1] = __floats2half2_rn(o4.z, o4.w);
        }
    }
}

// ---------------- fused: residual(base|scatter) + layernorm2 ----------------
// x2 = x + (row in topk ? aout[slot] : cs/S); then LN(x2) -> xn2h.
// Grid NROWS/8; 8 rows per block, all in one batch (2048 % 8 == 0).
__global__ __launch_bounds__(256) void lnfuse_kernel(const float* __restrict__ x,
        const float* __restrict__ cs, const float* __restrict__ aout,
        const int* __restrict__ tidx,
        const float* __restrict__ g, const float* __restrict__ bb,
        float* __restrict__ x2, __half* __restrict__ out16)
{
    int row  = blockIdx.x * 8 + (threadIdx.x >> 5);
    int lane = threadIdx.x & 31;
    int b    = row >> 11;
    int rin  = row & (SS-1);
    __shared__ int stid[TOPQ];
    if (threadIdx.x < TOPQ) stid[threadIdx.x] = tidx[b*TOPQ + threadIdx.x];
    __syncthreads();
    int slot = -1;
    #pragma unroll
    for (int j = 0; j < TOPQ; j++) if (stid[j] == rin) slot = j;

    const float4* xr = (const float4*)x + (size_t)row*(DD/4);
    float4 v[4];
    #pragma unroll
    for (int j = 0; j < 4; j++) v[j] = xr[lane + 32*j];
    if (slot >= 0) {
        const float4* ar = (const float4*)aout + (size_t)(b*TOPQ + slot)*(DD/4);
        #pragma unroll
        for (int j = 0; j < 4; j++) {
            float4 a = ar[lane + 32*j];
            v[j].x += a.x; v[j].y += a.y; v[j].z += a.z; v[j].w += a.w;
        }
    } else {
        const float4* cr = (const float4*)cs + b*(DD/4);
        const float r = 1.0f / SS;
        #pragma unroll
        for (int j = 0; j < 4; j++) {
            float4 c = cr[lane + 32*j];
            v[j].x += c.x*r; v[j].y += c.y*r; v[j].z += c.z*r; v[j].w += c.w*r;
        }
    }
    // write x2 (residual input to FFN2)
    #pragma unroll
    for (int j = 0; j < 4; j++)
        ((float4*)x2)[(size_t)row*(DD/4) + lane + 32*j] = v[j];
    // layernorm
    float s = 0.f;
    #pragma unroll
    for (int j = 0; j < 4; j++) s += v[j].x + v[j].y + v[j].z + v[j].w;
    #pragma unroll
    for (int o = 16; o > 0; o >>= 1) s += __shfl_xor_sync(0xffffffffu, s, o);
    float mean = s * (1.0f/DD);
    float q = 0.f;
    #pragma unroll
    for (int j = 0; j < 4; j++) {
        float a = v[j].x-mean, bq = v[j].y-mean, c = v[j].z-mean, d = v[j].w-mean;
        q += a*a + bq*bq + c*c + d*d;
    }
    #pragma unroll
    for (int o = 16; o > 0; o >>= 1) q += __shfl_xor_sync(0xffffffffu, q, o);
    float inv = rsqrtf(q * (1.0f/DD) + 1e-5f);
    #pragma unroll
    for (int j = 0; j < 4; j++) {
        float4 gg = ((const float4*)g)[lane + 32*j];
        float4 bv = ((const float4*)bb)[lane + 32*j];
        float4 o4 = make_float4(
            (v[j].x-mean)*inv*gg.x + bv.x, (v[j].y-mean)*inv*gg.y + bv.y,
            (v[j].z-mean)*inv*gg.z + bv.z, (v[j].w-mean)*inv*gg.w + bv.w);
        int base = (int)(lane + 32*j);
        ((__half2*)(out16 + (size_t)row*DD))[2*base]   = __floats2half2_rn(o4.x, o4.y);
        ((__half2*)(out16 + (size_t)row*DD))[2*base+1] = __floats2half2_rn(o4.z, o4.w);
    }
}

// ---------------- column sums, two-stage deterministic ----------------
__global__ void colsum1_kernel(const float* __restrict__ xn, float* __restrict__ part)
{
    int b = blockIdx.y;
    int c = blockIdx.z;
    int d = blockIdx.x * 128 + threadIdx.x;
    const float* p = xn + (size_t)b*SS*DD + (size_t)c*128*DD + d;
    float s = 0.f;
    #pragma unroll 8
    for (int k = 0; k < 128; k++) s += p[(size_t)k*DD];
    part[((size_t)c*BB + b)*DD + d] = s;
}
__global__ void colsum2_kernel(const float* __restrict__ part, float* __restrict__ cs)
{
    int i = blockIdx.x * 256 + threadIdx.x;
    if (i < BB*DD) {
        float s = 0.f;
        #pragma unroll
        for (int c = 0; c < 16; c++) s += part[(size_t)c*BB*DD + i];
        cs[i] = s;
    }
}

// ---------------- sparsity: warp per row ----------------
__global__ __launch_bounds__(256) void sparsw_kernel(const float* __restrict__ xn,
        const float* __restrict__ cs, float* __restrict__ sp)
{
    int row  = blockIdx.x * 8 + (threadIdx.x >> 5);
    int lane = threadIdx.x & 31;
    int b = row >> 11;
    const float4* xr = (const float4*)xn + (size_t)row*(DD/4);
    const float4* cr = (const float4*)cs + b*(DD/4);
    float dp = 0.f, de = 0.f, mp = 0.f, me = 0.f;
    #pragma unroll
    for (int j = 0; j < 4; j++) {
        float4 v = xr[lane + 32*j];
        float4 c = cr[lane + 32*j];
        float vv[4] = {v.x, v.y, v.z, v.w};
        float cc[4] = {c.x, c.y, c.z, c.w};
        #pragma unroll
        for (int e = 0; e < 4; e++) {
            float p = vv[e]*vv[e];
            de += fmaf(vv[e], vv[e], -p);
            dp += p;
            float q = vv[e]*cc[e];
            me += fmaf(vv[e], cc[e], -q);
            mp += q;
        }
    }
    double dd = (double)dp + (double)de;
    double dm = (double)mp + (double)me;
    #pragma unroll
    for (int o = 16; o > 0; o >>= 1) {
        dd += __shfl_xor_sync(0xffffffffu, dd, o);
        dm += __shfl_xor_sync(0xffffffffu, dm, o);
    }
    if (lane == 0)
        sp[row] = (float)((dd - dm * (1.0/SS)) * 0.04419417382415922);
}

// ---------------- top-39 ----------------
__global__ __launch_bounds__(256) void topk_kernel(const float* __restrict__ sp,
        int* __restrict__ tidx)
{
    int b = blockIdx.x;
    int t = threadIdx.x;
    __shared__ float sv[SS];
    __shared__ float rbv[8];
    __shared__ int   rbi[8];
    for (int i = t; i < SS; i += 256) sv[i] = sp[b*SS + i];
    __syncthreads();
    for (int sel = 0; sel < TOPQ; ++sel) {
        float bv = -3.0e38f; int bi = 0;
        for (int i = t; i < SS; i += 256) {
            float v = sv[i];
            if (v > bv || (v == bv && i < bi)) { bv = v; bi = i; }
        }
        #pragma unroll
        for (int o = 16; o > 0; o >>= 1) {
            float ov = __shfl_down_sync(0xffffffffu, bv, o);
            int   oi = __shfl_down_sync(0xffffffffu, bi, o);
            if (ov > bv || (ov == bv && oi < bi)) { bv = ov; bi = oi; }
        }
        if ((t & 31) == 0) { rbv[t >> 5] = bv; rbi[t >> 5] = bi; }
        __syncthreads();
        if (t == 0) {
            float fv = rbv[0]; int fi = rbi[0];
            #pragma unroll
            for (int w = 1; w < 8; w++)
                if (rbv[w] > fv || (rbv[w] == fv && rbi[w] < fi)) { fv = rbv[w]; fi = rbi[w]; }
            tidx[b*TOPQ + sel] = fi;
            sv[fi] = -3.4e38f;
        }
        __syncthreads();
    }
}

// ---------------- small row projection ----------------
__global__ __launch_bounds__(256) void rowproj_kernel(const float* __restrict__ src,
        const int* __restrict__ gidx, const float* __restrict__ part,
        const float* __restrict__ W, const float* __restrict__ bias,
        float* __restrict__ out)
{
    int r = blockIdx.x;
    __shared__ float xr[DD];
    if (part) {
        const int N4 = BB*TOPQ*DD/4;
        const float4* p = (const float4*)part;
        for (int i = threadIdx.x; i < DD/4; i += 256) {
            int idx = r*(DD/4) + i;
            float4 a = p[idx], b = p[idx+N4], c = p[idx+2*N4], d = p[idx+3*N4];
            ((float4*)xr)[i] = make_float4(a.x+b.x+c.x+d.x, a.y+b.y+c.y+d.y,
                                           a.z+b.z+c.z+d.z, a.w+b.w+c.w+d.w);
        }
    } else {
        const float* srow;
        if (gidx) { int b = r / TOPQ; srow = src + ((size_t)b*SS + gidx[r]) * DD; }
        else        srow = src + (size_t)r * DD;
        for (int i = threadIdx.x; i < DD/4; i += 256)
            ((float4*)xr)[i] = ((const float4*)srow)[i];
    }
    __syncthreads();
    for (int j = threadIdx.x; j < DD; j += 256) {
        const float4* w4 = (const float4*)(W + (size_t)j*DD);
        float acc = 0.f;
        #pragma unroll 4
        for (int k = 0; k < DD/4; k++) {
            float4 w = w4[k]; float4 xv = ((float4*)xr)[k];
            acc = fmaf(w.x, xv.x, fmaf(w.y, xv.y, fmaf(w.z, xv.z, fmaf(w.w, xv.w, acc))));
        }
        out[(size_t)r*DD + j] = acc + bias[j];
    }
}

// ---------------- attention: scores ----------------
__global__ __launch_bounds__(256) void scorek_kernel(const float* __restrict__ qs,
        const float* __restrict__ kv, float* __restrict__ sc)
{
    int kt = blockIdx.x, h = blockIdx.y, b = blockIdx.z;
    __shared__ float Qt[DH][TOPQ+1];
    __shared__ float Ks[128][DH];
    int tid = threadIdx.x;
    for (int i = tid; i < TOPQ*DH; i += 256) {
        int q = i % TOPQ, d = i / TOPQ;
        Qt[d][q] = qs[((size_t)(b*TOPQ+q))*DD + h*DH + d];
    }
    for (int i = tid; i < 128*16; i += 256) {
        int row = i >> 4, c4 = i & 15;
        *(float4*)&Ks[row][c4*4] =
            *(const float4*)(kv + ((size_t)(b*SS + kt*128 + row))*(2*DD) + h*DH + c4*4);
    }
    __syncthreads();
    for (int p = tid; p < TOPQ*128; p += 256) {
        int q = p % TOPQ, k = p / TOPQ;
        float a = 0.f;
        #pragma unroll 8
        for (int d = 0; d < DH; d++) a = fmaf(Qt[d][q], Ks[k][d], a);
        sc[((size_t)(b*HH+h)*TOPQ + q)*SS + kt*128 + k] = a * 0.125f;
    }
}

// ---------------- attention: row softmax ----------------
__global__ __launch_bounds__(256) void softmax_kernel(float* __restrict__ sc)
{
    size_t base = (size_t)blockIdx.x * SS;
    int t = threadIdx.x;
    float4* p = (float4*)(sc + base);
    float4 v0 = p[t], v1 = p[t + 256];
    __shared__ float red[8];
    float m = fmaxf(fmaxf(fmaxf(v0.x, v0.y), fmaxf(v0.z, v0.w)),
                    fmaxf(fmaxf(v1.x, v1.y), fmaxf(v1.z, v1.w)));
    #pragma unroll
    for (int o = 16; o > 0; o >>= 1) m = fmaxf(m, __shfl_down_sync(0xffffffffu, m, o));
    if ((t & 31) == 0) red[t >> 5] = m;
    __syncthreads();
    m = red[0];
    #pragma unroll
    for (int w = 1; w < 8; w++) m = fmaxf(m, red[w]);
    __syncthreads();
    v0.x = __expf(v0.x - m); v0.y = __expf(v0.y - m);
    v0.z = __expf(v0.z - m); v0.w = __expf(v0.w - m);
    v1.x = __expf(v1.x - m); v1.y = __expf(v1.y - m);
    v1.z = __expf(v1.z - m); v1.w = __expf(v1.w - m);
    float s = v0.x+v0.y+v0.z+v0.w + v1.x+v1.y+v1.z+v1.w;
    #pragma unroll
    for (int o = 16; o > 0; o >>= 1) s += __shfl_down_sync(0xffffffffu, s, o);
    if ((t & 31) == 0) red[t >> 5] = s;
    __syncthreads();
    float tot = red[0]+red[1]+red[2]+red[3]+red[4]+red[5]+red[6]+red[7];
    float inv = 1.0f / tot;
    v0.x*=inv; v0.y*=inv; v0.z*=inv; v0.w*=inv;
    v1.x*=inv; v1.y*=inv; v1.z*=inv; v1.w*=inv;
    p[t] = v0; p[t + 256] = v1;
}

// ---------------- attention: probs @ V ----------------
__global__ __launch_bounds__(256) void ctxv_kernel(const float* __restrict__ pr_g,
        const float* __restrict__ kv, float* __restrict__ part)
{
    int g = blockIdx.x, h = blockIdx.y, b = blockIdx.z;
    __shared__ float Vt[64][64];
    __shared__ float Pt[TOPQ][64];
    int tid = threadIdx.x, w = tid >> 5, lid = tid & 31;
    float acc[5][2];
    #pragma unroll
    for (int i = 0; i < 5; i++) { acc[i][0] = 0.f; acc[i][1] = 0.f; }
    for (int t = 0; t < 8; t++) {
        int k0 = g * 512 + t * 64;
        for (int i = tid; i < 64*16; i += 256) {
            int row = i >> 4, c4 = i & 15;
            *(float4*)&Vt[row][c4*4] =
                *(const float4*)(kv + ((size_t)(b*SS + k0 + row))*(2*DD) + DD + h*DH + c4*4);
        }
        for (int i = tid; i < TOPQ*64; i += 256) {
            int q = i >> 6, kk = i & 63;
            Pt[q][kk] = pr_g[((size_t)(b*HH+h)*TOPQ + q)*SS + k0 + kk];
        }
        __syncthreads();
        int ii = 0;
        for (int q = w; q < TOPQ; q += 8, ii++) {
            float a0 = acc[ii][0], a1 = acc[ii][1];
            #pragma unroll 8
            for (int kk = 0; kk < 64; kk++) {
                float2 v = *(float2*)&Vt[kk][2*lid];
                float pp = Pt[q][kk];
                a0 = fmaf(pp, v.x, a0); a1 = fmaf(pp, v.y, a1);
            }
            acc[ii][0] = a0; acc[ii][1] = a1;
        }
        __syncthreads();
    }
    int ii = 0;
    for (int q = w; q < TOPQ; q += 8, ii++) {
        float* dst = part + (size_t)g*(BB*TOPQ*DD) + ((size_t)(b*TOPQ+q))*DD + h*DH + 2*lid;
        *(float2*)dst = make_float2(acc[ii][0], acc[ii][1]);
    }
}

// ---------------- ratio tail ----------------
__global__ void ratio_kernel(float* out, int out_size)
{
    int i = NROWS*DD + blockIdx.x*blockDim.x + threadIdx.x;
    if (i < out_size) out[i] = (float)TOPQ / (float)SS;
}

// ---------------- launch ----------------
extern "C" void kernel_launch(void* const* d_in, const int* in_sizes, int n_in,
                              void* d_out, int out_size)
{
    const float* x    = (const float*)d_in[0];
    const float* ln1g = (const float*)d_in[1];
    const float* ln1b = (const float*)d_in[2];
    const float* in_w = (const float*)d_in[3];
    const float* in_b = (const float*)d_in[4];
    const float* outw = (const float*)d_in[5];
    const float* outb = (const float*)d_in[6];
    const float* ln2g = (const float*)d_in[7];
    const float* ln2b = (const float*)d_in[8];
    const float* w1   = (const float*)d_in[9];
    const float* b1   = (const float*)d_in[10];
    const float* w2   = (const float*)d_in[11];
    const float* b2   = (const float*)d_in[12];
    float* out = (float*)d_out;

    float *xn, *x2, *kv, *cs, *csp, *sp, *qs, *ctxp, *aout, *scores;
    __half *xn16, *xn2h, *h1h, *wkv16, *w1h, *w2h;
    int *tidx;
    cudaGetSymbolAddress((void**)&xn,    g_xn);
    cudaGetSymbolAddress((void**)&x2,    g_x2);
    cudaGetSymbolAddress((void**)&kv,    g_kv);
    cudaGetSymbolAddress((void**)&cs,    g_cs);
    cudaGetSymbolAddress((void**)&csp,   g_cspart);
    cudaGetSymbolAddress((void**)&sp,    g_sp);
    cudaGetSymbolAddress((void**)&qs,    g_qs);
    cudaGetSymbolAddress((void**)&ctxp,  g_ctxp);
    cudaGetSymbolAddress((void**)&aout,  g_aout);
    cudaGetSymbolAddress((void**)&scores,g_scores);
    cudaGetSymbolAddress((void**)&tidx,  g_tidx);
    cudaGetSymbolAddress((void**)&xn16,  g_xn16);
    cudaGetSymbolAddress((void**)&xn2h,  g_xn2h);
    cudaGetSymbolAddress((void**)&h1h,   g_h1h);
    cudaGetSymbolAddress((void**)&wkv16, g_wkv16);
    cudaGetSymbolAddress((void**)&w1h,   g_w1h);
    cudaGetSymbolAddress((void**)&w2h,   g_w2h);

    cudaFuncSetAttribute(hgemm<0, float>,  cudaFuncAttributeMaxDynamicSharedMemorySize, HG_SMEM);
    cudaFuncSetAttribute(hgemm<1, __half>, cudaFuncAttributeMaxDynamicSharedMemorySize, HG_SMEM);
    cudaFuncSetAttribute(hgemm<2, float>,  cudaFuncAttributeMaxDynamicSharedMemorySize, HG_SMEM);

    // launches 1-3: weight conversions
    f2h_kernel<<<(2*DD*DD/4 + 255)/256, 256>>>(in_w + (size_t)DD*DD, wkv16, 2*DD*DD/4);
    f2h_kernel<<<(FF_*DD/4 + 255)/256, 256>>>(w1, w1h, FF_*DD/4);
    f2h_kernel<<<(DD*FF_/4 + 255)/256, 256>>>(w2, w2h, DD*FF_/4);
    // launch 4: layernorm1
    lnw_kernel<<<NROWS/8, 256>>>(x, ln1g, ln1b, xn, xn16);
    // launch 5: colsum stage 1
    colsum1_kernel<<<dim3(DD/128, BB, 16), 128>>>(xn, csp);
    // launch 6: KV projection  <-- ncu -s 5 -c 1 captures THIS
    hgemm<0, float><<<dim3((2*DD)/128, NROWS/128), 256, HG_SMEM>>>(
        xn16, wkv16, in_b + DD, nullptr, kv, 2*DD, DD);
    // rest of ranking chain
    colsum2_kernel<<<(BB*DD + 255)/256, 256>>>(csp, cs);
    sparsw_kernel<<<NROWS/8, 256>>>(xn, cs, sp);
    topk_kernel<<<BB, 256>>>(sp, tidx);
    rowproj_kernel<<<BB*TOPQ, 256>>>(xn, tidx, nullptr, in_w, in_b, qs);
    // attention
    scorek_kernel<<<dim3(SS/128, HH, BB), 256>>>(qs, kv, scores);
    softmax_kernel<<<BB*HH*TOPQ, 256>>>(scores);
    ctxv_kernel<<<dim3(4, HH, BB), 256>>>(scores, kv, ctxp);
    rowproj_kernel<<<BB*TOPQ, 256>>>(nullptr, nullptr, ctxp, outw, outb, aout);
    // fused residual + layernorm2
    lnfuse_kernel<<<NROWS/8, 256>>>(x, cs, aout, tidx, ln2g, ln2b, x2, xn2h);
    // FFN
    hgemm<1, __half><<<dim3(FF_/128, NROWS/128), 256, HG_SMEM>>>(
        xn2h, w1h, b1, nullptr, h1h, FF_, DD);
    hgemm<2, float><<<dim3(DD/128, NROWS/128), 256, HG_SMEM>>>(
        h1h, w2h, b2, x2, out, DD, FF_);
    // ratio tail
    if (out_size > NROWS*DD) {
        int tail = out_size - NROWS*DD;
        ratio_kernel<<<(tail + 255)/256, 256>>>(out, out_size);
    }
}

// round 8
// speedup vs baseline: 1.1331x; 1.1331x over previous
#include <cuda_runtime.h>
#include <cuda_fp16.h>
#include <math.h>
#include <stdint.h>

#define BB 8
#define SS 2048
#define DD 512
#define FF_ 2048
#define HH 8
#define DH 64
#define TOPQ 39
#define QPW 5
#define NROWS (BB*SS)   /* 16384 */

// ---------------- static scratch ----------------
__device__ float g_xn  [NROWS*DD];
__device__ float g_x2  [NROWS*DD];
__device__ float g_cs  [BB*DD];
__device__ float g_cspart[16*BB*DD];
__device__ float g_sp  [BB*SS];
__device__ int   g_tidx[BB*TOPQ];
__device__ float g_qs  [BB*TOPQ*DD];
__device__ float g_ctxp[4*BB*TOPQ*DD];
__device__ float2 g_ml [4*BB*HH*TOPQ];
__device__ float g_aout[BB*TOPQ*DD];
// fp16 operands
__device__ __half g_kvh  [NROWS*2*DD];
__device__ __half g_xn16 [NROWS*DD];
__device__ __half g_xn2h [NROWS*DD];
__device__ __half g_h1h  [(size_t)NROWS*FF_];
__device__ __half g_wkv16[2*DD*DD];
__device__ __half g_w1h  [FF_*DD];
__device__ __half g_w2h  [DD*FF_];

// ---------------- helpers ----------------
__device__ __forceinline__ uint32_t s2u(const void* p) {
    uint32_t a;
    asm("{ .reg .u64 t; cvta.to.shared.u64 t, %1; cvt.u32.u64 %0, t; }" : "=r"(a) : "l"(p));
    return a;
}
__device__ __forceinline__ void mma_f16(float* d, const uint32_t* a, const uint32_t* b) {
    asm volatile("mma.sync.aligned.m16n8k16.row.col.f32.f16.f16.f32 "
        "{%0,%1,%2,%3}, {%4,%5,%6,%7}, {%8,%9}, {%0,%1,%2,%3};"
        : "+f"(d[0]), "+f"(d[1]), "+f"(d[2]), "+f"(d[3])
        : "r"(a[0]), "r"(a[1]), "r"(a[2]), "r"(a[3]), "r"(b[0]), "r"(b[1]));
}
__device__ __forceinline__ void ldsm4(uint32_t* r, uint32_t addr) {
    asm volatile("ldmatrix.sync.aligned.m8n8.x4.shared.b16 {%0,%1,%2,%3}, [%4];"
        : "=r"(r[0]), "=r"(r[1]), "=r"(r[2]), "=r"(r[3]) : "r"(addr));
}
__device__ __forceinline__ void cpa16(uint32_t dst, const void* src) {
    asm volatile("cp.async.cg.shared.global [%0], [%1], 16;" :: "r"(dst), "l"(src));
}
__device__ __forceinline__ void cpcommit() {
    asm volatile("cp.async.commit_group;" ::: "memory");
}
template<int N> __device__ __forceinline__ void cpwait() {
    asm volatile("cp.async.wait_group %0;" :: "n"(N) : "memory");
}
__device__ __forceinline__ float gelu_f(float x) {
    return 0.5f * x * (1.0f + erff(x * 0.7071067811865476f));
}

// ====================================================================
// fp16 GEMM, fp16 operands, 4-stage cp.async pipeline (structure held).
// ====================================================================
#define HG_SMEM (4*16384)

template<int EPI, typename OutT>   // EPI: 0=none, 1=gelu, 2=+res
__global__ __launch_bounds__(256, 2) void hgemm(
    const __half* __restrict__ A, const __half* __restrict__ W,
    const float* __restrict__ bias, const float* __restrict__ res,
    OutT* __restrict__ C, int N, int K)
{
    extern __shared__ __align__(16) char smh[];
    const int tid  = threadIdx.x;
    const int lane = tid & 31;
    const int wid  = tid >> 5;
    const int wm   = wid >> 2;
    const int wn   = wid & 3;
    const int bm = blockIdx.y * 128;
    const int bn = blockIdx.x * 128;
    const uint32_t sb = s2u(smh);

    const __half* Ab = A + (size_t)bm * K;
    const __half* Wb = W + (size_t)bn * K;

    const int crow0 = tid >> 2;
    const int cunit = tid & 3;

    auto ISSUE = [&](int buf, int kbase) {
        uint32_t base = sb + buf * 16384;
        #pragma unroll
        for (int i = 0; i < 2; i++) {
            int row = crow0 + i * 64;
            uint32_t off = row*64 + ((cunit ^ (row&3))*16);
            cpa16(base + off,        Ab + (size_t)row*K + kbase + cunit*8);
            cpa16(base + 8192 + off, Wb + (size_t)row*K + kbase + cunit*8);
        }
        cpcommit();
    };

    float acc[4][4][4];
    #pragma unroll
    for (int a = 0; a < 4; a++)
        #pragma unroll
        for (int b = 0; b < 4; b++)
            #pragma unroll
            for (int c = 0; c < 4; c++) acc[a][b][c] = 0.f;

    const int nk = K >> 5;
    const int lm = lane >> 3;
    const int lr = lane & 7;

    ISSUE(0, 0);
    ISSUE(1, 32);
    ISSUE(2, 64);

    for (int kt = 0; kt < nk; kt++) {
        cpwait<2>();
        __syncthreads();
        if (kt + 3 < nk) ISSUE((kt + 3) & 3, (kt + 3) << 5);
        else             cpcommit();

        int buf = kt & 3;
        uint32_t Abase = sb + buf*16384;
        uint32_t Bbase = Abase + 8192;
        #pragma unroll
        for (int s = 0; s < 2; s++) {
            uint32_t af[4][4];
            #pragma unroll
            for (int mt = 0; mt < 4; mt++) {
                int row = wm*64 + mt*16 + (lm&1)*8 + lr;
                int unit = s*2 + (lm>>1);
                ldsm4(af[mt], Abase + row*64 + ((unit ^ (row&3))*16));
            }
            uint32_t bf[4][2];
            #pragma unroll
            for (int np = 0; np < 2; np++) {
                int nr = wn*32 + (np*2 + (lm>>1))*8 + lr;
                int unit = s*2 + (lm&1);
                uint32_t r[4];
                ldsm4(r, Bbase + nr*64 + ((unit ^ (nr&3))*16));
                bf[np*2][0] = r[0]; bf[np*2][1] = r[1];
                bf[np*2+1][0] = r[2]; bf[np*2+1][1] = r[3];
            }
            #pragma unroll
            for (int mt = 0; mt < 4; mt++)
                #pragma unroll
                for (int nt = 0; nt < 4; nt++)
                    mma_f16(acc[mt][nt], af[mt], bf[nt]);
        }
    }

    const int g = lane >> 2, t = lane & 3;
    #pragma unroll
    for (int mt = 0; mt < 4; mt++) {
        int row0 = bm + wm*64 + mt*16 + g;
        #pragma unroll
        for (int nt = 0; nt < 4; nt++) {
            int col = bn + wn*32 + nt*8 + 2*t;
            float b0 = bias[col], b1 = bias[col+1];
            float v0 = acc[mt][nt][0] + b0;
            float v1 = acc[mt][nt][1] + b1;
            float v2 = acc[mt][nt][2] + b0;
            float v3 = acc[mt][nt][3] + b1;
            if (EPI == 1) {
                v0 = gelu_f(v0); v1 = gelu_f(v1); v2 = gelu_f(v2); v3 = gelu_f(v3);
            }
            if (EPI == 2) {
                const float* r0 = res + (size_t)row0*N + col;
                const float* r1 = res + (size_t)(row0+8)*N + col;
                v0 += r0[0]; v1 += r0[1]; v2 += r1[0]; v3 += r1[1];
            }
            if constexpr (sizeof(OutT) == 2) {
                *(__half2*)&C[(size_t)row0*N + col]     = __floats2half2_rn(v0, v1);
                *(__half2*)&C[(size_t)(row0+8)*N + col] = __floats2half2_rn(v2, v3);
            } else {
                *(float2*)&C[(size_t)row0*N + col]     = make_float2(v0, v1);
                *(float2*)&C[(size_t)(row0+8)*N + col] = make_float2(v2, v3);
            }
        }
    }
}

// ---------------- fp32 -> fp16 bulk convert (3 regions, one launch) --------
__global__ void f2h3_kernel(const float* __restrict__ a, __half* __restrict__ da, int na4,
                            const float* __restrict__ b, __half* __restrict__ db, int nb4,
                            const float* __restrict__ c, __half* __restrict__ dc, int nc4)
{
    int i = blockIdx.x * 256 + threadIdx.x;
    const float* s; __half* d; int j = i;
    if (j < na4) { s = a; d = da; }
    else {
        j -= na4;
        if (j < nb4) { s = b; d = db; }
        else { j -= nb4; if (j >= nc4) return; s = c; d = dc; }
    }
    float4 v = ((const float4*)s)[j];
    ((__half2*)d)[2*j]   = __floats2half2_rn(v.x, v.y);
    ((__half2*)d)[2*j+1] = __floats2half2_rn(v.z, v.w);
}

// ---------------- layernorm1: warp per row ----------------
__global__ __launch_bounds__(256) void lnw_kernel(const float* __restrict__ x,
        const float* __restrict__ g, const float* __restrict__ bb,
        float* __restrict__ out, __half* __restrict__ out16)
{
    int row  = blockIdx.x * 8 + (threadIdx.x >> 5);
    int lane = threadIdx.x & 31;
    const float4* xr = (const float4*)x + (size_t)row*(DD/4);
    float4 v[4];
    #pragma unroll
    for (int j = 0; j < 4; j++) v[j] = xr[lane + 32*j];
    float s = 0.f;
    #pragma unroll
    for (int j = 0; j < 4; j++) s += v[j].x + v[j].y + v[j].z + v[j].w;
    #pragma unroll
    for (int o = 16; o > 0; o >>= 1) s += __shfl_xor_sync(0xffffffffu, s, o);
    float mean = s * (1.0f/DD);
    float q = 0.f;
    #pragma unroll
    for (int j = 0; j < 4; j++) {
        float a = v[j].x-mean, b = v[j].y-mean, c = v[j].z-mean, d = v[j].w-mean;
        q += a*a + b*b + c*c + d*d;
    }
    #pragma unroll
    for (int o = 16; o > 0; o >>= 1) q += __shfl_xor_sync(0xffffffffu, q, o);
    float inv = rsqrtf(q * (1.0f/DD) + 1e-5f);
    #pragma unroll
    for (int j = 0; j < 4; j++) {
        float4 gg = ((const float4*)g)[lane + 32*j];
        float4 bv = ((const float4*)bb)[lane + 32*j];
        float4 o4 = make_float4(
            (v[j].x-mean)*inv*gg.x + bv.x, (v[j].y-mean)*inv*gg.y + bv.y,
            (v[j].z-mean)*inv*gg.z + bv.z, (v[j].w-mean)*inv*gg.w + bv.w);
        if (out) ((float4*)out)[(size_t)row*(DD/4) + lane + 32*j] = o4;
        if (out16) {
            int base = (int)(lane + 32*j);
            ((__half2*)(out16 + (size_t)row*DD))[2*base]   = __floats2half2_rn(o4.x, o4.y);
            ((__half2*)(out16 + (size_t)row*DD))[2*base+1] = __floats2half2_rn(o4.z, o4.w);
        }
    }
}

// ---------------- fused: residual(base|scatter) + layernorm2 ----------------
__global__ __launch_bounds__(256) void lnfuse_kernel(const float* __restrict__ x,
        const float* __restrict__ cs, const float* __restrict__ aout,
        const int* __restrict__ tidx,
        const float* __restrict__ g, const float* __restrict__ bb,
        float* __restrict__ x2, __half* __restrict__ out16)
{
    int row  = blockIdx.x * 8 + (threadIdx.x >> 5);
    int lane = threadIdx.x & 31;
    int b    = row >> 11;
    int rin  = row & (SS-1);
    __shared__ int stid[TOPQ];
    if (threadIdx.x < TOPQ) stid[threadIdx.x] = tidx[b*TOPQ + threadIdx.x];
    __syncthreads();
    int slot = -1;
    #pragma unroll
    for (int j = 0; j < TOPQ; j++) if (stid[j] == rin) slot = j;

    const float4* xr = (const float4*)x + (size_t)row*(DD/4);
    float4 v[4];
    #pragma unroll
    for (int j = 0; j < 4; j++) v[j] = xr[lane + 32*j];
    if (slot >= 0) {
        const float4* ar = (const float4*)aout + (size_t)(b*TOPQ + slot)*(DD/4);
        #pragma unroll
        for (int j = 0; j < 4; j++) {
            float4 a = ar[lane + 32*j];
            v[j].x += a.x; v[j].y += a.y; v[j].z += a.z; v[j].w += a.w;
        }
    } else {
        const float4* cr = (const float4*)cs + b*(DD/4);
        const float r = 1.0f / SS;
        #pragma unroll
        for (int j = 0; j < 4; j++) {
            float4 c = cr[lane + 32*j];
            v[j].x += c.x*r; v[j].y += c.y*r; v[j].z += c.z*r; v[j].w += c.w*r;
        }
    }
    #pragma unroll
    for (int j = 0; j < 4; j++)
        ((float4*)x2)[(size_t)row*(DD/4) + lane + 32*j] = v[j];
    float s = 0.f;
    #pragma unroll
    for (int j = 0; j < 4; j++) s += v[j].x + v[j].y + v[j].z + v[j].w;
    #pragma unroll
    for (int o = 16; o > 0; o >>= 1) s += __shfl_xor_sync(0xffffffffu, s, o);
    float mean = s * (1.0f/DD);
    float q = 0.f;
    #pragma unroll
    for (int j = 0; j < 4; j++) {
        float a = v[j].x-mean, bq = v[j].y-mean, c = v[j].z-mean, d = v[j].w-mean;
        q += a*a + bq*bq + c*c + d*d;
    }
    #pragma unroll
    for (int o = 16; o > 0; o >>= 1) q += __shfl_xor_sync(0xffffffffu, q, o);
    float inv = rsqrtf(q * (1.0f/DD) + 1e-5f);
    #pragma unroll
    for (int j = 0; j < 4; j++) {
        float4 gg = ((const float4*)g)[lane + 32*j];
        float4 bv = ((const float4*)bb)[lane + 32*j];
        float4 o4 = make_float4(
            (v[j].x-mean)*inv*gg.x + bv.x, (v[j].y-mean)*inv*gg.y + bv.y,
            (v[j].z-mean)*inv*gg.z + bv.z, (v[j].w-mean)*inv*gg.w + bv.w);
        int base = (int)(lane + 32*j);
        ((__half2*)(out16 + (size_t)row*DD))[2*base]   = __floats2half2_rn(o4.x, o4.y);
        ((__half2*)(out16 + (size_t)row*DD))[2*base+1] = __floats2half2_rn(o4.z, o4.w);
    }
}

// ---------------- column sums ----------------
__global__ void colsum1_kernel(const float* __restrict__ xn, float* __restrict__ part)
{
    int b = blockIdx.y;
    int c = blockIdx.z;
    int d = blockIdx.x * 128 + threadIdx.x;
    const float* p = xn + (size_t)b*SS*DD + (size_t)c*128*DD + d;
    float s = 0.f;
    #pragma unroll 8
    for (int k = 0; k < 128; k++) s += p[(size_t)k*DD];
    part[((size_t)c*BB + b)*DD + d] = s;
}
__global__ void colsum2_kernel(const float* __restrict__ part, float* __restrict__ cs)
{
    int i = blockIdx.x * 256 + threadIdx.x;
    if (i < BB*DD) {
        float s = 0.f;
        #pragma unroll
        for (int c = 0; c < 16; c++) s += part[(size_t)c*BB*DD + i];
        cs[i] = s;
    }
}

// ---------------- sparsity ----------------
__global__ __launch_bounds__(256) void sparsw_kernel(const float* __restrict__ xn,
        const float* __restrict__ cs, float* __restrict__ sp)
{
    int row  = blockIdx.x * 8 + (threadIdx.x >> 5);
    int lane = threadIdx.x & 31;
    int b = row >> 11;
    const float4* xr = (const float4*)xn + (size_t)row*(DD/4);
    const float4* cr = (const float4*)cs + b*(DD/4);
    float dp = 0.f, de = 0.f, mp = 0.f, me = 0.f;
    #pragma unroll
    for (int j = 0; j < 4; j++) {
        float4 v = xr[lane + 32*j];
        float4 c = cr[lane + 32*j];
        float vv[4] = {v.x, v.y, v.z, v.w};
        float cc[4] = {c.x, c.y, c.z, c.w};
        #pragma unroll
        for (int e = 0; e < 4; e++) {
            float p = vv[e]*vv[e];
            de += fmaf(vv[e], vv[e], -p);
            dp += p;
            float q = vv[e]*cc[e];
            me += fmaf(vv[e], cc[e], -q);
            mp += q;
        }
    }
    double dd = (double)dp + (double)de;
    double dm = (double)mp + (double)me;
    #pragma unroll
    for (int o = 16; o > 0; o >>= 1) {
        dd += __shfl_xor_sync(0xffffffffu, dd, o);
        dm += __shfl_xor_sync(0xffffffffu, dm, o);
    }
    if (lane == 0)
        sp[row] = (float)((dd - dm * (1.0/SS)) * 0.04419417382415922);
}

// ---------------- top-39 ----------------
__global__ __launch_bounds__(256) void topk_kernel(const float* __restrict__ sp,
        int* __restrict__ tidx)
{
    int b = blockIdx.x;
    int t = threadIdx.x;
    __shared__ float sv[SS];
    __shared__ float rbv[8];
    __shared__ int   rbi[8];
    for (int i = t; i < SS; i += 256) sv[i] = sp[b*SS + i];
    __syncthreads();
    for (int sel = 0; sel < TOPQ; ++sel) {
        float bv = -3.0e38f; int bi = 0;
        for (int i = t; i < SS; i += 256) {
            float v = sv[i];
            if (v > bv || (v == bv && i < bi)) { bv = v; bi = i; }
        }
        #pragma unroll
        for (int o = 16; o > 0; o >>= 1) {
            float ov = __shfl_down_sync(0xffffffffu, bv, o);
            int   oi = __shfl_down_sync(0xffffffffu, bi, o);
            if (ov > bv || (ov == bv && oi < bi)) { bv = ov; bi = oi; }
        }
        if ((t & 31) == 0) { rbv[t >> 5] = bv; rbi[t >> 5] = bi; }
        __syncthreads();
        if (t == 0) {
            float fv = rbv[0]; int fi = rbi[0];
            #pragma unroll
            for (int w = 1; w < 8; w++)
                if (rbv[w] > fv || (rbv[w] == fv && rbi[w] < fi)) { fv = rbv[w]; fi = rbi[w]; }
            tidx[b*TOPQ + sel] = fi;
            sv[fi] = -3.4e38f;
        }
        __syncthreads();
    }
}

// ---------------- flash attention: per (kslice g, head, batch) --------------
// Partial online softmax over keys [g*512, g*512+512); unnormalized ctx + (m,l).
__global__ __launch_bounds__(256) void ctxflash_kernel(
    const float* __restrict__ qs, const __half* __restrict__ kvh,
    float* __restrict__ part, float2* __restrict__ ml)
{
    int g = blockIdx.x, h = blockIdx.y, b = blockIdx.z;
    int tid = threadIdx.x, w = tid >> 5, lane = tid & 31;
    __shared__ __half Kt[64][66];     // [d][k] transposed, padded
    __shared__ __half Vs[64][64];     // [k][d]
    __shared__ float  Qt[64][40];     // [d][q]
    __shared__ float  Pw[8][QPW][64];

    for (int i = tid; i < TOPQ*DH; i += 256) {
        int q = i >> 6, d = i & 63;
        Qt[d][q] = qs[((size_t)(b*TOPQ + q))*DD + h*DH + d];
    }
    float2 acc[QPW];
    float m_run[QPW], l_run[QPW];
    #pragma unroll
    for (int iq = 0; iq < QPW; iq++) {
        acc[iq] = make_float2(0.f, 0.f); m_run[iq] = -3.0e38f; l_run[iq] = 0.f;
    }
    __syncthreads();

    for (int t = 0; t < 8; t++) {
        int k0 = g*512 + t*64;
        for (int i = tid; i < 64*32; i += 256) {
            int k = i >> 5, dp = i & 31;
            const __half2* src = (const __half2*)(kvh + ((size_t)(b*SS + k0 + k))*(2*DD) + h*DH) + dp;
            __half2 kk = src[0];
            Kt[2*dp][k]   = __low2half(kk);
            Kt[2*dp+1][k] = __high2half(kk);
            *(__half2*)&Vs[k][2*dp] = src[DD/2];
        }
        __syncthreads();
        #pragma unroll
        for (int iq = 0; iq < QPW; iq++) {
            int q = w + 8*iq;
            if (q < TOPQ) {
                float s0 = 0.f, s1 = 0.f;
                #pragma unroll 8
                for (int d = 0; d < DH; d++) {
                    float qv = Qt[d][q];
                    float2 kk = __half22float2(*(const __half2*)&Kt[d][2*lane]);
                    s0 = fmaf(qv, kk.x, s0);
                    s1 = fmaf(qv, kk.y, s1);
                }
                s0 *= 0.125f; s1 *= 0.125f;
                float mt = fmaxf(s0, s1);
                #pragma unroll
                for (int o = 16; o > 0; o >>= 1)
                    mt = fmaxf(mt, __shfl_xor_sync(0xffffffffu, mt, o));
                float mnew = fmaxf(m_run[iq], mt);
                float p0 = __expf(s0 - mnew), p1 = __expf(s1 - mnew);
                float ps = p0 + p1;
                #pragma unroll
                for (int o = 16; o > 0; o >>= 1)
                    ps += __shfl_xor_sync(0xffffffffu, ps, o);
                float scale = __expf(m_run[iq] - mnew);
                l_run[iq] = l_run[iq]*scale + ps;
                m_run[iq] = mnew;
                Pw[w][iq][2*lane]   = p0;
                Pw[w][iq][2*lane+1] = p1;
                acc[iq].x *= scale; acc[iq].y *= scale;
                __syncwarp();
                #pragma unroll 8
                for (int k = 0; k < 64; k++) {
                    float pv = Pw[w][iq][k];
                    float2 vv = __half22float2(*(const __half2*)&Vs[k][2*lane]);
                    acc[iq].x = fmaf(pv, vv.x, acc[iq].x);
                    acc[iq].y = fmaf(pv, vv.y, acc[iq].y);
                }
            }
        }
        __syncthreads();
    }
    #pragma unroll
    for (int iq = 0; iq < QPW; iq++) {
        int q = w + 8*iq;
        if (q < TOPQ) {
            float* dst = part + (size_t)g*(BB*TOPQ*DD) + ((size_t)(b*TOPQ + q))*DD + h*DH + 2*lane;
            *(float2*)dst = acc[iq];
            if (lane == 0)
                ml[((size_t)(g*BB + b)*HH + h)*TOPQ + q] = make_float2(m_run[iq], l_run[iq]);
        }
    }
}

// ---------------- row projection (gather mode, or flash-combine mode) -------
__global__ __launch_bounds__(256) void rowproj_kernel(const float* __restrict__ src,
        const int* __restrict__ gidx, const float* __restrict__ part,
        const float2* __restrict__ ml,
        const float* __restrict__ W, const float* __restrict__ bias,
        float* __restrict__ out)
{
    int r = blockIdx.x;
    __shared__ float xr[DD];
    __shared__ float wt[HH][4];
    if (part) {
        int b = r / TOPQ, q = r % TOPQ;
        if (threadIdx.x < HH) {
            int h = threadIdx.x;
            float m[4], l[4];
            #pragma unroll
            for (int g = 0; g < 4; g++) {
                float2 v = ml[((size_t)(g*BB + b)*HH + h)*TOPQ + q];
                m[g] = v.x; l[g] = v.y;
            }
            float M = fmaxf(fmaxf(m[0], m[1]), fmaxf(m[2], m[3]));
            float e[4], L = 0.f;
            #pragma unroll
            for (int g = 0; g < 4; g++) { e[g] = __expf(m[g] - M); L += l[g]*e[g]; }
            float invL = 1.0f / L;
            #pragma unroll
            for (int g = 0; g < 4; g++) wt[h][g] = e[g]*invL;
        }
        __syncthreads();
        const int N4 = BB*TOPQ*DD/4;
        const float4* p = (const float4*)part;
        for (int i = threadIdx.x; i < DD/4; i += 256) {
            int h = i >> 4;
            int idx = r*(DD/4) + i;
            float4 a = p[idx], bb4 = p[idx+N4], c = p[idx+2*N4], d = p[idx+3*N4];
            float w0 = wt[h][0], w1 = wt[h][1], w2 = wt[h][2], w3 = wt[h][3];
            ((float4*)xr)[i] = make_float4(
                a.x*w0 + bb4.x*w1 + c.x*w2 + d.x*w3,
                a.y*w0 + bb4.y*w1 + c.y*w2 + d.y*w3,
                a.z*w0 + bb4.z*w1 + c.z*w2 + d.z*w3,
                a.w*w0 + bb4.w*w1 + c.w*w2 + d.w*w3);
        }
    } else {
        const float* srow;
        if (gidx) { int b = r / TOPQ; srow = src + ((size_t)b*SS + gidx[r]) * DD; }
        else        srow = src + (size_t)r * DD;
        for (int i = threadIdx.x; i < DD/4; i += 256)
            ((float4*)xr)[i] = ((const float4*)srow)[i];
    }
    __syncthreads();
    for (int j = threadIdx.x; j < DD; j += 256) {
        const float4* w4 = (const float4*)(W + (size_t)j*DD);
        float acc = 0.f;
        #pragma unroll 4
        for (int k = 0; k < DD/4; k++) {
            float4 w = w4[k]; float4 xv = ((float4*)xr)[k];
            acc = fmaf(w.x, xv.x, fmaf(w.y, xv.y, fmaf(w.z, xv.z, fmaf(w.w, xv.w, acc))));
        }
        out[(size_t)r*DD + j] = acc + bias[j];
    }
}

// ---------------- ratio tail ----------------
__global__ void ratio_kernel(float* out, int out_size)
{
    int i = NROWS*DD + blockIdx.x*blockDim.x + threadIdx.x;
    if (i < out_size) out[i] = (float)TOPQ / (float)SS;
}

// ---------------- launch ----------------
extern "C" void kernel_launch(void* const* d_in, const int* in_sizes, int n_in,
                              void* d_out, int out_size)
{
    const float* x    = (const float*)d_in[0];
    const float* ln1g = (const float*)d_in[1];
    const float* ln1b = (const float*)d_in[2];
    const float* in_w = (const float*)d_in[3];
    const float* in_b = (const float*)d_in[4];
    const float* outw = (const float*)d_in[5];
    const float* outb = (const float*)d_in[6];
    const float* ln2g = (const float*)d_in[7];
    const float* ln2b = (const float*)d_in[8];
    const float* w1   = (const float*)d_in[9];
    const float* b1   = (const float*)d_in[10];
    const float* w2   = (const float*)d_in[11];
    const float* b2   = (const float*)d_in[12];
    float* out = (float*)d_out;

    float *xn, *x2, *cs, *csp, *sp, *qs, *ctxp, *aout;
    float2 *ml;
    __half *kvh, *xn16, *xn2h, *h1h, *wkv16, *w1h, *w2h;
    int *tidx;
    cudaGetSymbolAddress((void**)&xn,    g_xn);
    cudaGetSymbolAddress((void**)&x2,    g_x2);
    cudaGetSymbolAddress((void**)&cs,    g_cs);
    cudaGetSymbolAddress((void**)&csp,   g_cspart);
    cudaGetSymbolAddress((void**)&sp,    g_sp);
    cudaGetSymbolAddress((void**)&qs,    g_qs);
    cudaGetSymbolAddress((void**)&ctxp,  g_ctxp);
    cudaGetSymbolAddress((void**)&ml,    g_ml);
    cudaGetSymbolAddress((void**)&aout,  g_aout);
    cudaGetSymbolAddress((void**)&tidx,  g_tidx);
    cudaGetSymbolAddress((void**)&kvh,   g_kvh);
    cudaGetSymbolAddress((void**)&xn16,  g_xn16);
    cudaGetSymbolAddress((void**)&xn2h,  g_xn2h);
    cudaGetSymbolAddress((void**)&h1h,   g_h1h);
    cudaGetSymbolAddress((void**)&wkv16, g_wkv16);
    cudaGetSymbolAddress((void**)&w1h,   g_w1h);
    cudaGetSymbolAddress((void**)&w2h,   g_w2h);

    cudaFuncSetAttribute(hgemm<0, __half>, cudaFuncAttributeMaxDynamicSharedMemorySize, HG_SMEM);
    cudaFuncSetAttribute(hgemm<1, __half>, cudaFuncAttributeMaxDynamicSharedMemorySize, HG_SMEM);
    cudaFuncSetAttribute(hgemm<2, float>,  cudaFuncAttributeMaxDynamicSharedMemorySize, HG_SMEM);

    // 1: weight conversions (merged)
    {
        int na4 = 2*DD*DD/4, nb4 = FF_*DD/4, nc4 = DD*FF_/4;
        f2h3_kernel<<<(na4+nb4+nc4 + 255)/256, 256>>>(
            in_w + (size_t)DD*DD, wkv16, na4, w1, w1h, nb4, w2, w2h, nc4);
    }
    // 2: layernorm1
    lnw_kernel<<<NROWS/8, 256>>>(x, ln1g, ln1b, xn, xn16);
    // 3: colsum stage 1
    colsum1_kernel<<<dim3(DD/128, BB, 16), 128>>>(xn, csp);
    // 4: KV projection (fp16 out)  <- expected ncu capture slot
    hgemm<0, __half><<<dim3((2*DD)/128, NROWS/128), 256, HG_SMEM>>>(
        xn16, wkv16, in_b + DD, nullptr, kvh, 2*DD, DD);
    // ranking chain
    colsum2_kernel<<<(BB*DD + 255)/256, 256>>>(csp, cs);
    sparsw_kernel<<<NROWS/8, 256>>>(xn, cs, sp);
    topk_kernel<<<BB, 256>>>(sp, tidx);
    rowproj_kernel<<<BB*TOPQ, 256>>>(xn, tidx, nullptr, nullptr, in_w, in_b, qs);
    // flash attention (split-K partials) + combine-projection
    ctxflash_kernel<<<dim3(4, HH, BB), 256>>>(qs, kvh, ctxp, ml);
    rowproj_kernel<<<BB*TOPQ, 256>>>(nullptr, nullptr, ctxp, ml, outw, outb, aout);
    // fused residual + layernorm2
    lnfuse_kernel<<<NROWS/8, 256>>>(x, cs, aout, tidx, ln2g, ln2b, x2, xn2h);
    // FFN
    hgemm<1, __half><<<dim3(FF_/128, NROWS/128), 256, HG_SMEM>>>(
        xn2h, w1h, b1, nullptr, h1h, FF_, DD);
    hgemm<2, float><<<dim3(DD/128, NROWS/128), 256, HG_SMEM>>>(
        h1h, w2h, b2, x2, out, DD, FF_);
    // ratio tail
    if (out_size > NROWS*DD) {
        int tail = out_size - NROWS*DD;
        ratio_kernel<<<(tail + 255)/256, 256>>>(out, out_size);
    }
}

// round 9
// speedup vs baseline: 1.2731x; 1.1236x over previous
#include <cuda_runtime.h>
#include <cuda_fp16.h>
#include <math.h>
#include <stdint.h>

#define BB 8
#define SS 2048
#define DD 512
#define FF_ 2048
#define HH 8
#define DH 64
#define TOPQ 39
#define QPW 5
#define NROWS (BB*SS)   /* 16384 */

// ---------------- static scratch ----------------
__device__ float g_xn  [NROWS*DD];
__device__ float g_x2  [NROWS*DD];
__device__ float g_cs  [BB*DD];
__device__ float g_cspart[16*BB*DD];
__device__ float g_sp  [BB*SS];
__device__ int   g_tidx[BB*TOPQ];
__device__ float g_qs  [BB*TOPQ*DD];
__device__ float g_ctxp[4*BB*TOPQ*DD];
__device__ float2 g_ml [4*BB*HH*TOPQ];
__device__ float g_aout[BB*TOPQ*DD];
// fp16 operands
__device__ __half g_kvh  [NROWS*2*DD];
__device__ __half g_xn16 [NROWS*DD];
__device__ __half g_xn2h [NROWS*DD];
__device__ __half g_h1h  [(size_t)NROWS*FF_];
__device__ __half g_wkv16[2*DD*DD];
__device__ __half g_w1h  [FF_*DD];
__device__ __half g_w2h  [DD*FF_];

// ---------------- helpers ----------------
__device__ __forceinline__ uint32_t s2u(const void* p) {
    uint32_t a;
    asm("{ .reg .u64 t; cvta.to.shared.u64 t, %1; cvt.u32.u64 %0, t; }" : "=r"(a) : "l"(p));
    return a;
}
__device__ __forceinline__ void mma_f16(float* d, const uint32_t* a, const uint32_t* b) {
    asm volatile("mma.sync.aligned.m16n8k16.row.col.f32.f16.f16.f32 "
        "{%0,%1,%2,%3}, {%4,%5,%6,%7}, {%8,%9}, {%0,%1,%2,%3};"
        : "+f"(d[0]), "+f"(d[1]), "+f"(d[2]), "+f"(d[3])
        : "r"(a[0]), "r"(a[1]), "r"(a[2]), "r"(a[3]), "r"(b[0]), "r"(b[1]));
}
__device__ __forceinline__ void ldsm4(uint32_t* r, uint32_t addr) {
    asm volatile("ldmatrix.sync.aligned.m8n8.x4.shared.b16 {%0,%1,%2,%3}, [%4];"
        : "=r"(r[0]), "=r"(r[1]), "=r"(r[2]), "=r"(r[3]) : "r"(addr));
}
__device__ __forceinline__ void cpa16(uint32_t dst, const void* src) {
    asm volatile("cp.async.cg.shared.global [%0], [%1], 16;" :: "r"(dst), "l"(src));
}
__device__ __forceinline__ void cpcommit() {
    asm volatile("cp.async.commit_group;" ::: "memory");
}
template<int N> __device__ __forceinline__ void cpwait() {
    asm volatile("cp.async.wait_group %0;" :: "n"(N) : "memory");
}
__device__ __forceinline__ float gelu_f(float x) {
    return 0.5f * x * (1.0f + erff(x * 0.7071067811865476f));
}

// ====================================================================
// fp16 GEMM: CTA 128x128, 128 thr = 4 warps (2x2), warp tile 64x64,
// K-chunk 32, 4-stage cp.async, 2 CTAs/SM.
// SMEM per stage 16KB (A 8KB + B 8KB); row x 64B; unit u at (u ^ (row&3)).
// ====================================================================
#define HG_SMEM (4*16384)

template<int EPI, typename OutT>   // EPI: 0=none, 1=gelu, 2=+res
__global__ __launch_bounds__(128, 2) void hgemm(
    const __half* __restrict__ A, const __half* __restrict__ W,
    const float* __restrict__ bias, const float* __restrict__ res,
    OutT* __restrict__ C, int N, int K)
{
    extern __shared__ __align__(16) char smh[];
    const int tid  = threadIdx.x;
    const int lane = tid & 31;
    const int wid  = tid >> 5;
    const int wm   = wid >> 1;      // 0..1
    const int wn   = wid & 1;       // 0..1
    const int bm = blockIdx.y * 128;
    const int bn = blockIdx.x * 128;
    const uint32_t sb = s2u(smh);

    const __half* Ab = A + (size_t)bm * K;
    const __half* Wb = W + (size_t)bn * K;

    const int crow0 = tid >> 2;     // 0..31
    const int cunit = tid & 3;

    auto ISSUE = [&](int buf, int kbase) {
        uint32_t base = sb + buf * 16384;
        #pragma unroll
        for (int i = 0; i < 4; i++) {
            int row = crow0 + i * 32;
            uint32_t off = row*64 + ((cunit ^ (row&3))*16);
            cpa16(base + off,        Ab + (size_t)row*K + kbase + cunit*8);
            cpa16(base + 8192 + off, Wb + (size_t)row*K + kbase + cunit*8);
        }
        cpcommit();
    };

    float acc[4][8][4];
    #pragma unroll
    for (int a = 0; a < 4; a++)
        #pragma unroll
        for (int b = 0; b < 8; b++)
            #pragma unroll
            for (int c = 0; c < 4; c++) acc[a][b][c] = 0.f;

    const int nk = K >> 5;
    const int lm = lane >> 3;
    const int lr = lane & 7;

    ISSUE(0, 0);
    ISSUE(1, 32);
    ISSUE(2, 64);

    for (int kt = 0; kt < nk; kt++) {
        cpwait<2>();
        __syncthreads();
        if (kt + 3 < nk) ISSUE((kt + 3) & 3, (kt + 3) << 5);
        else             cpcommit();

        int buf = kt & 3;
        uint32_t Abase = sb + buf*16384;
        uint32_t Bbase = Abase + 8192;
        #pragma unroll
        for (int s = 0; s < 2; s++) {
            uint32_t af[4][4];
            #pragma unroll
            for (int mt = 0; mt < 4; mt++) {
                int row = wm*64 + mt*16 + (lm&1)*8 + lr;
                int unit = s*2 + (lm>>1);
                ldsm4(af[mt], Abase + row*64 + ((unit ^ (row&3))*16));
            }
            uint32_t bf[8][2];
            #pragma unroll
            for (int np = 0; np < 4; np++) {
                int nr = wn*64 + (np*2 + (lm>>1))*8 + lr;
                int unit = s*2 + (lm&1);
                uint32_t r[4];
                ldsm4(r, Bbase + nr*64 + ((unit ^ (nr&3))*16));
                bf[np*2][0] = r[0]; bf[np*2][1] = r[1];
                bf[np*2+1][0] = r[2]; bf[np*2+1][1] = r[3];
            }
            #pragma unroll
            for (int mt = 0; mt < 4; mt++)
                #pragma unroll
                for (int nt = 0; nt < 8; nt++)
                    mma_f16(acc[mt][nt], af[mt], bf[nt]);
        }
    }

    const int g = lane >> 2, t = lane & 3;
    #pragma unroll
    for (int mt = 0; mt < 4; mt++) {
        int row0 = bm + wm*64 + mt*16 + g;
        #pragma unroll
        for (int nt = 0; nt < 8; nt++) {
            int col = bn + wn*64 + nt*8 + 2*t;
            float b0 = bias[col], b1 = bias[col+1];
            float v0 = acc[mt][nt][0] + b0;
            float v1 = acc[mt][nt][1] + b1;
            float v2 = acc[mt][nt][2] + b0;
            float v3 = acc[mt][nt][3] + b1;
            if (EPI == 1) {
                v0 = gelu_f(v0); v1 = gelu_f(v1); v2 = gelu_f(v2); v3 = gelu_f(v3);
            }
            if (EPI == 2) {
                const float* r0 = res + (size_t)row0*N + col;
                const float* r1 = res + (size_t)(row0+8)*N + col;
                v0 += r0[0]; v1 += r0[1]; v2 += r1[0]; v3 += r1[1];
            }
            if constexpr (sizeof(OutT) == 2) {
                *(__half2*)&C[(size_t)row0*N + col]     = __floats2half2_rn(v0, v1);
                *(__half2*)&C[(size_t)(row0+8)*N + col] = __floats2half2_rn(v2, v3);
            } else {
                *(float2*)&C[(size_t)row0*N + col]     = make_float2(v0, v1);
                *(float2*)&C[(size_t)(row0+8)*N + col] = make_float2(v2, v3);
            }
        }
    }
}

// ---------------- fp32 -> fp16 bulk convert (3 regions, one launch) --------
__global__ void f2h3_kernel(const float* __restrict__ a, __half* __restrict__ da, int na4,
                            const float* __restrict__ b, __half* __restrict__ db, int nb4,
                            const float* __restrict__ c, __half* __restrict__ dc, int nc4)
{
    int i = blockIdx.x * 256 + threadIdx.x;
    const float* s; __half* d; int j = i;
    if (j < na4) { s = a; d = da; }
    else {
        j -= na4;
        if (j < nb4) { s = b; d = db; }
        else { j -= nb4; if (j >= nc4) return; s = c; d = dc; }
    }
    float4 v = ((const float4*)s)[j];
    ((__half2*)d)[2*j]   = __floats2half2_rn(v.x, v.y);
    ((__half2*)d)[2*j+1] = __floats2half2_rn(v.z, v.w);
}

// ---------------- layernorm1: warp per row ----------------
__global__ __launch_bounds__(256) void lnw_kernel(const float* __restrict__ x,
        const float* __restrict__ g, const float* __restrict__ bb,
        float* __restrict__ out, __half* __restrict__ out16)
{
    int row  = blockIdx.x * 8 + (threadIdx.x >> 5);
    int lane = threadIdx.x & 31;
    const float4* xr = (const float4*)x + (size_t)row*(DD/4);
    float4 v[4];
    #pragma unroll
    for (int j = 0; j < 4; j++) v[j] = xr[lane + 32*j];
    float s = 0.f;
    #pragma unroll
    for (int j = 0; j < 4; j++) s += v[j].x + v[j].y + v[j].z + v[j].w;
    #pragma unroll
    for (int o = 16; o > 0; o >>= 1) s += __shfl_xor_sync(0xffffffffu, s, o);
    float mean = s * (1.0f/DD);
    float q = 0.f;
    #pragma unroll
    for (int j = 0; j < 4; j++) {
        float a = v[j].x-mean, b = v[j].y-mean, c = v[j].z-mean, d = v[j].w-mean;
        q += a*a + b*b + c*c + d*d;
    }
    #pragma unroll
    for (int o = 16; o > 0; o >>= 1) q += __shfl_xor_sync(0xffffffffu, q, o);
    float inv = rsqrtf(q * (1.0f/DD) + 1e-5f);
    #pragma unroll
    for (int j = 0; j < 4; j++) {
        float4 gg = ((const float4*)g)[lane + 32*j];
        float4 bv = ((const float4*)bb)[lane + 32*j];
        float4 o4 = make_float4(
            (v[j].x-mean)*inv*gg.x + bv.x, (v[j].y-mean)*inv*gg.y + bv.y,
            (v[j].z-mean)*inv*gg.z + bv.z, (v[j].w-mean)*inv*gg.w + bv.w);
        if (out) ((float4*)out)[(size_t)row*(DD/4) + lane + 32*j] = o4;
        if (out16) {
            int base = (int)(lane + 32*j);
            ((__half2*)(out16 + (size_t)row*DD))[2*base]   = __floats2half2_rn(o4.x, o4.y);
            ((__half2*)(out16 + (size_t)row*DD))[2*base+1] = __floats2half2_rn(o4.z, o4.w);
        }
    }
}

// ---------------- fused: residual(base|scatter) + layernorm2 ----------------
__global__ __launch_bounds__(256) void lnfuse_kernel(const float* __restrict__ x,
        const float* __restrict__ cs, const float* __restrict__ aout,
        const int* __restrict__ tidx,
        const float* __restrict__ g, const float* __restrict__ bb,
        float* __restrict__ x2, __half* __restrict__ out16)
{
    int row  = blockIdx.x * 8 + (threadIdx.x >> 5);
    int lane = threadIdx.x & 31;
    int b    = row >> 11;
    int rin  = row & (SS-1);
    __shared__ int stid[TOPQ];
    if (threadIdx.x < TOPQ) stid[threadIdx.x] = tidx[b*TOPQ + threadIdx.x];
    __syncthreads();
    int slot = -1;
    #pragma unroll
    for (int j = 0; j < TOPQ; j++) if (stid[j] == rin) slot = j;

    const float4* xr = (const float4*)x + (size_t)row*(DD/4);
    float4 v[4];
    #pragma unroll
    for (int j = 0; j < 4; j++) v[j] = xr[lane + 32*j];
    if (slot >= 0) {
        const float4* ar = (const float4*)aout + (size_t)(b*TOPQ + slot)*(DD/4);
        #pragma unroll
        for (int j = 0; j < 4; j++) {
            float4 a = ar[lane + 32*j];
            v[j].x += a.x; v[j].y += a.y; v[j].z += a.z; v[j].w += a.w;
        }
    } else {
        const float4* cr = (const float4*)cs + b*(DD/4);
        const float r = 1.0f / SS;
        #pragma unroll
        for (int j = 0; j < 4; j++) {
            float4 c = cr[lane + 32*j];
            v[j].x += c.x*r; v[j].y += c.y*r; v[j].z += c.z*r; v[j].w += c.w*r;
        }
    }
    #pragma unroll
    for (int j = 0; j < 4; j++)
        ((float4*)x2)[(size_t)row*(DD/4) + lane + 32*j] = v[j];
    float s = 0.f;
    #pragma unroll
    for (int j = 0; j < 4; j++) s += v[j].x + v[j].y + v[j].z + v[j].w;
    #pragma unroll
    for (int o = 16; o > 0; o >>= 1) s += __shfl_xor_sync(0xffffffffu, s, o);
    float mean = s * (1.0f/DD);
    float q = 0.f;
    #pragma unroll
    for (int j = 0; j < 4; j++) {
        float a = v[j].x-mean, bq = v[j].y-mean, c = v[j].z-mean, d = v[j].w-mean;
        q += a*a + bq*bq + c*c + d*d;
    }
    #pragma unroll
    for (int o = 16; o > 0; o >>= 1) q += __shfl_xor_sync(0xffffffffu, q, o);
    float inv = rsqrtf(q * (1.0f/DD) + 1e-5f);
    #pragma unroll
    for (int j = 0; j < 4; j++) {
        float4 gg = ((const float4*)g)[lane + 32*j];
        float4 bv = ((const float4*)bb)[lane + 32*j];
        float4 o4 = make_float4(
            (v[j].x-mean)*inv*gg.x + bv.x, (v[j].y-mean)*inv*gg.y + bv.y,
            (v[j].z-mean)*inv*gg.z + bv.z, (v[j].w-mean)*inv*gg.w + bv.w);
        int base = (int)(lane + 32*j);
        ((__half2*)(out16 + (size_t)row*DD))[2*base]   = __floats2half2_rn(o4.x, o4.y);
        ((__half2*)(out16 + (size_t)row*DD))[2*base+1] = __floats2half2_rn(o4.z, o4.w);
    }
}

// ---------------- column sums ----------------
__global__ void colsum1_kernel(const float* __restrict__ xn, float* __restrict__ part)
{
    int b = blockIdx.y;
    int c = blockIdx.z;
    int d = blockIdx.x * 128 + threadIdx.x;
    const float* p = xn + (size_t)b*SS*DD + (size_t)c*128*DD + d;
    float s = 0.f;
    #pragma unroll 8
    for (int k = 0; k < 128; k++) s += p[(size_t)k*DD];
    part[((size_t)c*BB + b)*DD + d] = s;
}
__global__ void colsum2_kernel(const float* __restrict__ part, float* __restrict__ cs)
{
    int i = blockIdx.x * 256 + threadIdx.x;
    if (i < BB*DD) {
        float s = 0.f;
        #pragma unroll
        for (int c = 0; c < 16; c++) s += part[(size_t)c*BB*DD + i];
        cs[i] = s;
    }
}

// ---------------- sparsity ----------------
__global__ __launch_bounds__(256) void sparsw_kernel(const float* __restrict__ xn,
        const float* __restrict__ cs, float* __restrict__ sp)
{
    int row  = blockIdx.x * 8 + (threadIdx.x >> 5);
    int lane = threadIdx.x & 31;
    int b = row >> 11;
    const float4* xr = (const float4*)xn + (size_t)row*(DD/4);
    const float4* cr = (const float4*)cs + b*(DD/4);
    float dp = 0.f, de = 0.f, mp = 0.f, me = 0.f;
    #pragma unroll
    for (int j = 0; j < 4; j++) {
        float4 v = xr[lane + 32*j];
        float4 c = cr[lane + 32*j];
        float vv[4] = {v.x, v.y, v.z, v.w};
        float cc[4] = {c.x, c.y, c.z, c.w};
        #pragma unroll
        for (int e = 0; e < 4; e++) {
            float p = vv[e]*vv[e];
            de += fmaf(vv[e], vv[e], -p);
            dp += p;
            float q = vv[e]*cc[e];
            me += fmaf(vv[e], cc[e], -q);
            mp += q;
        }
    }
    double dd = (double)dp + (double)de;
    double dm = (double)mp + (double)me;
    #pragma unroll
    for (int o = 16; o > 0; o >>= 1) {
        dd += __shfl_xor_sync(0xffffffffu, dd, o);
        dm += __shfl_xor_sync(0xffffffffu, dm, o);
    }
    if (lane == 0)
        sp[row] = (float)((dd - dm * (1.0/SS)) * 0.04419417382415922);
}

// ---------------- top-39 ----------------
__global__ __launch_bounds__(256) void topk_kernel(const float* __restrict__ sp,
        int* __restrict__ tidx)
{
    int b = blockIdx.x;
    int t = threadIdx.x;
    __shared__ float sv[SS];
    __shared__ float rbv[8];
    __shared__ int   rbi[8];
    for (int i = t; i < SS; i += 256) sv[i] = sp[b*SS + i];
    __syncthreads();
    for (int sel = 0; sel < TOPQ; ++sel) {
        float bv = -3.0e38f; int bi = 0;
        for (int i = t; i < SS; i += 256) {
            float v = sv[i];
            if (v > bv || (v == bv && i < bi)) { bv = v; bi = i; }
        }
        #pragma unroll
        for (int o = 16; o > 0; o >>= 1) {
            float ov = __shfl_down_sync(0xffffffffu, bv, o);
            int   oi = __shfl_down_sync(0xffffffffu, bi, o);
            if (ov > bv || (ov == bv && oi < bi)) { bv = ov; bi = oi; }
        }
        if ((t & 31) == 0) { rbv[t >> 5] = bv; rbi[t >> 5] = bi; }
        __syncthreads();
        if (t == 0) {
            float fv = rbv[0]; int fi = rbi[0];
            #pragma unroll
            for (int w = 1; w < 8; w++)
                if (rbv[w] > fv || (rbv[w] == fv && rbi[w] < fi)) { fv = rbv[w]; fi = rbi[w]; }
            tidx[b*TOPQ + sel] = fi;
            sv[fi] = -3.4e38f;
        }
        __syncthreads();
    }
}

// ---------------- flash attention ----------------
__global__ __launch_bounds__(256) void ctxflash_kernel(
    const float* __restrict__ qs, const __half* __restrict__ kvh,
    float* __restrict__ part, float2* __restrict__ ml)
{
    int g = blockIdx.x, h = blockIdx.y, b = blockIdx.z;
    int tid = threadIdx.x, w = tid >> 5, lane = tid & 31;
    __shared__ __half Kt[64][66];
    __shared__ __half Vs[64][64];
    __shared__ float  Qt[64][40];
    __shared__ float  Pw[8][QPW][64];

    for (int i = tid; i < TOPQ*DH; i += 256) {
        int q = i >> 6, d = i & 63;
        Qt[d][q] = qs[((size_t)(b*TOPQ + q))*DD + h*DH + d];
    }
    float2 acc[QPW];
    float m_run[QPW], l_run[QPW];
    #pragma unroll
    for (int iq = 0; iq < QPW; iq++) {
        acc[iq] = make_float2(0.f, 0.f); m_run[iq] = -3.0e38f; l_run[iq] = 0.f;
    }
    __syncthreads();

    for (int t = 0; t < 8; t++) {
        int k0 = g*512 + t*64;
        for (int i = tid; i < 64*32; i += 256) {
            int k = i >> 5, dp = i & 31;
            const __half2* src = (const __half2*)(kvh + ((size_t)(b*SS + k0 + k))*(2*DD) + h*DH) + dp;
            __half2 kk = src[0];
            Kt[2*dp][k]   = __low2half(kk);
            Kt[2*dp+1][k] = __high2half(kk);
            *(__half2*)&Vs[k][2*dp] = src[DD/2];
        }
        __syncthreads();
        #pragma unroll
        for (int iq = 0; iq < QPW; iq++) {
            int q = w + 8*iq;
            if (q < TOPQ) {
                float s0 = 0.f, s1 = 0.f;
                #pragma unroll 8
                for (int d = 0; d < DH; d++) {
                    float qv = Qt[d][q];
                    float2 kk = __half22float2(*(const __half2*)&Kt[d][2*lane]);
                    s0 = fmaf(qv, kk.x, s0);
                    s1 = fmaf(qv, kk.y, s1);
                }
                s0 *= 0.125f; s1 *= 0.125f;
                float mt = fmaxf(s0, s1);
                #pragma unroll
                for (int o = 16; o > 0; o >>= 1)
                    mt = fmaxf(mt, __shfl_xor_sync(0xffffffffu, mt, o));
                float mnew = fmaxf(m_run[iq], mt);
                float p0 = __expf(s0 - mnew), p1 = __expf(s1 - mnew);
                float ps = p0 + p1;
                #pragma unroll
                for (int o = 16; o > 0; o >>= 1)
                    ps += __shfl_xor_sync(0xffffffffu, ps, o);
                float scale = __expf(m_run[iq] - mnew);
                l_run[iq] = l_run[iq]*scale + ps;
                m_run[iq] = mnew;
                Pw[w][iq][2*lane]   = p0;
                Pw[w][iq][2*lane+1] = p1;
                acc[iq].x *= scale; acc[iq].y *= scale;
                __syncwarp();
                #pragma unroll 8
                for (int k = 0; k < 64; k++) {
                    float pv = Pw[w][iq][k];
                    float2 vv = __half22float2(*(const __half2*)&Vs[k][2*lane]);
                    acc[iq].x = fmaf(pv, vv.x, acc[iq].x);
                    acc[iq].y = fmaf(pv, vv.y, acc[iq].y);
                }
            }
        }
        __syncthreads();
    }
    #pragma unroll
    for (int iq = 0; iq < QPW; iq++) {
        int q = w + 8*iq;
        if (q < TOPQ) {
            float* dst = part + (size_t)g*(BB*TOPQ*DD) + ((size_t)(b*TOPQ + q))*DD + h*DH + 2*lane;
            *(float2*)dst = acc[iq];
            if (lane == 0)
                ml[((size_t)(g*BB + b)*HH + h)*TOPQ + q] = make_float2(m_run[iq], l_run[iq]);
        }
    }
}

// ---------------- row projection (gather / flash-combine) ----------------
__global__ __launch_bounds__(256) void rowproj_kernel(const float* __restrict__ src,
        const int* __restrict__ gidx, const float* __restrict__ part,
        const float2* __restrict__ ml,
        const float* __restrict__ W, const float* __restrict__ bias,
        float* __restrict__ out)
{
    int r = blockIdx.x;
    __shared__ float xr[DD];
    __shared__ float wt[HH][4];
    if (part) {
        int b = r / TOPQ, q = r % TOPQ;
        if (threadIdx.x < HH) {
            int h = threadIdx.x;
            float m[4], l[4];
            #pragma unroll
            for (int g = 0; g < 4; g++) {
                float2 v = ml[((size_t)(g*BB + b)*HH + h)*TOPQ + q];
                m[g] = v.x; l[g] = v.y;
            }
            float M = fmaxf(fmaxf(m[0], m[1]), fmaxf(m[2], m[3]));
            float e[4], L = 0.f;
            #pragma unroll
            for (int g = 0; g < 4; g++) { e[g] = __expf(m[g] - M); L += l[g]*e[g]; }
            float invL = 1.0f / L;
            #pragma unroll
            for (int g = 0; g < 4; g++) wt[h][g] = e[g]*invL;
        }
        __syncthreads();
        const int N4 = BB*TOPQ*DD/4;
        const float4* p = (const float4*)part;
        for (int i = threadIdx.x; i < DD/4; i += 256) {
            int h = i >> 4;
            int idx = r*(DD/4) + i;
            float4 a = p[idx], bb4 = p[idx+N4], c = p[idx+2*N4], d = p[idx+3*N4];
            float w0 = wt[h][0], w1 = wt[h][1], w2 = wt[h][2], w3 = wt[h][3];
            ((float4*)xr)[i] = make_float4(
                a.x*w0 + bb4.x*w1 + c.x*w2 + d.x*w3,
                a.y*w0 + bb4.y*w1 + c.y*w2 + d.y*w3,
                a.z*w0 + bb4.z*w1 + c.z*w2 + d.z*w3,
                a.w*w0 + bb4.w*w1 + c.w*w2 + d.w*w3);
        }
    } else {
        const float* srow;
        if (gidx) { int b = r / TOPQ; srow = src + ((size_t)b*SS + gidx[r]) * DD; }
        else        srow = src + (size_t)r * DD;
        for (int i = threadIdx.x; i < DD/4; i += 256)
            ((float4*)xr)[i] = ((const float4*)srow)[i];
    }
    __syncthreads();
    for (int j = threadIdx.x; j < DD; j += 256) {
        const float4* w4 = (const float4*)(W + (size_t)j*DD);
        float acc = 0.f;
        #pragma unroll 4
        for (int k = 0; k < DD/4; k++) {
            float4 w = w4[k]; float4 xv = ((float4*)xr)[k];
            acc = fmaf(w.x, xv.x, fmaf(w.y, xv.y, fmaf(w.z, xv.z, fmaf(w.w, xv.w, acc))));
        }
        out[(size_t)r*DD + j] = acc + bias[j];
    }
}

// ---------------- ratio tail ----------------
__global__ void ratio_kernel(float* out, int out_size)
{
    int i = NROWS*DD + blockIdx.x*blockDim.x + threadIdx.x;
    if (i < out_size) out[i] = (float)TOPQ / (float)SS;
}

// ---------------- launch ----------------
extern "C" void kernel_launch(void* const* d_in, const int* in_sizes, int n_in,
                              void* d_out, int out_size)
{
    const float* x    = (const float*)d_in[0];
    const float* ln1g = (const float*)d_in[1];
    const float* ln1b = (const float*)d_in[2];
    const float* in_w = (const float*)d_in[3];
    const float* in_b = (const float*)d_in[4];
    const float* outw = (const float*)d_in[5];
    const float* outb = (const float*)d_in[6];
    const float* ln2g = (const float*)d_in[7];
    const float* ln2b = (const float*)d_in[8];
    const float* w1   = (const float*)d_in[9];
    const float* b1   = (const float*)d_in[10];
    const float* w2   = (const float*)d_in[11];
    const float* b2   = (const float*)d_in[12];
    float* out = (float*)d_out;

    float *xn, *x2, *cs, *csp, *sp, *qs, *ctxp, *aout;
    float2 *ml;
    __half *kvh, *xn16, *xn2h, *h1h, *wkv16, *w1h, *w2h;
    int *tidx;
    cudaGetSymbolAddress((void**)&xn,    g_xn);
    cudaGetSymbolAddress((void**)&x2,    g_x2);
    cudaGetSymbolAddress((void**)&cs,    g_cs);
    cudaGetSymbolAddress((void**)&csp,   g_cspart);
    cudaGetSymbolAddress((void**)&sp,    g_sp);
    cudaGetSymbolAddress((void**)&qs,    g_qs);
    cudaGetSymbolAddress((void**)&ctxp,  g_ctxp);
    cudaGetSymbolAddress((void**)&ml,    g_ml);
    cudaGetSymbolAddress((void**)&aout,  g_aout);
    cudaGetSymbolAddress((void**)&tidx,  g_tidx);
    cudaGetSymbolAddress((void**)&kvh,   g_kvh);
    cudaGetSymbolAddress((void**)&xn16,  g_xn16);
    cudaGetSymbolAddress((void**)&xn2h,  g_xn2h);
    cudaGetSymbolAddress((void**)&h1h,   g_h1h);
    cudaGetSymbolAddress((void**)&wkv16, g_wkv16);
    cudaGetSymbolAddress((void**)&w1h,   g_w1h);
    cudaGetSymbolAddress((void**)&w2h,   g_w2h);

    cudaFuncSetAttribute(hgemm<0, __half>, cudaFuncAttributeMaxDynamicSharedMemorySize, HG_SMEM);
    cudaFuncSetAttribute(hgemm<1, __half>, cudaFuncAttributeMaxDynamicSharedMemorySize, HG_SMEM);
    cudaFuncSetAttribute(hgemm<2, float>,  cudaFuncAttributeMaxDynamicSharedMemorySize, HG_SMEM);

    // 1: weight conversions (merged)
    {
        int na4 = 2*DD*DD/4, nb4 = FF_*DD/4, nc4 = DD*FF_/4;
        f2h3_kernel<<<(na4+nb4+nc4 + 255)/256, 256>>>(
            in_w + (size_t)DD*DD, wkv16, na4, w1, w1h, nb4, w2, w2h, nc4);
    }
    // 2: layernorm1
    lnw_kernel<<<NROWS/8, 256>>>(x, ln1g, ln1b, xn, xn16);
    // 3: colsum stage 1
    colsum1_kernel<<<dim3(DD/128, BB, 16), 128>>>(xn, csp);
    // 4: KV projection (fp16 out)  <- ncu capture slot
    hgemm<0, __half><<<dim3((2*DD)/128, NROWS/128), 128, HG_SMEM>>>(
        xn16, wkv16, in_b + DD, nullptr, kvh, 2*DD, DD);
    // ranking chain
    colsum2_kernel<<<(BB*DD + 255)/256, 256>>>(csp, cs);
    sparsw_kernel<<<NROWS/8, 256>>>(xn, cs, sp);
    topk_kernel<<<BB, 256>>>(sp, tidx);
    rowproj_kernel<<<BB*TOPQ, 256>>>(xn, tidx, nullptr, nullptr, in_w, in_b, qs);
    // flash attention + combine-projection
    ctxflash_kernel<<<dim3(4, HH, BB), 256>>>(qs, kvh, ctxp, ml);
    rowproj_kernel<<<BB*TOPQ, 256>>>(nullptr, nullptr, ctxp, ml, outw, outb, aout);
    // fused residual + layernorm2
    lnfuse_kernel<<<NROWS/8, 256>>>(x, cs, aout, tidx, ln2g, ln2b, x2, xn2h);
    // FFN
    hgemm<1, __half><<<dim3(FF_/128, NROWS/128), 128, HG_SMEM>>>(
        xn2h, w1h, b1, nullptr, h1h, FF_, DD);
    hgemm<2, float><<<dim3(DD/128, NROWS/128), 128, HG_SMEM>>>(
        h1h, w2h, b2, x2, out, DD, FF_);
    // ratio tail
    if (out_size > NROWS*DD) {
        int tail = out_size - NROWS*DD;
        ratio_kernel<<<(tail + 255)/256, 256>>>(out, out_size);
    }
}

// round 10
// speedup vs baseline: 1.5447x; 1.2133x over previous
#include <cuda_runtime.h>
#include <cuda_fp16.h>
#include <math.h>
#include <stdint.h>

#define BB 8
#define SS 2048
#define DD 512
#define FF_ 2048
#define HH 8
#define DH 64
#define TOPQ 39
#define QPW 5
#define NROWS (BB*SS)   /* 16384 */

// ---------------- static scratch ----------------
__device__ float g_xn  [NROWS*DD];
__device__ float g_x2  [NROWS*DD];
__device__ float g_cs  [BB*DD];
__device__ float g_cspart[16*BB*DD];
__device__ float g_sp  [BB*SS];
__device__ int   g_tidx[BB*TOPQ];
__device__ float g_qs  [BB*TOPQ*DD];
__device__ float g_ctxp[4*BB*TOPQ*DD];
__device__ float2 g_ml [4*BB*HH*TOPQ];
__device__ float g_aout[BB*TOPQ*DD];
// fp16 operands
__device__ __half g_kvh  [NROWS*2*DD];
__device__ __half g_xn16 [NROWS*DD];
__device__ __half g_xn2h [NROWS*DD];
__device__ __half g_h1h  [(size_t)NROWS*FF_];
__device__ __half g_wkv16[2*DD*DD];
__device__ __half g_w1h  [FF_*DD];
__device__ __half g_w2h  [DD*FF_];

// ---------------- helpers ----------------
__device__ __forceinline__ uint32_t s2u(const void* p) {
    uint32_t a;
    asm("{ .reg .u64 t; cvta.to.shared.u64 t, %1; cvt.u32.u64 %0, t; }" : "=r"(a) : "l"(p));
    return a;
}
__device__ __forceinline__ void mma_f16(float* d, const uint32_t* a, const uint32_t* b) {
    asm volatile("mma.sync.aligned.m16n8k16.row.col.f32.f16.f16.f32 "
        "{%0,%1,%2,%3}, {%4,%5,%6,%7}, {%8,%9}, {%0,%1,%2,%3};"
        : "+f"(d[0]), "+f"(d[1]), "+f"(d[2]), "+f"(d[3])
        : "r"(a[0]), "r"(a[1]), "r"(a[2]), "r"(a[3]), "r"(b[0]), "r"(b[1]));
}
__device__ __forceinline__ void ldsm4(uint32_t* r, uint32_t addr) {
    asm volatile("ldmatrix.sync.aligned.m8n8.x4.shared.b16 {%0,%1,%2,%3}, [%4];"
        : "=r"(r[0]), "=r"(r[1]), "=r"(r[2]), "=r"(r[3]) : "r"(addr));
}
__device__ __forceinline__ void cpa16(uint32_t dst, const void* src) {
    asm volatile("cp.async.cg.shared.global [%0], [%1], 16;" :: "r"(dst), "l"(src));
}
__device__ __forceinline__ void cpcommit() {
    asm volatile("cp.async.commit_group;" ::: "memory");
}
template<int N> __device__ __forceinline__ void cpwait() {
    asm volatile("cp.async.wait_group %0;" :: "n"(N) : "memory");
}
__device__ __forceinline__ float gelu_f(float x) {
    return 0.5f * x * (1.0f + erff(x * 0.7071067811865476f));
}

// ====================================================================
// fp16 GEMM: CTA 128x128, 4 warps (2x2), warp tile 64x64 (unchanged R9).
// ====================================================================
#define HG_SMEM (4*16384)

template<int EPI, typename OutT>   // EPI: 0=none, 1=gelu, 2=+res
__global__ __launch_bounds__(128, 2) void hgemm(
    const __half* __restrict__ A, const __half* __restrict__ W,
    const float* __restrict__ bias, const float* __restrict__ res,
    OutT* __restrict__ C, int N, int K)
{
    extern __shared__ __align__(16) char smh[];
    const int tid  = threadIdx.x;
    const int lane = tid & 31;
    const int wid  = tid >> 5;
    const int wm   = wid >> 1;
    const int wn   = wid & 1;
    const int bm = blockIdx.y * 128;
    const int bn = blockIdx.x * 128;
    const uint32_t sb = s2u(smh);

    const __half* Ab = A + (size_t)bm * K;
    const __half* Wb = W + (size_t)bn * K;

    const int crow0 = tid >> 2;
    const int cunit = tid & 3;

    auto ISSUE = [&](int buf, int kbase) {
        uint32_t base = sb + buf * 16384;
        #pragma unroll
        for (int i = 0; i < 4; i++) {
            int row = crow0 + i * 32;
            uint32_t off = row*64 + ((cunit ^ (row&3))*16);
            cpa16(base + off,        Ab + (size_t)row*K + kbase + cunit*8);
            cpa16(base + 8192 + off, Wb + (size_t)row*K + kbase + cunit*8);
        }
        cpcommit();
    };

    float acc[4][8][4];
    #pragma unroll
    for (int a = 0; a < 4; a++)
        #pragma unroll
        for (int b = 0; b < 8; b++)
            #pragma unroll
            for (int c = 0; c < 4; c++) acc[a][b][c] = 0.f;

    const int nk = K >> 5;
    const int lm = lane >> 3;
    const int lr = lane & 7;

    ISSUE(0, 0);
    ISSUE(1, 32);
    ISSUE(2, 64);

    for (int kt = 0; kt < nk; kt++) {
        cpwait<2>();
        __syncthreads();
        if (kt + 3 < nk) ISSUE((kt + 3) & 3, (kt + 3) << 5);
        else             cpcommit();

        int buf = kt & 3;
        uint32_t Abase = sb + buf*16384;
        uint32_t Bbase = Abase + 8192;
        #pragma unroll
        for (int s = 0; s < 2; s++) {
            uint32_t af[4][4];
            #pragma unroll
            for (int mt = 0; mt < 4; mt++) {
                int row = wm*64 + mt*16 + (lm&1)*8 + lr;
                int unit = s*2 + (lm>>1);
                ldsm4(af[mt], Abase + row*64 + ((unit ^ (row&3))*16));
            }
            uint32_t bf[8][2];
            #pragma unroll
            for (int np = 0; np < 4; np++) {
                int nr = wn*64 + (np*2 + (lm>>1))*8 + lr;
                int unit = s*2 + (lm&1);
                uint32_t r[4];
                ldsm4(r, Bbase + nr*64 + ((unit ^ (nr&3))*16));
                bf[np*2][0] = r[0]; bf[np*2][1] = r[1];
                bf[np*2+1][0] = r[2]; bf[np*2+1][1] = r[3];
            }
            #pragma unroll
            for (int mt = 0; mt < 4; mt++)
                #pragma unroll
                for (int nt = 0; nt < 8; nt++)
                    mma_f16(acc[mt][nt], af[mt], bf[nt]);
        }
    }

    const int g = lane >> 2, t = lane & 3;
    #pragma unroll
    for (int mt = 0; mt < 4; mt++) {
        int row0 = bm + wm*64 + mt*16 + g;
        #pragma unroll
        for (int nt = 0; nt < 8; nt++) {
            int col = bn + wn*64 + nt*8 + 2*t;
            float b0 = bias[col], b1 = bias[col+1];
            float v0 = acc[mt][nt][0] + b0;
            float v1 = acc[mt][nt][1] + b1;
            float v2 = acc[mt][nt][2] + b0;
            float v3 = acc[mt][nt][3] + b1;
            if (EPI == 1) {
                v0 = gelu_f(v0); v1 = gelu_f(v1); v2 = gelu_f(v2); v3 = gelu_f(v3);
            }
            if (EPI == 2) {
                const float* r0 = res + (size_t)row0*N + col;
                const float* r1 = res + (size_t)(row0+8)*N + col;
                v0 += r0[0]; v1 += r0[1]; v2 += r1[0]; v3 += r1[1];
            }
            if constexpr (sizeof(OutT) == 2) {
                *(__half2*)&C[(size_t)row0*N + col]     = __floats2half2_rn(v0, v1);
                *(__half2*)&C[(size_t)(row0+8)*N + col] = __floats2half2_rn(v2, v3);
            } else {
                *(float2*)&C[(size_t)row0*N + col]     = make_float2(v0, v1);
                *(float2*)&C[(size_t)(row0+8)*N + col] = make_float2(v2, v3);
            }
        }
    }
}

// ---------------- fp32 -> fp16 bulk convert (3 regions) ----------------
__global__ void f2h3_kernel(const float* __restrict__ a, __half* __restrict__ da, int na4,
                            const float* __restrict__ b, __half* __restrict__ db, int nb4,
                            const float* __restrict__ c, __half* __restrict__ dc, int nc4)
{
    int i = blockIdx.x * 256 + threadIdx.x;
    const float* s; __half* d; int j = i;
    if (j < na4) { s = a; d = da; }
    else {
        j -= na4;
        if (j < nb4) { s = b; d = db; }
        else { j -= nb4; if (j >= nc4) return; s = c; d = dc; }
    }
    float4 v = ((const float4*)s)[j];
    ((__half2*)d)[2*j]   = __floats2half2_rn(v.x, v.y);
    ((__half2*)d)[2*j+1] = __floats2half2_rn(v.z, v.w);
}

// ---------------- layernorm1: warp per row ----------------
__global__ __launch_bounds__(256) void lnw_kernel(const float* __restrict__ x,
        const float* __restrict__ g, const float* __restrict__ bb,
        float* __restrict__ out, __half* __restrict__ out16)
{
    int row  = blockIdx.x * 8 + (threadIdx.x >> 5);
    int lane = threadIdx.x & 31;
    const float4* xr = (const float4*)x + (size_t)row*(DD/4);
    float4 v[4];
    #pragma unroll
    for (int j = 0; j < 4; j++) v[j] = xr[lane + 32*j];
    float s = 0.f;
    #pragma unroll
    for (int j = 0; j < 4; j++) s += v[j].x + v[j].y + v[j].z + v[j].w;
    #pragma unroll
    for (int o = 16; o > 0; o >>= 1) s += __shfl_xor_sync(0xffffffffu, s, o);
    float mean = s * (1.0f/DD);
    float q = 0.f;
    #pragma unroll
    for (int j = 0; j < 4; j++) {
        float a = v[j].x-mean, b = v[j].y-mean, c = v[j].z-mean, d = v[j].w-mean;
        q += a*a + b*b + c*c + d*d;
    }
    #pragma unroll
    for (int o = 16; o > 0; o >>= 1) q += __shfl_xor_sync(0xffffffffu, q, o);
    float inv = rsqrtf(q * (1.0f/DD) + 1e-5f);
    #pragma unroll
    for (int j = 0; j < 4; j++) {
        float4 gg = ((const float4*)g)[lane + 32*j];
        float4 bv = ((const float4*)bb)[lane + 32*j];
        float4 o4 = make_float4(
            (v[j].x-mean)*inv*gg.x + bv.x, (v[j].y-mean)*inv*gg.y + bv.y,
            (v[j].z-mean)*inv*gg.z + bv.z, (v[j].w-mean)*inv*gg.w + bv.w);
        if (out) ((float4*)out)[(size_t)row*(DD/4) + lane + 32*j] = o4;
        if (out16) {
            int base = (int)(lane + 32*j);
            ((__half2*)(out16 + (size_t)row*DD))[2*base]   = __floats2half2_rn(o4.x, o4.y);
            ((__half2*)(out16 + (size_t)row*DD))[2*base+1] = __floats2half2_rn(o4.z, o4.w);
        }
    }
}

// ---------------- fused: residual(base|scatter) + layernorm2 ----------------
__global__ __launch_bounds__(256) void lnfuse_kernel(const float* __restrict__ x,
        const float* __restrict__ cs, const float* __restrict__ aout,
        const int* __restrict__ tidx,
        const float* __restrict__ g, const float* __restrict__ bb,
        float* __restrict__ x2, __half* __restrict__ out16)
{
    int row  = blockIdx.x * 8 + (threadIdx.x >> 5);
    int lane = threadIdx.x & 31;
    int b    = row >> 11;
    int rin  = row & (SS-1);
    __shared__ int stid[TOPQ];
    if (threadIdx.x < TOPQ) stid[threadIdx.x] = tidx[b*TOPQ + threadIdx.x];
    __syncthreads();
    int slot = -1;
    #pragma unroll
    for (int j = 0; j < TOPQ; j++) if (stid[j] == rin) slot = j;

    const float4* xr = (const float4*)x + (size_t)row*(DD/4);
    float4 v[4];
    #pragma unroll
    for (int j = 0; j < 4; j++) v[j] = xr[lane + 32*j];
    if (slot >= 0) {
        const float4* ar = (const float4*)aout + (size_t)(b*TOPQ + slot)*(DD/4);
        #pragma unroll
        for (int j = 0; j < 4; j++) {
            float4 a = ar[lane + 32*j];
            v[j].x += a.x; v[j].y += a.y; v[j].z += a.z; v[j].w += a.w;
        }
    } else {
        const float4* cr = (const float4*)cs + b*(DD/4);
        const float r = 1.0f / SS;
        #pragma unroll
        for (int j = 0; j < 4; j++) {
            float4 c = cr[lane + 32*j];
            v[j].x += c.x*r; v[j].y += c.y*r; v[j].z += c.z*r; v[j].w += c.w*r;
        }
    }
    #pragma unroll
    for (int j = 0; j < 4; j++)
        ((float4*)x2)[(size_t)row*(DD/4) + lane + 32*j] = v[j];
    float s = 0.f;
    #pragma unroll
    for (int j = 0; j < 4; j++) s += v[j].x + v[j].y + v[j].z + v[j].w;
    #pragma unroll
    for (int o = 16; o > 0; o >>= 1) s += __shfl_xor_sync(0xffffffffu, s, o);
    float mean = s * (1.0f/DD);
    float q = 0.f;
    #pragma unroll
    for (int j = 0; j < 4; j++) {
        float a = v[j].x-mean, bq = v[j].y-mean, c = v[j].z-mean, d = v[j].w-mean;
        q += a*a + bq*bq + c*c + d*d;
    }
    #pragma unroll
    for (int o = 16; o > 0; o >>= 1) q += __shfl_xor_sync(0xffffffffu, q, o);
    float inv = rsqrtf(q * (1.0f/DD) + 1e-5f);
    #pragma unroll
    for (int j = 0; j < 4; j++) {
        float4 gg = ((const float4*)g)[lane + 32*j];
        float4 bv = ((const float4*)bb)[lane + 32*j];
        float4 o4 = make_float4(
            (v[j].x-mean)*inv*gg.x + bv.x, (v[j].y-mean)*inv*gg.y + bv.y,
            (v[j].z-mean)*inv*gg.z + bv.z, (v[j].w-mean)*inv*gg.w + bv.w);
        int base = (int)(lane + 32*j);
        ((__half2*)(out16 + (size_t)row*DD))[2*base]   = __floats2half2_rn(o4.x, o4.y);
        ((__half2*)(out16 + (size_t)row*DD))[2*base+1] = __floats2half2_rn(o4.z, o4.w);
    }
}

// ---------------- column sums ----------------
__global__ void colsum1_kernel(const float* __restrict__ xn, float* __restrict__ part)
{
    int b = blockIdx.y;
    int c = blockIdx.z;
    int d = blockIdx.x * 128 + threadIdx.x;
    const float* p = xn + (size_t)b*SS*DD + (size_t)c*128*DD + d;
    float s = 0.f;
    #pragma unroll 8
    for (int k = 0; k < 128; k++) s += p[(size_t)k*DD];
    part[((size_t)c*BB + b)*DD + d] = s;
}
__global__ void colsum2_kernel(const float* __restrict__ part, float* __restrict__ cs)
{
    int i = blockIdx.x * 256 + threadIdx.x;
    if (i < BB*DD) {
        float s = 0.f;
        #pragma unroll
        for (int c = 0; c < 16; c++) s += part[(size_t)c*BB*DD + i];
        cs[i] = s;
    }
}

// ---------------- sparsity ----------------
__global__ __launch_bounds__(256) void sparsw_kernel(const float* __restrict__ xn,
        const float* __restrict__ cs, float* __restrict__ sp)
{
    int row  = blockIdx.x * 8 + (threadIdx.x >> 5);
    int lane = threadIdx.x & 31;
    int b = row >> 11;
    const float4* xr = (const float4*)xn + (size_t)row*(DD/4);
    const float4* cr = (const float4*)cs + b*(DD/4);
    float dp = 0.f, de = 0.f, mp = 0.f, me = 0.f;
    #pragma unroll
    for (int j = 0; j < 4; j++) {
        float4 v = xr[lane + 32*j];
        float4 c = cr[lane + 32*j];
        float vv[4] = {v.x, v.y, v.z, v.w};
        float cc[4] = {c.x, c.y, c.z, c.w};
        #pragma unroll
        for (int e = 0; e < 4; e++) {
            float p = vv[e]*vv[e];
            de += fmaf(vv[e], vv[e], -p);
            dp += p;
            float q = vv[e]*cc[e];
            me += fmaf(vv[e], cc[e], -q);
            mp += q;
        }
    }
    double dd = (double)dp + (double)de;
    double dm = (double)mp + (double)me;
    #pragma unroll
    for (int o = 16; o > 0; o >>= 1) {
        dd += __shfl_xor_sync(0xffffffffu, dd, o);
        dm += __shfl_xor_sync(0xffffffffu, dm, o);
    }
    if (lane == 0)
        sp[row] = (float)((dd - dm * (1.0/SS)) * 0.04419417382415922);
}

// ---------------- top-39 ----------------
__global__ __launch_bounds__(256) void topk_kernel(const float* __restrict__ sp,
        int* __restrict__ tidx)
{
    int b = blockIdx.x;
    int t = threadIdx.x;
    __shared__ float sv[SS];
    __shared__ float rbv[8];
    __shared__ int   rbi[8];
    for (int i = t; i < SS; i += 256) sv[i] = sp[b*SS + i];
    __syncthreads();
    for (int sel = 0; sel < TOPQ; ++sel) {
        float bv = -3.0e38f; int bi = 0;
        for (int i = t; i < SS; i += 256) {
            float v = sv[i];
            if (v > bv || (v == bv && i < bi)) { bv = v; bi = i; }
        }
        #pragma unroll
        for (int o = 16; o > 0; o >>= 1) {
            float ov = __shfl_down_sync(0xffffffffu, bv, o);
            int   oi = __shfl_down_sync(0xffffffffu, bi, o);
            if (ov > bv || (ov == bv && oi < bi)) { bv = ov; bi = oi; }
        }
        if ((t & 31) == 0) { rbv[t >> 5] = bv; rbi[t >> 5] = bi; }
        __syncthreads();
        if (t == 0) {
            float fv = rbv[0]; int fi = rbi[0];
            #pragma unroll
            for (int w = 1; w < 8; w++)
                if (rbv[w] > fv || (rbv[w] == fv && rbi[w] < fi)) { fv = rbv[w]; fi = rbi[w]; }
            tidx[b*TOPQ + sel] = fi;
            sv[fi] = -3.4e38f;
        }
        __syncthreads();
    }
}

// ---------------- flash attention ----------------
__global__ __launch_bounds__(256) void ctxflash_kernel(
    const float* __restrict__ qs, const __half* __restrict__ kvh,
    float* __restrict__ part, float2* __restrict__ ml)
{
    int g = blockIdx.x, h = blockIdx.y, b = blockIdx.z;
    int tid = threadIdx.x, w = tid >> 5, lane = tid & 31;
    __shared__ __half Kt[64][66];
    __shared__ __half Vs[64][64];
    __shared__ float  Qt[64][40];
    __shared__ float  Pw[8][QPW][64];

    for (int i = tid; i < TOPQ*DH; i += 256) {
        int q = i >> 6, d = i & 63;
        Qt[d][q] = qs[((size_t)(b*TOPQ + q))*DD + h*DH + d];
    }
    float2 acc[QPW];
    float m_run[QPW], l_run[QPW];
    #pragma unroll
    for (int iq = 0; iq < QPW; iq++) {
        acc[iq] = make_float2(0.f, 0.f); m_run[iq] = -3.0e38f; l_run[iq] = 0.f;
    }
    __syncthreads();

    for (int t = 0; t < 8; t++) {
        int k0 = g*512 + t*64;
        for (int i = tid; i < 64*32; i += 256) {
            int k = i >> 5, dp = i & 31;
            const __half2* src = (const __half2*)(kvh + ((size_t)(b*SS + k0 + k))*(2*DD) + h*DH) + dp;
            __half2 kk = src[0];
            Kt[2*dp][k]   = __low2half(kk);
            Kt[2*dp+1][k] = __high2half(kk);
            *(__half2*)&Vs[k][2*dp] = src[DD/2];
        }
        __syncthreads();
        #pragma unroll
        for (int iq = 0; iq < QPW; iq++) {
            int q = w + 8*iq;
            if (q < TOPQ) {
                float s0 = 0.f, s1 = 0.f;
                #pragma unroll 8
                for (int d = 0; d < DH; d++) {
                    float qv = Qt[d][q];
                    float2 kk = __half22float2(*(const __half2*)&Kt[d][2*lane]);
                    s0 = fmaf(qv, kk.x, s0);
                    s1 = fmaf(qv, kk.y, s1);
                }
                s0 *= 0.125f; s1 *= 0.125f;
                float mt = fmaxf(s0, s1);
                #pragma unroll
                for (int o = 16; o > 0; o >>= 1)
                    mt = fmaxf(mt, __shfl_xor_sync(0xffffffffu, mt, o));
                float mnew = fmaxf(m_run[iq], mt);
                float p0 = __expf(s0 - mnew), p1 = __expf(s1 - mnew);
                float ps = p0 + p1;
                #pragma unroll
                for (int o = 16; o > 0; o >>= 1)
                    ps += __shfl_xor_sync(0xffffffffu, ps, o);
                float scale = __expf(m_run[iq] - mnew);
                l_run[iq] = l_run[iq]*scale + ps;
                m_run[iq] = mnew;
                Pw[w][iq][2*lane]   = p0;
                Pw[w][iq][2*lane+1] = p1;
                acc[iq].x *= scale; acc[iq].y *= scale;
                __syncwarp();
                #pragma unroll 8
                for (int k = 0; k < 64; k++) {
                    float pv = Pw[w][iq][k];
                    float2 vv = __half22float2(*(const __half2*)&Vs[k][2*lane]);
                    acc[iq].x = fmaf(pv, vv.x, acc[iq].x);
                    acc[iq].y = fmaf(pv, vv.y, acc[iq].y);
                }
            }
        }
        __syncthreads();
    }
    #pragma unroll
    for (int iq = 0; iq < QPW; iq++) {
        int q = w + 8*iq;
        if (q < TOPQ) {
            float* dst = part + (size_t)g*(BB*TOPQ*DD) + ((size_t)(b*TOPQ + q))*DD + h*DH + 2*lane;
            *(float2*)dst = acc[iq];
            if (lane == 0)
                ml[((size_t)(g*BB + b)*HH + h)*TOPQ + q] = make_float2(m_run[iq], l_run[iq]);
        }
    }
}

// ---------------- small projection: 8 rows x 128 cols per block -------------
// grid (DD/128, 39). Gather mode (gidx) or flash-combine mode (part+ml).
// Accumulation order identical to old rowproj -> bit-identical results.
__global__ __launch_bounds__(256) void sproj_kernel(const float* __restrict__ src,
        const int* __restrict__ gidx, const float* __restrict__ part,
        const float2* __restrict__ ml,
        const float* __restrict__ W, const float* __restrict__ bias,
        float* __restrict__ out)
{
    const int r0 = blockIdx.y * 8;
    const int tid = threadIdx.x;
    __shared__ float xr[8][DD];
    __shared__ float wt[8][HH][4];
    if (part) {
        if (tid < 64) {
            int row = tid >> 3, h = tid & 7;
            int r = r0 + row;
            int b = r / TOPQ, q = r % TOPQ;
            float m[4], l[4];
            #pragma unroll
            for (int g = 0; g < 4; g++) {
                float2 v = ml[((size_t)(g*BB + b)*HH + h)*TOPQ + q];
                m[g] = v.x; l[g] = v.y;
            }
            float M = fmaxf(fmaxf(m[0], m[1]), fmaxf(m[2], m[3]));
            float e[4], L = 0.f;
            #pragma unroll
            for (int g = 0; g < 4; g++) { e[g] = __expf(m[g] - M); L += l[g]*e[g]; }
            float invL = 1.0f / L;
            #pragma unroll
            for (int g = 0; g < 4; g++) wt[row][h][g] = e[g]*invL;
        }
        __syncthreads();
        const int N4 = BB*TOPQ*DD/4;
        const float4* p = (const float4*)part;
        for (int i = tid; i < 8*(DD/4); i += 256) {
            int row = i >> 7, c4 = i & 127;
            int h = c4 >> 4;
            size_t idx = (size_t)(r0 + row)*(DD/4) + c4;
            float4 a = p[idx], b4 = p[idx+N4], c = p[idx+2*N4], d = p[idx+3*N4];
            float w0 = wt[row][h][0], w1 = wt[row][h][1],
                  w2 = wt[row][h][2], w3 = wt[row][h][3];
            ((float4*)xr[row])[c4] = make_float4(
                a.x*w0 + b4.x*w1 + c.x*w2 + d.x*w3,
                a.y*w0 + b4.y*w1 + c.y*w2 + d.y*w3,
                a.z*w0 + b4.z*w1 + c.z*w2 + d.z*w3,
                a.w*w0 + b4.w*w1 + c.w*w2 + d.w*w3);
        }
    } else {
        for (int i = tid; i < 8*(DD/4); i += 256) {
            int row = i >> 7, c4 = i & 127;
            int r = r0 + row;
            int b = r / TOPQ;
            const float* srow = src + ((size_t)b*SS + gidx[r]) * DD;
            ((float4*)xr[row])[c4] = ((const float4*)srow)[c4];
        }
    }
    __syncthreads();
    const int jj = blockIdx.x * 128 + (tid & 127);
    const int rh = (tid >> 7) * 4;
    const float4* w4 = (const float4*)(W + (size_t)jj*DD);
    float a0 = 0.f, a1 = 0.f, a2 = 0.f, a3 = 0.f;
    #pragma unroll 4
    for (int k = 0; k < DD/4; k++) {
        float4 w = w4[k];
        float4 x0 = ((float4*)xr[rh+0])[k];
        float4 x1 = ((float4*)xr[rh+1])[k];
        float4 x2 = ((float4*)xr[rh+2])[k];
        float4 x3 = ((float4*)xr[rh+3])[k];
        a0 = fmaf(w.x, x0.x, fmaf(w.y, x0.y, fmaf(w.z, x0.z, fmaf(w.w, x0.w, a0))));
        a1 = fmaf(w.x, x1.x, fmaf(w.y, x1.y, fmaf(w.z, x1.z, fmaf(w.w, x1.w, a1))));
        a2 = fmaf(w.x, x2.x, fmaf(w.y, x2.y, fmaf(w.z, x2.z, fmaf(w.w, x2.w, a2))));
        a3 = fmaf(w.x, x3.x, fmaf(w.y, x3.y, fmaf(w.z, x3.z, fmaf(w.w, x3.w, a3))));
    }
    float bv = bias[jj];
    out[(size_t)(r0 + rh + 0)*DD + jj] = a0 + bv;
    out[(size_t)(r0 + rh + 1)*DD + jj] = a1 + bv;
    out[(size_t)(r0 + rh + 2)*DD + jj] = a2 + bv;
    out[(size_t)(r0 + rh + 3)*DD + jj] = a3 + bv;
}

// ---------------- ratio tail ----------------
__global__ void ratio_kernel(float* out, int out_size)
{
    int i = NROWS*DD + blockIdx.x*blockDim.x + threadIdx.x;
    if (i < out_size) out[i] = (float)TOPQ / (float)SS;
}

// ---------------- launch ----------------
extern "C" void kernel_launch(void* const* d_in, const int* in_sizes, int n_in,
                              void* d_out, int out_size)
{
    const float* x    = (const float*)d_in[0];
    const float* ln1g = (const float*)d_in[1];
    const float* ln1b = (const float*)d_in[2];
    const float* in_w = (const float*)d_in[3];
    const float* in_b = (const float*)d_in[4];
    const float* outw = (const float*)d_in[5];
    const float* outb = (const float*)d_in[6];
    const float* ln2g = (const float*)d_in[7];
    const float* ln2b = (const float*)d_in[8];
    const float* w1   = (const float*)d_in[9];
    const float* b1   = (const float*)d_in[10];
    const float* w2   = (const float*)d_in[11];
    const float* b2   = (const float*)d_in[12];
    float* out = (float*)d_out;

    float *xn, *x2, *cs, *csp, *sp, *qs, *ctxp, *aout;
    float2 *ml;
    __half *kvh, *xn16, *xn2h, *h1h, *wkv16, *w1h, *w2h;
    int *tidx;
    cudaGetSymbolAddress((void**)&xn,    g_xn);
    cudaGetSymbolAddress((void**)&x2,    g_x2);
    cudaGetSymbolAddress((void**)&cs,    g_cs);
    cudaGetSymbolAddress((void**)&csp,   g_cspart);
    cudaGetSymbolAddress((void**)&sp,    g_sp);
    cudaGetSymbolAddress((void**)&qs,    g_qs);
    cudaGetSymbolAddress((void**)&ctxp,  g_ctxp);
    cudaGetSymbolAddress((void**)&ml,    g_ml);
    cudaGetSymbolAddress((void**)&aout,  g_aout);
    cudaGetSymbolAddress((void**)&tidx,  g_tidx);
    cudaGetSymbolAddress((void**)&kvh,   g_kvh);
    cudaGetSymbolAddress((void**)&xn16,  g_xn16);
    cudaGetSymbolAddress((void**)&xn2h,  g_xn2h);
    cudaGetSymbolAddress((void**)&h1h,   g_h1h);
    cudaGetSymbolAddress((void**)&wkv16, g_wkv16);
    cudaGetSymbolAddress((void**)&w1h,   g_w1h);
    cudaGetSymbolAddress((void**)&w2h,   g_w2h);

    cudaFuncSetAttribute(hgemm<0, __half>, cudaFuncAttributeMaxDynamicSharedMemorySize, HG_SMEM);
    cudaFuncSetAttribute(hgemm<1, __half>, cudaFuncAttributeMaxDynamicSharedMemorySize, HG_SMEM);
    cudaFuncSetAttribute(hgemm<2, float>,  cudaFuncAttributeMaxDynamicSharedMemorySize, HG_SMEM);

    // 1: weight conversions
    {
        int na4 = 2*DD*DD/4, nb4 = FF_*DD/4, nc4 = DD*FF_/4;
        f2h3_kernel<<<(na4+nb4+nc4 + 255)/256, 256>>>(
            in_w + (size_t)DD*DD, wkv16, na4, w1, w1h, nb4, w2, w2h, nc4);
    }
    // 2: layernorm1
    lnw_kernel<<<NROWS/8, 256>>>(x, ln1g, ln1b, xn, xn16);
    // 3: colsum stage 1
    colsum1_kernel<<<dim3(DD/128, BB, 16), 128>>>(xn, csp);
    // 4: KV projection  <- ncu capture slot
    hgemm<0, __half><<<dim3((2*DD)/128, NROWS/128), 128, HG_SMEM>>>(
        xn16, wkv16, in_b + DD, nullptr, kvh, 2*DD, DD);
    // ranking chain
    colsum2_kernel<<<(BB*DD + 255)/256, 256>>>(csp, cs);
    sparsw_kernel<<<NROWS/8, 256>>>(xn, cs, sp);
    topk_kernel<<<BB, 256>>>(sp, tidx);
    sproj_kernel<<<dim3(DD/128, 39), 256>>>(xn, tidx, nullptr, nullptr, in_w, in_b, qs);
    // flash attention + combine-projection
    ctxflash_kernel<<<dim3(4, HH, BB), 256>>>(qs, kvh, ctxp, ml);
    sproj_kernel<<<dim3(DD/128, 39), 256>>>(nullptr, nullptr, ctxp, ml, outw, outb, aout);
    // fused residual + layernorm2
    lnfuse_kernel<<<NROWS/8, 256>>>(x, cs, aout, tidx, ln2g, ln2b, x2, xn2h);
    // FFN
    hgemm<1, __half><<<dim3(FF_/128, NROWS/128), 128, HG_SMEM>>>(
        xn2h, w1h, b1, nullptr, h1h, FF_, DD);
    hgemm<2, float><<<dim3(DD/128, NROWS/128), 128, HG_SMEM>>>(
        h1h, w2h, b2, x2, out, DD, FF_);
    // ratio tail
    if (out_size > NROWS*DD) {
        int tail = out_size - NROWS*DD;
        ratio_kernel<<<(tail + 255)/256, 256>>>(out, out_size);
    }
}

// round 11
// speedup vs baseline: 1.5796x; 1.0226x over previous
#include <cuda_runtime.h>
#include <cuda_fp16.h>
#include <math.h>
#include <stdint.h>

#define BB 8
#define SS 2048
#define DD 512
#define FF_ 2048
#define HH 8
#define DH 64
#define TOPQ 39
#define QPW 5
#define NROWS (BB*SS)   /* 16384 */

// ---------------- static scratch ----------------
__device__ float g_xn  [NROWS*DD];
__device__ float g_x2  [NROWS*DD];
__device__ float g_cs  [BB*DD];
__device__ float g_cspart[16*BB*DD];
__device__ float g_sp  [BB*SS];
__device__ int   g_tidx[BB*TOPQ];
__device__ float g_qs  [BB*TOPQ*DD];
__device__ float g_ctxp[4*BB*TOPQ*DD];
__device__ float2 g_ml [4*BB*HH*TOPQ];
__device__ float g_aout[BB*TOPQ*DD];
// fp16 operands
__device__ __half g_kvh  [NROWS*2*DD];
__device__ __half g_xn16 [NROWS*DD];
__device__ __half g_xn2h [NROWS*DD];
__device__ __half g_h1h  [(size_t)NROWS*FF_];
__device__ __half g_wkv16[2*DD*DD];
__device__ __half g_w1h  [FF_*DD];
__device__ __half g_w2h  [DD*FF_];

// ---------------- helpers ----------------
__device__ __forceinline__ uint32_t s2u(const void* p) {
    uint32_t a;
    asm("{ .reg .u64 t; cvta.to.shared.u64 t, %1; cvt.u32.u64 %0, t; }" : "=r"(a) : "l"(p));
    return a;
}
__device__ __forceinline__ void mma_f16(float* d, const uint32_t* a, const uint32_t* b) {
    asm volatile("mma.sync.aligned.m16n8k16.row.col.f32.f16.f16.f32 "
        "{%0,%1,%2,%3}, {%4,%5,%6,%7}, {%8,%9}, {%0,%1,%2,%3};"
        : "+f"(d[0]), "+f"(d[1]), "+f"(d[2]), "+f"(d[3])
        : "r"(a[0]), "r"(a[1]), "r"(a[2]), "r"(a[3]), "r"(b[0]), "r"(b[1]));
}
__device__ __forceinline__ void ldsm4(uint32_t* r, uint32_t addr) {
    asm volatile("ldmatrix.sync.aligned.m8n8.x4.shared.b16 {%0,%1,%2,%3}, [%4];"
        : "=r"(r[0]), "=r"(r[1]), "=r"(r[2]), "=r"(r[3]) : "r"(addr));
}
__device__ __forceinline__ void cpa16(uint32_t dst, const void* src) {
    asm volatile("cp.async.cg.shared.global [%0], [%1], 16;" :: "r"(dst), "l"(src));
}
__device__ __forceinline__ void cpcommit() {
    asm volatile("cp.async.commit_group;" ::: "memory");
}
template<int N> __device__ __forceinline__ void cpwait() {
    asm volatile("cp.async.wait_group %0;" :: "n"(N) : "memory");
}
__device__ __forceinline__ float gelu_f(float x) {
    return 0.5f * x * (1.0f + erff(x * 0.7071067811865476f));
}

// ====================================================================
// fp16 GEMM: CTA 128x128, 4 warps (2x2), warp tile 64x64 (unchanged).
// ====================================================================
#define HG_SMEM (4*16384)

template<int EPI, typename OutT>   // EPI: 0=none, 1=gelu, 2=+res
__global__ __launch_bounds__(128, 2) void hgemm(
    const __half* __restrict__ A, const __half* __restrict__ W,
    const float* __restrict__ bias, const float* __restrict__ res,
    OutT* __restrict__ C, int N, int K)
{
    extern __shared__ __align__(16) char smh[];
    const int tid  = threadIdx.x;
    const int lane = tid & 31;
    const int wid  = tid >> 5;
    const int wm   = wid >> 1;
    const int wn   = wid & 1;
    const int bm = blockIdx.y * 128;
    const int bn = blockIdx.x * 128;
    const uint32_t sb = s2u(smh);

    const __half* Ab = A + (size_t)bm * K;
    const __half* Wb = W + (size_t)bn * K;

    const int crow0 = tid >> 2;
    const int cunit = tid & 3;

    auto ISSUE = [&](int buf, int kbase) {
        uint32_t base = sb + buf * 16384;
        #pragma unroll
        for (int i = 0; i < 4; i++) {
            int row = crow0 + i * 32;
            uint32_t off = row*64 + ((cunit ^ (row&3))*16);
            cpa16(base + off,        Ab + (size_t)row*K + kbase + cunit*8);
            cpa16(base + 8192 + off, Wb + (size_t)row*K + kbase + cunit*8);
        }
        cpcommit();
    };

    float acc[4][8][4];
    #pragma unroll
    for (int a = 0; a < 4; a++)
        #pragma unroll
        for (int b = 0; b < 8; b++)
            #pragma unroll
            for (int c = 0; c < 4; c++) acc[a][b][c] = 0.f;

    const int nk = K >> 5;
    const int lm = lane >> 3;
    const int lr = lane & 7;

    ISSUE(0, 0);
    ISSUE(1, 32);
    ISSUE(2, 64);

    for (int kt = 0; kt < nk; kt++) {
        cpwait<2>();
        __syncthreads();
        if (kt + 3 < nk) ISSUE((kt + 3) & 3, (kt + 3) << 5);
        else             cpcommit();

        int buf = kt & 3;
        uint32_t Abase = sb + buf*16384;
        uint32_t Bbase = Abase + 8192;
        #pragma unroll
        for (int s = 0; s < 2; s++) {
            uint32_t af[4][4];
            #pragma unroll
            for (int mt = 0; mt < 4; mt++) {
                int row = wm*64 + mt*16 + (lm&1)*8 + lr;
                int unit = s*2 + (lm>>1);
                ldsm4(af[mt], Abase + row*64 + ((unit ^ (row&3))*16));
            }
            uint32_t bf[8][2];
            #pragma unroll
            for (int np = 0; np < 4; np++) {
                int nr = wn*64 + (np*2 + (lm>>1))*8 + lr;
                int unit = s*2 + (lm&1);
                uint32_t r[4];
                ldsm4(r, Bbase + nr*64 + ((unit ^ (nr&3))*16));
                bf[np*2][0] = r[0]; bf[np*2][1] = r[1];
                bf[np*2+1][0] = r[2]; bf[np*2+1][1] = r[3];
            }
            #pragma unroll
            for (int mt = 0; mt < 4; mt++)
                #pragma unroll
                for (int nt = 0; nt < 8; nt++)
                    mma_f16(acc[mt][nt], af[mt], bf[nt]);
        }
    }

    const int g = lane >> 2, t = lane & 3;
    #pragma unroll
    for (int mt = 0; mt < 4; mt++) {
        int row0 = bm + wm*64 + mt*16 + g;
        #pragma unroll
        for (int nt = 0; nt < 8; nt++) {
            int col = bn + wn*64 + nt*8 + 2*t;
            float b0 = bias[col], b1 = bias[col+1];
            float v0 = acc[mt][nt][0] + b0;
            float v1 = acc[mt][nt][1] + b1;
            float v2 = acc[mt][nt][2] + b0;
            float v3 = acc[mt][nt][3] + b1;
            if (EPI == 1) {
                v0 = gelu_f(v0); v1 = gelu_f(v1); v2 = gelu_f(v2); v3 = gelu_f(v3);
            }
            if (EPI == 2) {
                const float* r0 = res + (size_t)row0*N + col;
                const float* r1 = res + (size_t)(row0+8)*N + col;
                v0 += r0[0]; v1 += r0[1]; v2 += r1[0]; v3 += r1[1];
            }
            if constexpr (sizeof(OutT) == 2) {
                *(__half2*)&C[(size_t)row0*N + col]     = __floats2half2_rn(v0, v1);
                *(__half2*)&C[(size_t)(row0+8)*N + col] = __floats2half2_rn(v2, v3);
            } else {
                *(float2*)&C[(size_t)row0*N + col]     = make_float2(v0, v1);
                *(float2*)&C[(size_t)(row0+8)*N + col] = make_float2(v2, v3);
            }
        }
    }
}

// ---------------- fp32 -> fp16 bulk convert (3 regions) ----------------
__global__ void f2h3_kernel(const float* __restrict__ a, __half* __restrict__ da, int na4,
                            const float* __restrict__ b, __half* __restrict__ db, int nb4,
                            const float* __restrict__ c, __half* __restrict__ dc, int nc4)
{
    int i = blockIdx.x * 256 + threadIdx.x;
    const float* s; __half* d; int j = i;
    if (j < na4) { s = a; d = da; }
    else {
        j -= na4;
        if (j < nb4) { s = b; d = db; }
        else { j -= nb4; if (j >= nc4) return; s = c; d = dc; }
    }
    float4 v = ((const float4*)s)[j];
    ((__half2*)d)[2*j]   = __floats2half2_rn(v.x, v.y);
    ((__half2*)d)[2*j+1] = __floats2half2_rn(v.z, v.w);
}

// ---------------- layernorm1: warp per row ----------------
__global__ __launch_bounds__(256) void lnw_kernel(const float* __restrict__ x,
        const float* __restrict__ g, const float* __restrict__ bb,
        float* __restrict__ out, __half* __restrict__ out16)
{
    int row  = blockIdx.x * 8 + (threadIdx.x >> 5);
    int lane = threadIdx.x & 31;
    const float4* xr = (const float4*)x + (size_t)row*(DD/4);
    float4 v[4];
    #pragma unroll
    for (int j = 0; j < 4; j++) v[j] = xr[lane + 32*j];
    float s = 0.f;
    #pragma unroll
    for (int j = 0; j < 4; j++) s += v[j].x + v[j].y + v[j].z + v[j].w;
    #pragma unroll
    for (int o = 16; o > 0; o >>= 1) s += __shfl_xor_sync(0xffffffffu, s, o);
    float mean = s * (1.0f/DD);
    float q = 0.f;
    #pragma unroll
    for (int j = 0; j < 4; j++) {
        float a = v[j].x-mean, b = v[j].y-mean, c = v[j].z-mean, d = v[j].w-mean;
        q += a*a + b*b + c*c + d*d;
    }
    #pragma unroll
    for (int o = 16; o > 0; o >>= 1) q += __shfl_xor_sync(0xffffffffu, q, o);
    float inv = rsqrtf(q * (1.0f/DD) + 1e-5f);
    #pragma unroll
    for (int j = 0; j < 4; j++) {
        float4 gg = ((const float4*)g)[lane + 32*j];
        float4 bv = ((const float4*)bb)[lane + 32*j];
        float4 o4 = make_float4(
            (v[j].x-mean)*inv*gg.x + bv.x, (v[j].y-mean)*inv*gg.y + bv.y,
            (v[j].z-mean)*inv*gg.z + bv.z, (v[j].w-mean)*inv*gg.w + bv.w);
        if (out) ((float4*)out)[(size_t)row*(DD/4) + lane + 32*j] = o4;
        if (out16) {
            int base = (int)(lane + 32*j);
            ((__half2*)(out16 + (size_t)row*DD))[2*base]   = __floats2half2_rn(o4.x, o4.y);
            ((__half2*)(out16 + (size_t)row*DD))[2*base+1] = __floats2half2_rn(o4.z, o4.w);
        }
    }
}

// ---------------- fused: residual(base|scatter) + layernorm2 ----------------
__global__ __launch_bounds__(256) void lnfuse_kernel(const float* __restrict__ x,
        const float* __restrict__ cs, const float* __restrict__ aout,
        const int* __restrict__ tidx,
        const float* __restrict__ g, const float* __restrict__ bb,
        float* __restrict__ x2, __half* __restrict__ out16)
{
    int row  = blockIdx.x * 8 + (threadIdx.x >> 5);
    int lane = threadIdx.x & 31;
    int b    = row >> 11;
    int rin  = row & (SS-1);
    __shared__ int stid[TOPQ];
    if (threadIdx.x < TOPQ) stid[threadIdx.x] = tidx[b*TOPQ + threadIdx.x];
    __syncthreads();
    int slot = -1;
    #pragma unroll
    for (int j = 0; j < TOPQ; j++) if (stid[j] == rin) slot = j;

    const float4* xr = (const float4*)x + (size_t)row*(DD/4);
    float4 v[4];
    #pragma unroll
    for (int j = 0; j < 4; j++) v[j] = xr[lane + 32*j];
    if (slot >= 0) {
        const float4* ar = (const float4*)aout + (size_t)(b*TOPQ + slot)*(DD/4);
        #pragma unroll
        for (int j = 0; j < 4; j++) {
            float4 a = ar[lane + 32*j];
            v[j].x += a.x; v[j].y += a.y; v[j].z += a.z; v[j].w += a.w;
        }
    } else {
        const float4* cr = (const float4*)cs + b*(DD/4);
        const float r = 1.0f / SS;
        #pragma unroll
        for (int j = 0; j < 4; j++) {
            float4 c = cr[lane + 32*j];
            v[j].x += c.x*r; v[j].y += c.y*r; v[j].z += c.z*r; v[j].w += c.w*r;
        }
    }
    #pragma unroll
    for (int j = 0; j < 4; j++)
        ((float4*)x2)[(size_t)row*(DD/4) + lane + 32*j] = v[j];
    float s = 0.f;
    #pragma unroll
    for (int j = 0; j < 4; j++) s += v[j].x + v[j].y + v[j].z + v[j].w;
    #pragma unroll
    for (int o = 16; o > 0; o >>= 1) s += __shfl_xor_sync(0xffffffffu, s, o);
    float mean = s * (1.0f/DD);
    float q = 0.f;
    #pragma unroll
    for (int j = 0; j < 4; j++) {
        float a = v[j].x-mean, bq = v[j].y-mean, c = v[j].z-mean, d = v[j].w-mean;
        q += a*a + bq*bq + c*c + d*d;
    }
    #pragma unroll
    for (int o = 16; o > 0; o >>= 1) q += __shfl_xor_sync(0xffffffffu, q, o);
    float inv = rsqrtf(q * (1.0f/DD) + 1e-5f);
    #pragma unroll
    for (int j = 0; j < 4; j++) {
        float4 gg = ((const float4*)g)[lane + 32*j];
        float4 bv = ((const float4*)bb)[lane + 32*j];
        float4 o4 = make_float4(
            (v[j].x-mean)*inv*gg.x + bv.x, (v[j].y-mean)*inv*gg.y + bv.y,
            (v[j].z-mean)*inv*gg.z + bv.z, (v[j].w-mean)*inv*gg.w + bv.w);
        int base = (int)(lane + 32*j);
        ((__half2*)(out16 + (size_t)row*DD))[2*base]   = __floats2half2_rn(o4.x, o4.y);
        ((__half2*)(out16 + (size_t)row*DD))[2*base+1] = __floats2half2_rn(o4.z, o4.w);
    }
}

// ---------------- column sums ----------------
__global__ void colsum1_kernel(const float* __restrict__ xn, float* __restrict__ part)
{
    int b = blockIdx.y;
    int c = blockIdx.z;
    int d = blockIdx.x * 128 + threadIdx.x;
    const float* p = xn + (size_t)b*SS*DD + (size_t)c*128*DD + d;
    float s = 0.f;
    #pragma unroll 8
    for (int k = 0; k < 128; k++) s += p[(size_t)k*DD];
    part[((size_t)c*BB + b)*DD + d] = s;
}
__global__ void colsum2_kernel(const float* __restrict__ part, float* __restrict__ cs)
{
    int i = blockIdx.x * 256 + threadIdx.x;
    if (i < BB*DD) {
        float s = 0.f;
        #pragma unroll
        for (int c = 0; c < 16; c++) s += part[(size_t)c*BB*DD + i];
        cs[i] = s;
    }
}

// ---------------- sparsity ----------------
__global__ __launch_bounds__(256) void sparsw_kernel(const float* __restrict__ xn,
        const float* __restrict__ cs, float* __restrict__ sp)
{
    int row  = blockIdx.x * 8 + (threadIdx.x >> 5);
    int lane = threadIdx.x & 31;
    int b = row >> 11;
    const float4* xr = (const float4*)xn + (size_t)row*(DD/4);
    const float4* cr = (const float4*)cs + b*(DD/4);
    float dp = 0.f, de = 0.f, mp = 0.f, me = 0.f;
    #pragma unroll
    for (int j = 0; j < 4; j++) {
        float4 v = xr[lane + 32*j];
        float4 c = cr[lane + 32*j];
        float vv[4] = {v.x, v.y, v.z, v.w};
        float cc[4] = {c.x, c.y, c.z, c.w};
        #pragma unroll
        for (int e = 0; e < 4; e++) {
            float p = vv[e]*vv[e];
            de += fmaf(vv[e], vv[e], -p);
            dp += p;
            float q = vv[e]*cc[e];
            me += fmaf(vv[e], cc[e], -q);
            mp += q;
        }
    }
    double dd = (double)dp + (double)de;
    double dm = (double)mp + (double)me;
    #pragma unroll
    for (int o = 16; o > 0; o >>= 1) {
        dd += __shfl_xor_sync(0xffffffffu, dd, o);
        dm += __shfl_xor_sync(0xffffffffu, dm, o);
    }
    if (lane == 0)
        sp[row] = (float)((dd - dm * (1.0/SS)) * 0.04419417382415922);
}

// ---------------- top-39 ----------------
__global__ __launch_bounds__(256) void topk_kernel(const float* __restrict__ sp,
        int* __restrict__ tidx)
{
    int b = blockIdx.x;
    int t = threadIdx.x;
    __shared__ float sv[SS];
    __shared__ float rbv[8];
    __shared__ int   rbi[8];
    for (int i = t; i < SS; i += 256) sv[i] = sp[b*SS + i];
    __syncthreads();
    for (int sel = 0; sel < TOPQ; ++sel) {
        float bv = -3.0e38f; int bi = 0;
        for (int i = t; i < SS; i += 256) {
            float v = sv[i];
            if (v > bv || (v == bv && i < bi)) { bv = v; bi = i; }
        }
        #pragma unroll
        for (int o = 16; o > 0; o >>= 1) {
            float ov = __shfl_down_sync(0xffffffffu, bv, o);
            int   oi = __shfl_down_sync(0xffffffffu, bi, o);
            if (ov > bv || (ov == bv && oi < bi)) { bv = ov; bi = oi; }
        }
        if ((t & 31) == 0) { rbv[t >> 5] = bv; rbi[t >> 5] = bi; }
        __syncthreads();
        if (t == 0) {
            float fv = rbv[0]; int fi = rbi[0];
            #pragma unroll
            for (int w = 1; w < 8; w++)
                if (rbv[w] > fv || (rbv[w] == fv && rbi[w] < fi)) { fv = rbv[w]; fi = rbi[w]; }
            tidx[b*TOPQ + sel] = fi;
            sv[fi] = -3.4e38f;
        }
        __syncthreads();
    }
}

// ---------------- flash attention ----------------
__global__ __launch_bounds__(256) void ctxflash_kernel(
    const float* __restrict__ qs, const __half* __restrict__ kvh,
    float* __restrict__ part, float2* __restrict__ ml)
{
    int g = blockIdx.x, h = blockIdx.y, b = blockIdx.z;
    int tid = threadIdx.x, w = tid >> 5, lane = tid & 31;
    __shared__ __half Kt[64][66];
    __shared__ __half Vs[64][64];
    __shared__ float  Qt[64][40];
    __shared__ float  Pw[8][QPW][64];

    for (int i = tid; i < TOPQ*DH; i += 256) {
        int q = i >> 6, d = i & 63;
        Qt[d][q] = qs[((size_t)(b*TOPQ + q))*DD + h*DH + d];
    }
    float2 acc[QPW];
    float m_run[QPW], l_run[QPW];
    #pragma unroll
    for (int iq = 0; iq < QPW; iq++) {
        acc[iq] = make_float2(0.f, 0.f); m_run[iq] = -3.0e38f; l_run[iq] = 0.f;
    }
    __syncthreads();

    for (int t = 0; t < 8; t++) {
        int k0 = g*512 + t*64;
        for (int i = tid; i < 64*32; i += 256) {
            int k = i >> 5, dp = i & 31;
            const __half2* src = (const __half2*)(kvh + ((size_t)(b*SS + k0 + k))*(2*DD) + h*DH) + dp;
            __half2 kk = src[0];
            Kt[2*dp][k]   = __low2half(kk);
            Kt[2*dp+1][k] = __high2half(kk);
            *(__half2*)&Vs[k][2*dp] = src[DD/2];
        }
        __syncthreads();
        #pragma unroll
        for (int iq = 0; iq < QPW; iq++) {
            int q = w + 8*iq;
            if (q < TOPQ) {
                float s0 = 0.f, s1 = 0.f;
                #pragma unroll 8
                for (int d = 0; d < DH; d++) {
                    float qv = Qt[d][q];
                    float2 kk = __half22float2(*(const __half2*)&Kt[d][2*lane]);
                    s0 = fmaf(qv, kk.x, s0);
                    s1 = fmaf(qv, kk.y, s1);
                }
                s0 *= 0.125f; s1 *= 0.125f;
                float mt = fmaxf(s0, s1);
                #pragma unroll
                for (int o = 16; o > 0; o >>= 1)
                    mt = fmaxf(mt, __shfl_xor_sync(0xffffffffu, mt, o));
                float mnew = fmaxf(m_run[iq], mt);
                float p0 = __expf(s0 - mnew), p1 = __expf(s1 - mnew);
                float ps = p0 + p1;
                #pragma unroll
                for (int o = 16; o > 0; o >>= 1)
                    ps += __shfl_xor_sync(0xffffffffu, ps, o);
                float scale = __expf(m_run[iq] - mnew);
                l_run[iq] = l_run[iq]*scale + ps;
                m_run[iq] = mnew;
                Pw[w][iq][2*lane]   = p0;
                Pw[w][iq][2*lane+1] = p1;
                acc[iq].x *= scale; acc[iq].y *= scale;
                __syncwarp();
                #pragma unroll 8
                for (int k = 0; k < 64; k++) {
                    float pv = Pw[w][iq][k];
                    float2 vv = __half22float2(*(const __half2*)&Vs[k][2*lane]);
                    acc[iq].x = fmaf(pv, vv.x, acc[iq].x);
                    acc[iq].y = fmaf(pv, vv.y, acc[iq].y);
                }
            }
        }
        __syncthreads();
    }
    #pragma unroll
    for (int iq = 0; iq < QPW; iq++) {
        int q = w + 8*iq;
        if (q < TOPQ) {
            float* dst = part + (size_t)g*(BB*TOPQ*DD) + ((size_t)(b*TOPQ + q))*DD + h*DH + 2*lane;
            *(float2*)dst = acc[iq];
            if (lane == 0)
                ml[((size_t)(g*BB + b)*HH + h)*TOPQ + q] = make_float2(m_run[iq], l_run[iq]);
        }
    }
}

// ---------------- small projection: 8 rows x 128 cols per block -------------
__global__ __launch_bounds__(256) void sproj_kernel(const float* __restrict__ src,
        const int* __restrict__ gidx, const float* __restrict__ part,
        const float2* __restrict__ ml,
        const float* __restrict__ W, const float* __restrict__ bias,
        float* __restrict__ out)
{
    const int r0 = blockIdx.y * 8;
    const int tid = threadIdx.x;
    __shared__ float xr[8][DD];
    __shared__ float wt[8][HH][4];
    if (part) {
        if (tid < 64) {
            int row = tid >> 3, h = tid & 7;
            int r = r0 + row;
            int b = r / TOPQ, q = r % TOPQ;
            float m[4], l[4];
            #pragma unroll
            for (int g = 0; g < 4; g++) {
                float2 v = ml[((size_t)(g*BB + b)*HH + h)*TOPQ + q];
                m[g] = v.x; l[g] = v.y;
            }
            float M = fmaxf(fmaxf(m[0], m[1]), fmaxf(m[2], m[3]));
            float e[4], L = 0.f;
            #pragma unroll
            for (int g = 0; g < 4; g++) { e[g] = __expf(m[g] - M); L += l[g]*e[g]; }
            float invL = 1.0f / L;
            #pragma unroll
            for (int g = 0; g < 4; g++) wt[row][h][g] = e[g]*invL;
        }
        __syncthreads();
        const int N4 = BB*TOPQ*DD/4;
        const float4* p = (const float4*)part;
        for (int i = tid; i < 8*(DD/4); i += 256) {
            int row = i >> 7, c4 = i & 127;
            int h = c4 >> 4;
            size_t idx = (size_t)(r0 + row)*(DD/4) + c4;
            float4 a = p[idx], b4 = p[idx+N4], c = p[idx+2*N4], d = p[idx+3*N4];
            float w0 = wt[row][h][0], w1 = wt[row][h][1],
                  w2 = wt[row][h][2], w3 = wt[row][h][3];
            ((float4*)xr[row])[c4] = make_float4(
                a.x*w0 + b4.x*w1 + c.x*w2 + d.x*w3,
                a.y*w0 + b4.y*w1 + c.y*w2 + d.y*w3,
                a.z*w0 + b4.z*w1 + c.z*w2 + d.z*w3,
                a.w*w0 + b4.w*w1 + c.w*w2 + d.w*w3);
        }
    } else {
        for (int i = tid; i < 8*(DD/4); i += 256) {
            int row = i >> 7, c4 = i & 127;
            int r = r0 + row;
            int b = r / TOPQ;
            const float* srow = src + ((size_t)b*SS + gidx[r]) * DD;
            ((float4*)xr[row])[c4] = ((const float4*)srow)[c4];
        }
    }
    __syncthreads();
    const int jj = blockIdx.x * 128 + (tid & 127);
    const int rh = (tid >> 7) * 4;
    const float4* w4 = (const float4*)(W + (size_t)jj*DD);
    float a0 = 0.f, a1 = 0.f, a2 = 0.f, a3 = 0.f;
    #pragma unroll 4
    for (int k = 0; k < DD/4; k++) {
        float4 w = w4[k];
        float4 x0 = ((float4*)xr[rh+0])[k];
        float4 x1 = ((float4*)xr[rh+1])[k];
        float4 x2 = ((float4*)xr[rh+2])[k];
        float4 x3 = ((float4*)xr[rh+3])[k];
        a0 = fmaf(w.x, x0.x, fmaf(w.y, x0.y, fmaf(w.z, x0.z, fmaf(w.w, x0.w, a0))));
        a1 = fmaf(w.x, x1.x, fmaf(w.y, x1.y, fmaf(w.z, x1.z, fmaf(w.w, x1.w, a1))));
        a2 = fmaf(w.x, x2.x, fmaf(w.y, x2.y, fmaf(w.z, x2.z, fmaf(w.w, x2.w, a2))));
        a3 = fmaf(w.x, x3.x, fmaf(w.y, x3.y, fmaf(w.z, x3.z, fmaf(w.w, x3.w, a3))));
    }
    float bv = bias[jj];
    out[(size_t)(r0 + rh + 0)*DD + jj] = a0 + bv;
    out[(size_t)(r0 + rh + 1)*DD + jj] = a1 + bv;
    out[(size_t)(r0 + rh + 2)*DD + jj] = a2 + bv;
    out[(size_t)(r0 + rh + 3)*DD + jj] = a3 + bv;
}

// ---------------- ratio tail ----------------
__global__ void ratio_kernel(float* out, int out_size)
{
    int i = NROWS*DD + blockIdx.x*blockDim.x + threadIdx.x;
    if (i < out_size) out[i] = (float)TOPQ / (float)SS;
}

// ---------------- launch (multi-stream fork/join for overlap) ----------------
extern "C" void kernel_launch(void* const* d_in, const int* in_sizes, int n_in,
                              void* d_out, int out_size)
{
    const float* x    = (const float*)d_in[0];
    const float* ln1g = (const float*)d_in[1];
    const float* ln1b = (const float*)d_in[2];
    const float* in_w = (const float*)d_in[3];
    const float* in_b = (const float*)d_in[4];
    const float* outw = (const float*)d_in[5];
    const float* outb = (const float*)d_in[6];
    const float* ln2g = (const float*)d_in[7];
    const float* ln2b = (const float*)d_in[8];
    const float* w1   = (const float*)d_in[9];
    const float* b1   = (const float*)d_in[10];
    const float* w2   = (const float*)d_in[11];
    const float* b2   = (const float*)d_in[12];
    float* out = (float*)d_out;

    float *xn, *x2, *cs, *csp, *sp, *qs, *ctxp, *aout;
    float2 *ml;
    __half *kvh, *xn16, *xn2h, *h1h, *wkv16, *w1h, *w2h;
    int *tidx;
    cudaGetSymbolAddress((void**)&xn,    g_xn);
    cudaGetSymbolAddress((void**)&x2,    g_x2);
    cudaGetSymbolAddress((void**)&cs,    g_cs);
    cudaGetSymbolAddress((void**)&csp,   g_cspart);
    cudaGetSymbolAddress((void**)&sp,    g_sp);
    cudaGetSymbolAddress((void**)&qs,    g_qs);
    cudaGetSymbolAddress((void**)&ctxp,  g_ctxp);
    cudaGetSymbolAddress((void**)&ml,    g_ml);
    cudaGetSymbolAddress((void**)&aout,  g_aout);
    cudaGetSymbolAddress((void**)&tidx,  g_tidx);
    cudaGetSymbolAddress((void**)&kvh,   g_kvh);
    cudaGetSymbolAddress((void**)&xn16,  g_xn16);
    cudaGetSymbolAddress((void**)&xn2h,  g_xn2h);
    cudaGetSymbolAddress((void**)&h1h,   g_h1h);
    cudaGetSymbolAddress((void**)&wkv16, g_wkv16);
    cudaGetSymbolAddress((void**)&w1h,   g_w1h);
    cudaGetSymbolAddress((void**)&w2h,   g_w2h);

    cudaFuncSetAttribute(hgemm<0, __half>, cudaFuncAttributeMaxDynamicSharedMemorySize, HG_SMEM);
    cudaFuncSetAttribute(hgemm<1, __half>, cudaFuncAttributeMaxDynamicSharedMemorySize, HG_SMEM);
    cudaFuncSetAttribute(hgemm<2, float>,  cudaFuncAttributeMaxDynamicSharedMemorySize, HG_SMEM);

    // Side streams + events, created once on the first (uncaptured) call.
    static cudaStream_t sA = nullptr, sB = nullptr;
    static cudaEvent_t eFork = nullptr, eF2h = nullptr, eCs1 = nullptr, eRank = nullptr;
    if (!sA) {
        cudaStreamCreateWithFlags(&sA, cudaStreamNonBlocking);
        cudaStreamCreateWithFlags(&sB, cudaStreamNonBlocking);
        cudaEventCreateWithFlags(&eFork, cudaEventDisableTiming);
        cudaEventCreateWithFlags(&eF2h,  cudaEventDisableTiming);
        cudaEventCreateWithFlags(&eCs1,  cudaEventDisableTiming);
        cudaEventCreateWithFlags(&eRank, cudaEventDisableTiming);
    }
    cudaStream_t m = 0;   // capture/legacy stream the harness drives

    // fork side streams off the main stream
    cudaEventRecord(eFork, m);
    cudaStreamWaitEvent(sA, eFork, 0);

    // sideA: weight conversions (independent of x path)
    {
        int na4 = 2*DD*DD/4, nb4 = FF_*DD/4, nc4 = DD*FF_/4;
        f2h3_kernel<<<(na4+nb4+nc4 + 255)/256, 256, 0, sA>>>(
            in_w + (size_t)DD*DD, wkv16, na4, w1, w1h, nb4, w2, w2h, nc4);
        cudaEventRecord(eF2h, sA);
    }

    // main: layernorm1 + colsum stage 1
    lnw_kernel<<<NROWS/8, 256, 0, m>>>(x, ln1g, ln1b, xn, xn16);
    colsum1_kernel<<<dim3(DD/128, BB, 16), 128, 0, m>>>(xn, csp);
    cudaEventRecord(eCs1, m);

    // sideB: ranking chain (needs xn + csp; independent of KV GEMM)
    cudaStreamWaitEvent(sB, eCs1, 0);
    colsum2_kernel<<<(BB*DD + 255)/256, 256, 0, sB>>>(csp, cs);
    sparsw_kernel<<<NROWS/8, 256, 0, sB>>>(xn, cs, sp);
    topk_kernel<<<BB, 256, 0, sB>>>(sp, tidx);
    sproj_kernel<<<dim3(DD/128, 39), 256, 0, sB>>>(xn, tidx, nullptr, nullptr, in_w, in_b, qs);
    cudaEventRecord(eRank, sB);

    // main: KV projection (needs wkv16 from sideA)
    cudaStreamWaitEvent(m, eF2h, 0);
    hgemm<0, __half><<<dim3((2*DD)/128, NROWS/128), 128, HG_SMEM, m>>>(
        xn16, wkv16, in_b + DD, nullptr, kvh, 2*DD, DD);

    // join: attention needs kvh (main) + qs/tidx/cs (sideB)
    cudaStreamWaitEvent(m, eRank, 0);
    ctxflash_kernel<<<dim3(4, HH, BB), 256, 0, m>>>(qs, kvh, ctxp, ml);
    sproj_kernel<<<dim3(DD/128, 39), 256, 0, m>>>(nullptr, nullptr, ctxp, ml, outw, outb, aout);
    // fused residual + layernorm2
    lnfuse_kernel<<<NROWS/8, 256, 0, m>>>(x, cs, aout, tidx, ln2g, ln2b, x2, xn2h);
    // FFN
    hgemm<1, __half><<<dim3(FF_/128, NROWS/128), 128, HG_SMEM, m>>>(
        xn2h, w1h, b1, nullptr, h1h, FF_, DD);
    hgemm<2, float><<<dim3(DD/128, NROWS/128), 128, HG_SMEM, m>>>(
        h1h, w2h, b2, x2, out, DD, FF_);
    // ratio tail
    if (out_size > NROWS*DD) {
        int tail = out_size - NROWS*DD;
        ratio_kernel<<<(tail + 255)/256, 256, 0, m>>>(out, out_size);
    }
}

// round 12
// speedup vs baseline: 1.5913x; 1.0074x over previous
#include <cuda_runtime.h>
#include <cuda_fp16.h>
#include <math.h>
#include <stdint.h>

#define BB 8
#define SS 2048
#define DD 512
#define FF_ 2048
#define HH 8
#define DH 64
#define TOPQ 39
#define QPW 5
#define NROWS (BB*SS)   /* 16384 */

// ---------------- static scratch ----------------
__device__ float g_xn  [NROWS*DD];
__device__ float g_x2  [NROWS*DD];
__device__ float g_cs  [BB*DD];
__device__ float g_cspart[16*BB*DD];
__device__ float g_sp  [BB*SS];
__device__ int   g_tidx[BB*TOPQ];
__device__ float g_qs  [BB*TOPQ*DD];
__device__ float g_ctxp[4*BB*TOPQ*DD];
__device__ float2 g_ml [4*BB*HH*TOPQ];
__device__ float g_aout[BB*TOPQ*DD];
// fp16 operands
__device__ __half g_kvh  [NROWS*2*DD];
__device__ __half g_xn16 [NROWS*DD];
__device__ __half g_xn2h [NROWS*DD];
__device__ __half g_h1h  [(size_t)NROWS*FF_];
__device__ __half g_wkv16[2*DD*DD];
__device__ __half g_w1h  [FF_*DD];
__device__ __half g_w2h  [DD*FF_];

// ---------------- helpers ----------------
__device__ __forceinline__ uint32_t s2u(const void* p) {
    uint32_t a;
    asm("{ .reg .u64 t; cvta.to.shared.u64 t, %1; cvt.u32.u64 %0, t; }" : "=r"(a) : "l"(p));
    return a;
}
__device__ __forceinline__ void mma_f16(float* d, const uint32_t* a, const uint32_t* b) {
    asm volatile("mma.sync.aligned.m16n8k16.row.col.f32.f16.f16.f32 "
        "{%0,%1,%2,%3}, {%4,%5,%6,%7}, {%8,%9}, {%0,%1,%2,%3};"
        : "+f"(d[0]), "+f"(d[1]), "+f"(d[2]), "+f"(d[3])
        : "r"(a[0]), "r"(a[1]), "r"(a[2]), "r"(a[3]), "r"(b[0]), "r"(b[1]));
}
__device__ __forceinline__ void mma_h16(uint32_t* d, const uint32_t* a, const uint32_t* b) {
    asm volatile("mma.sync.aligned.m16n8k16.row.col.f16.f16.f16.f16 "
        "{%0,%1}, {%2,%3,%4,%5}, {%6,%7}, {%0,%1};"
        : "+r"(d[0]), "+r"(d[1])
        : "r"(a[0]), "r"(a[1]), "r"(a[2]), "r"(a[3]), "r"(b[0]), "r"(b[1]));
}
__device__ __forceinline__ void ldsm4(uint32_t* r, uint32_t addr) {
    asm volatile("ldmatrix.sync.aligned.m8n8.x4.shared.b16 {%0,%1,%2,%3}, [%4];"
        : "=r"(r[0]), "=r"(r[1]), "=r"(r[2]), "=r"(r[3]) : "r"(addr));
}
__device__ __forceinline__ void cpa16(uint32_t dst, const void* src) {
    asm volatile("cp.async.cg.shared.global [%0], [%1], 16;" :: "r"(dst), "l"(src));
}
__device__ __forceinline__ void cpcommit() {
    asm volatile("cp.async.commit_group;" ::: "memory");
}
template<int N> __device__ __forceinline__ void cpwait() {
    asm volatile("cp.async.wait_group %0;" :: "n"(N) : "memory");
}
__device__ __forceinline__ float gelu_f(float x) {
    return 0.5f * x * (1.0f + erff(x * 0.7071067811865476f));
}

// ====================================================================
// fp16 GEMM: CTA 128x128, 4 warps (2x2), warp tile 64x64, 4-stage cp.async.
// HACC: fp16 accumulators (KV projection only — output rounded to fp16 anyway).
// ====================================================================
#define HG_SMEM (4*16384)

template<int EPI, typename OutT, bool HACC>   // EPI: 0=none, 1=gelu, 2=+res
__global__ __launch_bounds__(128, 2) void hgemm(
    const __half* __restrict__ A, const __half* __restrict__ W,
    const float* __restrict__ bias, const float* __restrict__ res,
    OutT* __restrict__ C, int N, int K)
{
    extern __shared__ __align__(16) char smh[];
    const int tid  = threadIdx.x;
    const int lane = tid & 31;
    const int wid  = tid >> 5;
    const int wm   = wid >> 1;
    const int wn   = wid & 1;
    const int bm = blockIdx.y * 128;
    const int bn = blockIdx.x * 128;
    const uint32_t sb = s2u(smh);

    const __half* Ab = A + (size_t)bm * K;
    const __half* Wb = W + (size_t)bn * K;

    const int crow0 = tid >> 2;
    const int cunit = tid & 3;

    auto ISSUE = [&](int buf, int kbase) {
        uint32_t base = sb + buf * 16384;
        #pragma unroll
        for (int i = 0; i < 4; i++) {
            int row = crow0 + i * 32;
            uint32_t off = row*64 + ((cunit ^ (row&3))*16);
            cpa16(base + off,        Ab + (size_t)row*K + kbase + cunit*8);
            cpa16(base + 8192 + off, Wb + (size_t)row*K + kbase + cunit*8);
        }
        cpcommit();
    };

    float    acc[HACC ? 1 : 4][8][4];
    uint32_t hac[HACC ? 4 : 1][8][2];
    #pragma unroll
    for (int a = 0; a < (HACC ? 1 : 4); a++)
        #pragma unroll
        for (int b = 0; b < 8; b++)
            #pragma unroll
            for (int c = 0; c < 4; c++) acc[a][b][c] = 0.f;
    #pragma unroll
    for (int a = 0; a < (HACC ? 4 : 1); a++)
        #pragma unroll
        for (int b = 0; b < 8; b++) { hac[a][b][0] = 0u; hac[a][b][1] = 0u; }

    const int nk = K >> 5;
    const int lm = lane >> 3;
    const int lr = lane & 7;

    ISSUE(0, 0);
    ISSUE(1, 32);
    ISSUE(2, 64);

    for (int kt = 0; kt < nk; kt++) {
        cpwait<2>();
        __syncthreads();
        if (kt + 3 < nk) ISSUE((kt + 3) & 3, (kt + 3) << 5);
        else             cpcommit();

        int buf = kt & 3;
        uint32_t Abase = sb + buf*16384;
        uint32_t Bbase = Abase + 8192;
        #pragma unroll
        for (int s = 0; s < 2; s++) {
            uint32_t af[4][4];
            #pragma unroll
            for (int mt = 0; mt < 4; mt++) {
                int row = wm*64 + mt*16 + (lm&1)*8 + lr;
                int unit = s*2 + (lm>>1);
                ldsm4(af[mt], Abase + row*64 + ((unit ^ (row&3))*16));
            }
            uint32_t bf[8][2];
            #pragma unroll
            for (int np = 0; np < 4; np++) {
                int nr = wn*64 + (np*2 + (lm>>1))*8 + lr;
                int unit = s*2 + (lm&1);
                uint32_t r[4];
                ldsm4(r, Bbase + nr*64 + ((unit ^ (nr&3))*16));
                bf[np*2][0] = r[0]; bf[np*2][1] = r[1];
                bf[np*2+1][0] = r[2]; bf[np*2+1][1] = r[3];
            }
            #pragma unroll
            for (int mt = 0; mt < 4; mt++)
                #pragma unroll
                for (int nt = 0; nt < 8; nt++) {
                    if constexpr (HACC) mma_h16(hac[mt][nt], af[mt], bf[nt]);
                    else                mma_f16(acc[mt][nt], af[mt], bf[nt]);
                }
        }
    }

    const int g = lane >> 2, t = lane & 3;
    #pragma unroll
    for (int mt = 0; mt < 4; mt++) {
        int row0 = bm + wm*64 + mt*16 + g;
        #pragma unroll
        for (int nt = 0; nt < 8; nt++) {
            int col = bn + wn*64 + nt*8 + 2*t;
            float b0 = bias[col], b1 = bias[col+1];
            float v0, v1, v2, v3;
            if constexpr (HACC) {
                float2 f0 = __half22float2(*(__half2*)&hac[mt][nt][0]);
                float2 f1 = __half22float2(*(__half2*)&hac[mt][nt][1]);
                v0 = f0.x + b0; v1 = f0.y + b1;
                v2 = f1.x + b0; v3 = f1.y + b1;
            } else {
                v0 = acc[mt][nt][0] + b0; v1 = acc[mt][nt][1] + b1;
                v2 = acc[mt][nt][2] + b0; v3 = acc[mt][nt][3] + b1;
            }
            if (EPI == 1) {
                v0 = gelu_f(v0); v1 = gelu_f(v1); v2 = gelu_f(v2); v3 = gelu_f(v3);
            }
            if (EPI == 2) {
                const float* r0 = res + (size_t)row0*N + col;
                const float* r1 = res + (size_t)(row0+8)*N + col;
                v0 += r0[0]; v1 += r0[1]; v2 += r1[0]; v3 += r1[1];
            }
            if constexpr (sizeof(OutT) == 2) {
                *(__half2*)&C[(size_t)row0*N + col]     = __floats2half2_rn(v0, v1);
                *(__half2*)&C[(size_t)(row0+8)*N + col] = __floats2half2_rn(v2, v3);
            } else {
                *(float2*)&C[(size_t)row0*N + col]     = make_float2(v0, v1);
                *(float2*)&C[(size_t)(row0+8)*N + col] = make_float2(v2, v3);
            }
        }
    }
}

// ---------------- fp32 -> fp16 bulk convert (3 regions) ----------------
__global__ void f2h3_kernel(const float* __restrict__ a, __half* __restrict__ da, int na4,
                            const float* __restrict__ b, __half* __restrict__ db, int nb4,
                            const float* __restrict__ c, __half* __restrict__ dc, int nc4)
{
    int i = blockIdx.x * 256 + threadIdx.x;
    const float* s; __half* d; int j = i;
    if (j < na4) { s = a; d = da; }
    else {
        j -= na4;
        if (j < nb4) { s = b; d = db; }
        else { j -= nb4; if (j >= nc4) return; s = c; d = dc; }
    }
    float4 v = ((const float4*)s)[j];
    ((__half2*)d)[2*j]   = __floats2half2_rn(v.x, v.y);
    ((__half2*)d)[2*j+1] = __floats2half2_rn(v.z, v.w);
}

// ---------------- layernorm1: warp per row ----------------
__global__ __launch_bounds__(256) void lnw_kernel(const float* __restrict__ x,
        const float* __restrict__ g, const float* __restrict__ bb,
        float* __restrict__ out, __half* __restrict__ out16)
{
    int row  = blockIdx.x * 8 + (threadIdx.x >> 5);
    int lane = threadIdx.x & 31;
    const float4* xr = (const float4*)x + (size_t)row*(DD/4);
    float4 v[4];
    #pragma unroll
    for (int j = 0; j < 4; j++) v[j] = xr[lane + 32*j];
    float s = 0.f;
    #pragma unroll
    for (int j = 0; j < 4; j++) s += v[j].x + v[j].y + v[j].z + v[j].w;
    #pragma unroll
    for (int o = 16; o > 0; o >>= 1) s += __shfl_xor_sync(0xffffffffu, s, o);
    float mean = s * (1.0f/DD);
    float q = 0.f;
    #pragma unroll
    for (int j = 0; j < 4; j++) {
        float a = v[j].x-mean, b = v[j].y-mean, c = v[j].z-mean, d = v[j].w-mean;
        q += a*a + b*b + c*c + d*d;
    }
    #pragma unroll
    for (int o = 16; o > 0; o >>= 1) q += __shfl_xor_sync(0xffffffffu, q, o);
    float inv = rsqrtf(q * (1.0f/DD) + 1e-5f);
    #pragma unroll
    for (int j = 0; j < 4; j++) {
        float4 gg = ((const float4*)g)[lane + 32*j];
        float4 bv = ((const float4*)bb)[lane + 32*j];
        float4 o4 = make_float4(
            (v[j].x-mean)*inv*gg.x + bv.x, (v[j].y-mean)*inv*gg.y + bv.y,
            (v[j].z-mean)*inv*gg.z + bv.z, (v[j].w-mean)*inv*gg.w + bv.w);
        if (out) ((float4*)out)[(size_t)row*(DD/4) + lane + 32*j] = o4;
        if (out16) {
            int base = (int)(lane + 32*j);
            ((__half2*)(out16 + (size_t)row*DD))[2*base]   = __floats2half2_rn(o4.x, o4.y);
            ((__half2*)(out16 + (size_t)row*DD))[2*base+1] = __floats2half2_rn(o4.z, o4.w);
        }
    }
}

// ---------------- fused: residual(base|scatter) + layernorm2 ----------------
__global__ __launch_bounds__(256) void lnfuse_kernel(const float* __restrict__ x,
        const float* __restrict__ cs, const float* __restrict__ aout,
        const int* __restrict__ tidx,
        const float* __restrict__ g, const float* __restrict__ bb,
        float* __restrict__ x2, __half* __restrict__ out16)
{
    int row  = blockIdx.x * 8 + (threadIdx.x >> 5);
    int lane = threadIdx.x & 31;
    int b    = row >> 11;
    int rin  = row & (SS-1);
    __shared__ int stid[TOPQ];
    if (threadIdx.x < TOPQ) stid[threadIdx.x] = tidx[b*TOPQ + threadIdx.x];
    __syncthreads();
    int slot = -1;
    #pragma unroll
    for (int j = 0; j < TOPQ; j++) if (stid[j] == rin) slot = j;

    const float4* xr = (const float4*)x + (size_t)row*(DD/4);
    float4 v[4];
    #pragma unroll
    for (int j = 0; j < 4; j++) v[j] = xr[lane + 32*j];
    if (slot >= 0) {
        const float4* ar = (const float4*)aout + (size_t)(b*TOPQ + slot)*(DD/4);
        #pragma unroll
        for (int j = 0; j < 4; j++) {
            float4 a = ar[lane + 32*j];
            v[j].x += a.x; v[j].y += a.y; v[j].z += a.z; v[j].w += a.w;
        }
    } else {
        const float4* cr = (const float4*)cs + b*(DD/4);
        const float r = 1.0f / SS;
        #pragma unroll
        for (int j = 0; j < 4; j++) {
            float4 c = cr[lane + 32*j];
            v[j].x += c.x*r; v[j].y += c.y*r; v[j].z += c.z*r; v[j].w += c.w*r;
        }
    }
    #pragma unroll
    for (int j = 0; j < 4; j++)
        ((float4*)x2)[(size_t)row*(DD/4) + lane + 32*j] = v[j];
    float s = 0.f;
    #pragma unroll
    for (int j = 0; j < 4; j++) s += v[j].x + v[j].y + v[j].z + v[j].w;
    #pragma unroll
    for (int o = 16; o > 0; o >>= 1) s += __shfl_xor_sync(0xffffffffu, s, o);
    float mean = s * (1.0f/DD);
    float q = 0.f;
    #pragma unroll
    for (int j = 0; j < 4; j++) {
        float a = v[j].x-mean, bq = v[j].y-mean, c = v[j].z-mean, d = v[j].w-mean;
        q += a*a + bq*bq + c*c + d*d;
    }
    #pragma unroll
    for (int o = 16; o > 0; o >>= 1) q += __shfl_xor_sync(0xffffffffu, q, o);
    float inv = rsqrtf(q * (1.0f/DD) + 1e-5f);
    #pragma unroll
    for (int j = 0; j < 4; j++) {
        float4 gg = ((const float4*)g)[lane + 32*j];
        float4 bv = ((const float4*)bb)[lane + 32*j];
        float4 o4 = make_float4(
            (v[j].x-mean)*inv*gg.x + bv.x, (v[j].y-mean)*inv*gg.y + bv.y,
            (v[j].z-mean)*inv*gg.z + bv.z, (v[j].w-mean)*inv*gg.w + bv.w);
        int base = (int)(lane + 32*j);
        ((__half2*)(out16 + (size_t)row*DD))[2*base]   = __floats2half2_rn(o4.x, o4.y);
        ((__half2*)(out16 + (size_t)row*DD))[2*base+1] = __floats2half2_rn(o4.z, o4.w);
    }
}

// ---------------- column sums ----------------
__global__ void colsum1_kernel(const float* __restrict__ xn, float* __restrict__ part)
{
    int b = blockIdx.y;
    int c = blockIdx.z;
    int d = blockIdx.x * 128 + threadIdx.x;
    const float* p = xn + (size_t)b*SS*DD + (size_t)c*128*DD + d;
    float s = 0.f;
    #pragma unroll 8
    for (int k = 0; k < 128; k++) s += p[(size_t)k*DD];
    part[((size_t)c*BB + b)*DD + d] = s;
}
__global__ void colsum2_kernel(const float* __restrict__ part, float* __restrict__ cs)
{
    int i = blockIdx.x * 256 + threadIdx.x;
    if (i < BB*DD) {
        float s = 0.f;
        #pragma unroll
        for (int c = 0; c < 16; c++) s += part[(size_t)c*BB*DD + i];
        cs[i] = s;
    }
}

// ---------------- sparsity ----------------
__global__ __launch_bounds__(256) void sparsw_kernel(const float* __restrict__ xn,
        const float* __restrict__ cs, float* __restrict__ sp)
{
    int row  = blockIdx.x * 8 + (threadIdx.x >> 5);
    int lane = threadIdx.x & 31;
    int b = row >> 11;
    const float4* xr = (const float4*)xn + (size_t)row*(DD/4);
    const float4* cr = (const float4*)cs + b*(DD/4);
    float dp = 0.f, de = 0.f, mp = 0.f, me = 0.f;
    #pragma unroll
    for (int j = 0; j < 4; j++) {
        float4 v = xr[lane + 32*j];
        float4 c = cr[lane + 32*j];
        float vv[4] = {v.x, v.y, v.z, v.w};
        float cc[4] = {c.x, c.y, c.z, c.w};
        #pragma unroll
        for (int e = 0; e < 4; e++) {
            float p = vv[e]*vv[e];
            de += fmaf(vv[e], vv[e], -p);
            dp += p;
            float q = vv[e]*cc[e];
            me += fmaf(vv[e], cc[e], -q);
            mp += q;
        }
    }
    double dd = (double)dp + (double)de;
    double dm = (double)mp + (double)me;
    #pragma unroll
    for (int o = 16; o > 0; o >>= 1) {
        dd += __shfl_xor_sync(0xffffffffu, dd, o);
        dm += __shfl_xor_sync(0xffffffffu, dm, o);
    }
    if (lane == 0)
        sp[row] = (float)((dd - dm * (1.0/SS)) * 0.04419417382415922);
}

// ---------------- top-39 ----------------
__global__ __launch_bounds__(256) void topk_kernel(const float* __restrict__ sp,
        int* __restrict__ tidx)
{
    int b = blockIdx.x;
    int t = threadIdx.x;
    __shared__ float sv[SS];
    __shared__ float rbv[8];
    __shared__ int   rbi[8];
    for (int i = t; i < SS; i += 256) sv[i] = sp[b*SS + i];
    __syncthreads();
    for (int sel = 0; sel < TOPQ; ++sel) {
        float bv = -3.0e38f; int bi = 0;
        for (int i = t; i < SS; i += 256) {
            float v = sv[i];
            if (v > bv || (v == bv && i < bi)) { bv = v; bi = i; }
        }
        #pragma unroll
        for (int o = 16; o > 0; o >>= 1) {
            float ov = __shfl_down_sync(0xffffffffu, bv, o);
            int   oi = __shfl_down_sync(0xffffffffu, bi, o);
            if (ov > bv || (ov == bv && oi < bi)) { bv = ov; bi = oi; }
        }
        if ((t & 31) == 0) { rbv[t >> 5] = bv; rbi[t >> 5] = bi; }
        __syncthreads();
        if (t == 0) {
            float fv = rbv[0]; int fi = rbi[0];
            #pragma unroll
            for (int w = 1; w < 8; w++)
                if (rbv[w] > fv || (rbv[w] == fv && rbi[w] < fi)) { fv = rbv[w]; fi = rbi[w]; }
            tidx[b*TOPQ + sel] = fi;
            sv[fi] = -3.4e38f;
        }
        __syncthreads();
    }
}

// ---------------- flash attention ----------------
__global__ __launch_bounds__(256) void ctxflash_kernel(
    const float* __restrict__ qs, const __half* __restrict__ kvh,
    float* __restrict__ part, float2* __restrict__ ml)
{
    int g = blockIdx.x, h = blockIdx.y, b = blockIdx.z;
    int tid = threadIdx.x, w = tid >> 5, lane = tid & 31;
    __shared__ __half Kt[64][66];
    __shared__ __half Vs[64][64];
    __shared__ float  Qt[64][40];
    __shared__ float  Pw[8][QPW][64];

    for (int i = tid; i < TOPQ*DH; i += 256) {
        int q = i >> 6, d = i & 63;
        Qt[d][q] = qs[((size_t)(b*TOPQ + q))*DD + h*DH + d];
    }
    float2 acc[QPW];
    float m_run[QPW], l_run[QPW];
    #pragma unroll
    for (int iq = 0; iq < QPW; iq++) {
        acc[iq] = make_float2(0.f, 0.f); m_run[iq] = -3.0e38f; l_run[iq] = 0.f;
    }
    __syncthreads();

    for (int t = 0; t < 8; t++) {
        int k0 = g*512 + t*64;
        for (int i = tid; i < 64*32; i += 256) {
            int k = i >> 5, dp = i & 31;
            const __half2* src = (const __half2*)(kvh + ((size_t)(b*SS + k0 + k))*(2*DD) + h*DH) + dp;
            __half2 kk = src[0];
            Kt[2*dp][k]   = __low2half(kk);
            Kt[2*dp+1][k] = __high2half(kk);
            *(__half2*)&Vs[k][2*dp] = src[DD/2];
        }
        __syncthreads();
        #pragma unroll
        for (int iq = 0; iq < QPW; iq++) {
            int q = w + 8*iq;
            if (q < TOPQ) {
                float s0 = 0.f, s1 = 0.f;
                #pragma unroll 8
                for (int d = 0; d < DH; d++) {
                    float qv = Qt[d][q];
                    float2 kk = __half22float2(*(const __half2*)&Kt[d][2*lane]);
                    s0 = fmaf(qv, kk.x, s0);
                    s1 = fmaf(qv, kk.y, s1);
                }
                s0 *= 0.125f; s1 *= 0.125f;
                float mt = fmaxf(s0, s1);
                #pragma unroll
                for (int o = 16; o > 0; o >>= 1)
                    mt = fmaxf(mt, __shfl_xor_sync(0xffffffffu, mt, o));
                float mnew = fmaxf(m_run[iq], mt);
                float p0 = __expf(s0 - mnew), p1 = __expf(s1 - mnew);
                float ps = p0 + p1;
                #pragma unroll
                for (int o = 16; o > 0; o >>= 1)
                    ps += __shfl_xor_sync(0xffffffffu, ps, o);
                float scale = __expf(m_run[iq] - mnew);
                l_run[iq] = l_run[iq]*scale + ps;
                m_run[iq] = mnew;
                Pw[w][iq][2*lane]   = p0;
                Pw[w][iq][2*lane+1] = p1;
                acc[iq].x *= scale; acc[iq].y *= scale;
                __syncwarp();
                #pragma unroll 8
                for (int k = 0; k < 64; k++) {
                    float pv = Pw[w][iq][k];
                    float2 vv = __half22float2(*(const __half2*)&Vs[k][2*lane]);
                    acc[iq].x = fmaf(pv, vv.x, acc[iq].x);
                    acc[iq].y = fmaf(pv, vv.y, acc[iq].y);
                }
            }
        }
        __syncthreads();
    }
    #pragma unroll
    for (int iq = 0; iq < QPW; iq++) {
        int q = w + 8*iq;
        if (q < TOPQ) {
            float* dst = part + (size_t)g*(BB*TOPQ*DD) + ((size_t)(b*TOPQ + q))*DD + h*DH + 2*lane;
            *(float2*)dst = acc[iq];
            if (lane == 0)
                ml[((size_t)(g*BB + b)*HH + h)*TOPQ + q] = make_float2(m_run[iq], l_run[iq]);
        }
    }
}

// ---------------- small projection: 8 rows x 128 cols per block -------------
__global__ __launch_bounds__(256) void sproj_kernel(const float* __restrict__ src,
        const int* __restrict__ gidx, const float* __restrict__ part,
        const float2* __restrict__ ml,
        const float* __restrict__ W, const float* __restrict__ bias,
        float* __restrict__ out)
{
    const int r0 = blockIdx.y * 8;
    const int tid = threadIdx.x;
    __shared__ float xr[8][DD];
    __shared__ float wt[8][HH][4];
    if (part) {
        if (tid < 64) {
            int row = tid >> 3, h = tid & 7;
            int r = r0 + row;
            int b = r / TOPQ, q = r % TOPQ;
            float m[4], l[4];
            #pragma unroll
            for (int g = 0; g < 4; g++) {
                float2 v = ml[((size_t)(g*BB + b)*HH + h)*TOPQ + q];
                m[g] = v.x; l[g] = v.y;
            }
            float M = fmaxf(fmaxf(m[0], m[1]), fmaxf(m[2], m[3]));
            float e[4], L = 0.f;
            #pragma unroll
            for (int g = 0; g < 4; g++) { e[g] = __expf(m[g] - M); L += l[g]*e[g]; }
            float invL = 1.0f / L;
            #pragma unroll
            for (int g = 0; g < 4; g++) wt[row][h][g] = e[g]*invL;
        }
        __syncthreads();
        const int N4 = BB*TOPQ*DD/4;
        const float4* p = (const float4*)part;
        for (int i = tid; i < 8*(DD/4); i += 256) {
            int row = i >> 7, c4 = i & 127;
            int h = c4 >> 4;
            size_t idx = (size_t)(r0 + row)*(DD/4) + c4;
            float4 a = p[idx], b4 = p[idx+N4], c = p[idx+2*N4], d = p[idx+3*N4];
            float w0 = wt[row][h][0], w1 = wt[row][h][1],
                  w2 = wt[row][h][2], w3 = wt[row][h][3];
            ((float4*)xr[row])[c4] = make_float4(
                a.x*w0 + b4.x*w1 + c.x*w2 + d.x*w3,
                a.y*w0 + b4.y*w1 + c.y*w2 + d.y*w3,
                a.z*w0 + b4.z*w1 + c.z*w2 + d.z*w3,
                a.w*w0 + b4.w*w1 + c.w*w2 + d.w*w3);
        }
    } else {
        for (int i = tid; i < 8*(DD/4); i += 256) {
            int row = i >> 7, c4 = i & 127;
            int r = r0 + row;
            int b = r / TOPQ;
            const float* srow = src + ((size_t)b*SS + gidx[r]) * DD;
            ((float4*)xr[row])[c4] = ((const float4*)srow)[c4];
        }
    }
    __syncthreads();
    const int jj = blockIdx.x * 128 + (tid & 127);
    const int rh = (tid >> 7) * 4;
    const float4* w4 = (const float4*)(W + (size_t)jj*DD);
    float a0 = 0.f, a1 = 0.f, a2 = 0.f, a3 = 0.f;
    #pragma unroll 4
    for (int k = 0; k < DD/4; k++) {
        float4 w = w4[k];
        float4 x0 = ((float4*)xr[rh+0])[k];
        float4 x1 = ((float4*)xr[rh+1])[k];
        float4 x2 = ((float4*)xr[rh+2])[k];
        float4 x3 = ((float4*)xr[rh+3])[k];
        a0 = fmaf(w.x, x0.x, fmaf(w.y, x0.y, fmaf(w.z, x0.z, fmaf(w.w, x0.w, a0))));
        a1 = fmaf(w.x, x1.x, fmaf(w.y, x1.y, fmaf(w.z, x1.z, fmaf(w.w, x1.w, a1))));
        a2 = fmaf(w.x, x2.x, fmaf(w.y, x2.y, fmaf(w.z, x2.z, fmaf(w.w, x2.w, a2))));
        a3 = fmaf(w.x, x3.x, fmaf(w.y, x3.y, fmaf(w.z, x3.z, fmaf(w.w, x3.w, a3))));
    }
    float bv = bias[jj];
    out[(size_t)(r0 + rh + 0)*DD + jj] = a0 + bv;
    out[(size_t)(r0 + rh + 1)*DD + jj] = a1 + bv;
    out[(size_t)(r0 + rh + 2)*DD + jj] = a2 + bv;
    out[(size_t)(r0 + rh + 3)*DD + jj] = a3 + bv;
}

// ---------------- ratio tail ----------------
__global__ void ratio_kernel(float* out, int out_size)
{
    int i = NROWS*DD + blockIdx.x*blockDim.x + threadIdx.x;
    if (i < out_size) out[i] = (float)TOPQ / (float)SS;
}

// ---------------- launch (multi-stream fork/join) ----------------
extern "C" void kernel_launch(void* const* d_in, const int* in_sizes, int n_in,
                              void* d_out, int out_size)
{
    const float* x    = (const float*)d_in[0];
    const float* ln1g = (const float*)d_in[1];
    const float* ln1b = (const float*)d_in[2];
    const float* in_w = (const float*)d_in[3];
    const float* in_b = (const float*)d_in[4];
    const float* outw = (const float*)d_in[5];
    const float* outb = (const float*)d_in[6];
    const float* ln2g = (const float*)d_in[7];
    const float* ln2b = (const float*)d_in[8];
    const float* w1   = (const float*)d_in[9];
    const float* b1   = (const float*)d_in[10];
    const float* w2   = (const float*)d_in[11];
    const float* b2   = (const float*)d_in[12];
    float* out = (float*)d_out;

    float *xn, *x2, *cs, *csp, *sp, *qs, *ctxp, *aout;
    float2 *ml;
    __half *kvh, *xn16, *xn2h, *h1h, *wkv16, *w1h, *w2h;
    int *tidx;
    cudaGetSymbolAddress((void**)&xn,    g_xn);
    cudaGetSymbolAddress((void**)&x2,    g_x2);
    cudaGetSymbolAddress((void**)&cs,    g_cs);
    cudaGetSymbolAddress((void**)&csp,   g_cspart);
    cudaGetSymbolAddress((void**)&sp,    g_sp);
    cudaGetSymbolAddress((void**)&qs,    g_qs);
    cudaGetSymbolAddress((void**)&ctxp,  g_ctxp);
    cudaGetSymbolAddress((void**)&ml,    g_ml);
    cudaGetSymbolAddress((void**)&aout,  g_aout);
    cudaGetSymbolAddress((void**)&tidx,  g_tidx);
    cudaGetSymbolAddress((void**)&kvh,   g_kvh);
    cudaGetSymbolAddress((void**)&xn16,  g_xn16);
    cudaGetSymbolAddress((void**)&xn2h,  g_xn2h);
    cudaGetSymbolAddress((void**)&h1h,   g_h1h);
    cudaGetSymbolAddress((void**)&wkv16, g_wkv16);
    cudaGetSymbolAddress((void**)&w1h,   g_w1h);
    cudaGetSymbolAddress((void**)&w2h,   g_w2h);

    cudaFuncSetAttribute((const void*)hgemm<0, __half, true>,  cudaFuncAttributeMaxDynamicSharedMemorySize, HG_SMEM);
    cudaFuncSetAttribute((const void*)hgemm<1, __half, false>, cudaFuncAttributeMaxDynamicSharedMemorySize, HG_SMEM);
    cudaFuncSetAttribute((const void*)hgemm<2, float,  false>, cudaFuncAttributeMaxDynamicSharedMemorySize, HG_SMEM);

    static cudaStream_t sA = nullptr, sB = nullptr;
    static cudaEvent_t eFork = nullptr, eF2h = nullptr, eCs1 = nullptr, eRank = nullptr;
    if (!sA) {
        cudaStreamCreateWithFlags(&sA, cudaStreamNonBlocking);
        cudaStreamCreateWithFlags(&sB, cudaStreamNonBlocking);
        cudaEventCreateWithFlags(&eFork, cudaEventDisableTiming);
        cudaEventCreateWithFlags(&eF2h,  cudaEventDisableTiming);
        cudaEventCreateWithFlags(&eCs1,  cudaEventDisableTiming);
        cudaEventCreateWithFlags(&eRank, cudaEventDisableTiming);
    }
    cudaStream_t m = 0;

    cudaEventRecord(eFork, m);
    cudaStreamWaitEvent(sA, eFork, 0);

    // sideA: weight conversions + ratio tail (both off critical path)
    {
        int na4 = 2*DD*DD/4, nb4 = FF_*DD/4, nc4 = DD*FF_/4;
        f2h3_kernel<<<(na4+nb4+nc4 + 255)/256, 256, 0, sA>>>(
            in_w + (size_t)DD*DD, wkv16, na4, w1, w1h, nb4, w2, w2h, nc4);
        if (out_size > NROWS*DD) {
            int tail = out_size - NROWS*DD;
            ratio_kernel<<<(tail + 255)/256, 256, 0, sA>>>(out, out_size);
        }
        cudaEventRecord(eF2h, sA);
    }

    // main: layernorm1 + colsum stage 1
    lnw_kernel<<<NROWS/8, 256, 0, m>>>(x, ln1g, ln1b, xn, xn16);
    colsum1_kernel<<<dim3(DD/128, BB, 16), 128, 0, m>>>(xn, csp);
    cudaEventRecord(eCs1, m);

    // sideB: ranking chain
    cudaStreamWaitEvent(sB, eCs1, 0);
    colsum2_kernel<<<(BB*DD + 255)/256, 256, 0, sB>>>(csp, cs);
    sparsw_kernel<<<NROWS/8, 256, 0, sB>>>(xn, cs, sp);
    topk_kernel<<<BB, 256, 0, sB>>>(sp, tidx);
    sproj_kernel<<<dim3(DD/128, 39), 256, 0, sB>>>(xn, tidx, nullptr, nullptr, in_w, in_b, qs);
    cudaEventRecord(eRank, sB);

    // main: KV projection (fp16 accumulators)
    cudaStreamWaitEvent(m, eF2h, 0);
    hgemm<0, __half, true><<<dim3((2*DD)/128, NROWS/128), 128, HG_SMEM, m>>>(
        xn16, wkv16, in_b + DD, nullptr, kvh, 2*DD, DD);

    // join: attention
    cudaStreamWaitEvent(m, eRank, 0);
    ctxflash_kernel<<<dim3(4, HH, BB), 256, 0, m>>>(qs, kvh, ctxp, ml);
    sproj_kernel<<<dim3(DD/128, 39), 256, 0, m>>>(nullptr, nullptr, ctxp, ml, outw, outb, aout);
    lnfuse_kernel<<<NROWS/8, 256, 0, m>>>(x, cs, aout, tidx, ln2g, ln2b, x2, xn2h);
    // FFN (fp32 accumulators)
    hgemm<1, __half, false><<<dim3(FF_/128, NROWS/128), 128, HG_SMEM, m>>>(
        xn2h, w1h, b1, nullptr, h1h, FF_, DD);
    hgemm<2, float, false><<<dim3(DD/128, NROWS/128), 128, HG_SMEM, m>>>(
        h1h, w2h, b2, x2, out, DD, FF_);
}

// round 13
// speedup vs baseline: 1.6031x; 1.0074x over previous
#include <cuda_runtime.h>
#include <cuda_fp16.h>
#include <math.h>
#include <stdint.h>

#define BB 8
#define SS 2048
#define DD 512
#define FF_ 2048
#define HH 8
#define DH 64
#define TOPQ 39
#define QPW 5
#define NROWS (BB*SS)   /* 16384 */
#define NBLK (NROWS/8)  /* 2048 ln blocks, 256 per batch */

// ---------------- static scratch ----------------
__device__ float g_xn  [NROWS*DD];
__device__ float g_x2  [NROWS*DD];
__device__ float g_cs  [BB*DD];
__device__ float g_csp2[(size_t)NBLK*DD];   // per-ln-block column partials
__device__ float g_sp  [BB*SS];
__device__ int   g_tidx[BB*TOPQ];
__device__ float g_qs  [BB*TOPQ*DD];
__device__ float g_ctxp[4*BB*TOPQ*DD];
__device__ float2 g_ml [4*BB*HH*TOPQ];
__device__ float g_aout[BB*TOPQ*DD];
// fp16 operands
__device__ __half g_kvh  [NROWS*2*DD];
__device__ __half g_xn16 [NROWS*DD];
__device__ __half g_xn2h [NROWS*DD];
__device__ __half g_h1h  [(size_t)NROWS*FF_];
__device__ __half g_wkv16[2*DD*DD];
__device__ __half g_w1h  [FF_*DD];
__device__ __half g_w2h  [DD*FF_];

// ---------------- helpers ----------------
__device__ __forceinline__ uint32_t s2u(const void* p) {
    uint32_t a;
    asm("{ .reg .u64 t; cvta.to.shared.u64 t, %1; cvt.u32.u64 %0, t; }" : "=r"(a) : "l"(p));
    return a;
}
__device__ __forceinline__ void mma_f16(float* d, const uint32_t* a, const uint32_t* b) {
    asm volatile("mma.sync.aligned.m16n8k16.row.col.f32.f16.f16.f32 "
        "{%0,%1,%2,%3}, {%4,%5,%6,%7}, {%8,%9}, {%0,%1,%2,%3};"
        : "+f"(d[0]), "+f"(d[1]), "+f"(d[2]), "+f"(d[3])
        : "r"(a[0]), "r"(a[1]), "r"(a[2]), "r"(a[3]), "r"(b[0]), "r"(b[1]));
}
__device__ __forceinline__ void ldsm4(uint32_t* r, uint32_t addr) {
    asm volatile("ldmatrix.sync.aligned.m8n8.x4.shared.b16 {%0,%1,%2,%3}, [%4];"
        : "=r"(r[0]), "=r"(r[1]), "=r"(r[2]), "=r"(r[3]) : "r"(addr));
}
__device__ __forceinline__ void cpa16(uint32_t dst, const void* src) {
    asm volatile("cp.async.cg.shared.global [%0], [%1], 16;" :: "r"(dst), "l"(src));
}
__device__ __forceinline__ void cpcommit() {
    asm volatile("cp.async.commit_group;" ::: "memory");
}
template<int N> __device__ __forceinline__ void cpwait() {
    asm volatile("cp.async.wait_group %0;" :: "n"(N) : "memory");
}
__device__ __forceinline__ float gelu_f(float x) {
    return 0.5f * x * (1.0f + erff(x * 0.7071067811865476f));
}

// ====================================================================
// fp16 GEMM: CTA 128x128, 4 warps (2x2), warp 64x64, 4-stage cp.async.
// Inner loop: ALL 16 LDSM hoisted ahead of all 64 MMAs (latency cover).
// ====================================================================
#define HG_SMEM (4*16384)

template<int EPI, typename OutT>   // EPI: 0=none, 1=gelu, 2=+res
__global__ __launch_bounds__(128, 2) void hgemm(
    const __half* __restrict__ A, const __half* __restrict__ W,
    const float* __restrict__ bias, const float* __restrict__ res,
    OutT* __restrict__ C, int N, int K)
{
    extern __shared__ __align__(16) char smh[];
    const int tid  = threadIdx.x;
    const int lane = tid & 31;
    const int wid  = tid >> 5;
    const int wm   = wid >> 1;
    const int wn   = wid & 1;
    const int bm = blockIdx.y * 128;
    const int bn = blockIdx.x * 128;
    const uint32_t sb = s2u(smh);

    const __half* Ab = A + (size_t)bm * K;
    const __half* Wb = W + (size_t)bn * K;

    const int crow0 = tid >> 2;
    const int cunit = tid & 3;

    auto ISSUE = [&](int buf, int kbase) {
        uint32_t base = sb + buf * 16384;
        #pragma unroll
        for (int i = 0; i < 4; i++) {
            int row = crow0 + i * 32;
            uint32_t off = row*64 + ((cunit ^ (row&3))*16);
            cpa16(base + off,        Ab + (size_t)row*K + kbase + cunit*8);
            cpa16(base + 8192 + off, Wb + (size_t)row*K + kbase + cunit*8);
        }
        cpcommit();
    };

    float acc[4][8][4];
    #pragma unroll
    for (int a = 0; a < 4; a++)
        #pragma unroll
        for (int b = 0; b < 8; b++)
            #pragma unroll
            for (int c = 0; c < 4; c++) acc[a][b][c] = 0.f;

    const int nk = K >> 5;
    const int lm = lane >> 3;
    const int lr = lane & 7;

    ISSUE(0, 0);
    ISSUE(1, 32);
    ISSUE(2, 64);

    for (int kt = 0; kt < nk; kt++) {
        cpwait<2>();
        __syncthreads();
        if (kt + 3 < nk) ISSUE((kt + 3) & 3, (kt + 3) << 5);
        else             cpcommit();

        int buf = kt & 3;
        uint32_t Abase = sb + buf*16384;
        uint32_t Bbase = Abase + 8192;
        uint32_t af[2][4][4];
        uint32_t bf[2][8][2];
        #pragma unroll
        for (int s = 0; s < 2; s++) {
            #pragma unroll
            for (int mt = 0; mt < 4; mt++) {
                int row = wm*64 + mt*16 + (lm&1)*8 + lr;
                int unit = s*2 + (lm>>1);
                ldsm4(af[s][mt], Abase + row*64 + ((unit ^ (row&3))*16));
            }
            #pragma unroll
            for (int np = 0; np < 4; np++) {
                int nr = wn*64 + (np*2 + (lm>>1))*8 + lr;
                int unit = s*2 + (lm&1);
                uint32_t r[4];
                ldsm4(r, Bbase + nr*64 + ((unit ^ (nr&3))*16));
                bf[s][np*2][0] = r[0]; bf[s][np*2][1] = r[1];
                bf[s][np*2+1][0] = r[2]; bf[s][np*2+1][1] = r[3];
            }
        }
        #pragma unroll
        for (int s = 0; s < 2; s++)
            #pragma unroll
            for (int mt = 0; mt < 4; mt++)
                #pragma unroll
                for (int nt = 0; nt < 8; nt++)
                    mma_f16(acc[mt][nt], af[s][mt], bf[s][nt]);
    }

    const int g = lane >> 2, t = lane & 3;
    #pragma unroll
    for (int mt = 0; mt < 4; mt++) {
        int row0 = bm + wm*64 + mt*16 + g;
        #pragma unroll
        for (int nt = 0; nt < 8; nt++) {
            int col = bn + wn*64 + nt*8 + 2*t;
            float b0 = bias[col], b1 = bias[col+1];
            float v0 = acc[mt][nt][0] + b0;
            float v1 = acc[mt][nt][1] + b1;
            float v2 = acc[mt][nt][2] + b0;
            float v3 = acc[mt][nt][3] + b1;
            if (EPI == 1) {
                v0 = gelu_f(v0); v1 = gelu_f(v1); v2 = gelu_f(v2); v3 = gelu_f(v3);
            }
            if (EPI == 2) {
                const float* r0 = res + (size_t)row0*N + col;
                const float* r1 = res + (size_t)(row0+8)*N + col;
                v0 += r0[0]; v1 += r0[1]; v2 += r1[0]; v3 += r1[1];
            }
            if constexpr (sizeof(OutT) == 2) {
                *(__half2*)&C[(size_t)row0*N + col]     = __floats2half2_rn(v0, v1);
                *(__half2*)&C[(size_t)(row0+8)*N + col] = __floats2half2_rn(v2, v3);
            } else {
                *(float2*)&C[(size_t)row0*N + col]     = make_float2(v0, v1);
                *(float2*)&C[(size_t)(row0+8)*N + col] = make_float2(v2, v3);
            }
        }
    }
}

// ---------------- fp32 -> fp16 bulk convert (3 regions) ----------------
__global__ void f2h3_kernel(const float* __restrict__ a, __half* __restrict__ da, int na4,
                            const float* __restrict__ b, __half* __restrict__ db, int nb4,
                            const float* __restrict__ c, __half* __restrict__ dc, int nc4)
{
    int i = blockIdx.x * 256 + threadIdx.x;
    const float* s; __half* d; int j = i;
    if (j < na4) { s = a; d = da; }
    else {
        j -= na4;
        if (j < nb4) { s = b; d = db; }
        else { j -= nb4; if (j >= nc4) return; s = c; d = dc; }
    }
    float4 v = ((const float4*)s)[j];
    ((__half2*)d)[2*j]   = __floats2half2_rn(v.x, v.y);
    ((__half2*)d)[2*j+1] = __floats2half2_rn(v.z, v.w);
}

// ---------------- layernorm1 + fused per-block column partials ------------
__global__ __launch_bounds__(256) void lnw_kernel(const float* __restrict__ x,
        const float* __restrict__ g, const float* __restrict__ bb,
        float* __restrict__ out, __half* __restrict__ out16,
        float* __restrict__ csp)   // csp != null: write per-block colsum partial
{
    int blk  = blockIdx.x;
    int row  = blk * 8 + (threadIdx.x >> 5);
    int lane = threadIdx.x & 31;
    __shared__ float cbuf[8][DD];
    const float4* xr = (const float4*)x + (size_t)row*(DD/4);
    float4 v[4];
    #pragma unroll
    for (int j = 0; j < 4; j++) v[j] = xr[lane + 32*j];
    float s = 0.f;
    #pragma unroll
    for (int j = 0; j < 4; j++) s += v[j].x + v[j].y + v[j].z + v[j].w;
    #pragma unroll
    for (int o = 16; o > 0; o >>= 1) s += __shfl_xor_sync(0xffffffffu, s, o);
    float mean = s * (1.0f/DD);
    float q = 0.f;
    #pragma unroll
    for (int j = 0; j < 4; j++) {
        float a = v[j].x-mean, b = v[j].y-mean, c = v[j].z-mean, d = v[j].w-mean;
        q += a*a + b*b + c*c + d*d;
    }
    #pragma unroll
    for (int o = 16; o > 0; o >>= 1) q += __shfl_xor_sync(0xffffffffu, q, o);
    float inv = rsqrtf(q * (1.0f/DD) + 1e-5f);
    #pragma unroll
    for (int j = 0; j < 4; j++) {
        float4 gg = ((const float4*)g)[lane + 32*j];
        float4 bv = ((const float4*)bb)[lane + 32*j];
        float4 o4 = make_float4(
            (v[j].x-mean)*inv*gg.x + bv.x, (v[j].y-mean)*inv*gg.y + bv.y,
            (v[j].z-mean)*inv*gg.z + bv.z, (v[j].w-mean)*inv*gg.w + bv.w);
        if (out) ((float4*)out)[(size_t)row*(DD/4) + lane + 32*j] = o4;
        if (out16) {
            int base = (int)(lane + 32*j);
            ((__half2*)(out16 + (size_t)row*DD))[2*base]   = __floats2half2_rn(o4.x, o4.y);
            ((__half2*)(out16 + (size_t)row*DD))[2*base+1] = __floats2half2_rn(o4.z, o4.w);
        }
        if (csp) ((float4*)cbuf[threadIdx.x >> 5])[lane + 32*j] = o4;
    }
    if (csp) {
        __syncthreads();
        // 256 threads, 2 columns each: fixed-order sum over the 8 rows
        #pragma unroll
        for (int cc = 0; cc < 2; cc++) {
            int col = threadIdx.x + cc * 256;
            float acc = cbuf[0][col];
            #pragma unroll
            for (int r2 = 1; r2 < 8; r2++) acc += cbuf[r2][col];
            csp[(size_t)blk*DD + col] = acc;
        }
    }
}

// ---------------- colsum stage 2: 256 fixed-order partials per batch -------
__global__ void colsum2_kernel(const float* __restrict__ csp, float* __restrict__ cs)
{
    int i = blockIdx.x * 256 + threadIdx.x;   // i over BB*DD
    if (i < BB*DD) {
        int b = i / DD, d = i % DD;
        const float* p = csp + (size_t)(b*256)*DD + d;
        float s = 0.f;
        for (int k = 0; k < 256; k++) s += p[(size_t)k*DD];
        cs[i] = s;
    }
}

// ---------------- fused: residual(base|scatter) + layernorm2 ----------------
__global__ __launch_bounds__(256) void lnfuse_kernel(const float* __restrict__ x,
        const float* __restrict__ cs, const float* __restrict__ aout,
        const int* __restrict__ tidx,
        const float* __restrict__ g, const float* __restrict__ bb,
        float* __restrict__ x2, __half* __restrict__ out16)
{
    int row  = blockIdx.x * 8 + (threadIdx.x >> 5);
    int lane = threadIdx.x & 31;
    int b    = row >> 11;
    int rin  = row & (SS-1);
    __shared__ int stid[TOPQ];
    if (threadIdx.x < TOPQ) stid[threadIdx.x] = tidx[b*TOPQ + threadIdx.x];
    __syncthreads();
    int slot = -1;
    #pragma unroll
    for (int j = 0; j < TOPQ; j++) if (stid[j] == rin) slot = j;

    const float4* xr = (const float4*)x + (size_t)row*(DD/4);
    float4 v[4];
    #pragma unroll
    for (int j = 0; j < 4; j++) v[j] = xr[lane + 32*j];
    if (slot >= 0) {
        const float4* ar = (const float4*)aout + (size_t)(b*TOPQ + slot)*(DD/4);
        #pragma unroll
        for (int j = 0; j < 4; j++) {
            float4 a = ar[lane + 32*j];
            v[j].x += a.x; v[j].y += a.y; v[j].z += a.z; v[j].w += a.w;
        }
    } else {
        const float4* cr = (const float4*)cs + b*(DD/4);
        const float r = 1.0f / SS;
        #pragma unroll
        for (int j = 0; j < 4; j++) {
            float4 c = cr[lane + 32*j];
            v[j].x += c.x*r; v[j].y += c.y*r; v[j].z += c.z*r; v[j].w += c.w*r;
        }
    }
    #pragma unroll
    for (int j = 0; j < 4; j++)
        ((float4*)x2)[(size_t)row*(DD/4) + lane + 32*j] = v[j];
    float s = 0.f;
    #pragma unroll
    for (int j = 0; j < 4; j++) s += v[j].x + v[j].y + v[j].z + v[j].w;
    #pragma unroll
    for (int o = 16; o > 0; o >>= 1) s += __shfl_xor_sync(0xffffffffu, s, o);
    float mean = s * (1.0f/DD);
    float q = 0.f;
    #pragma unroll
    for (int j = 0; j < 4; j++) {
        float a = v[j].x-mean, bq = v[j].y-mean, c = v[j].z-mean, d = v[j].w-mean;
        q += a*a + bq*bq + c*c + d*d;
    }
    #pragma unroll
    for (int o = 16; o > 0; o >>= 1) q += __shfl_xor_sync(0xffffffffu, q, o);
    float inv = rsqrtf(q * (1.0f/DD) + 1e-5f);
    #pragma unroll
    for (int j = 0; j < 4; j++) {
        float4 gg = ((const float4*)g)[lane + 32*j];
        float4 bv = ((const float4*)bb)[lane + 32*j];
        float4 o4 = make_float4(
            (v[j].x-mean)*inv*gg.x + bv.x, (v[j].y-mean)*inv*gg.y + bv.y,
            (v[j].z-mean)*inv*gg.z + bv.z, (v[j].w-mean)*inv*gg.w + bv.w);
        int base = (int)(lane + 32*j);
        ((__half2*)(out16 + (size_t)row*DD))[2*base]   = __floats2half2_rn(o4.x, o4.y);
        ((__half2*)(out16 + (size_t)row*DD))[2*base+1] = __floats2half2_rn(o4.z, o4.w);
    }
}

// ---------------- sparsity ----------------
__global__ __launch_bounds__(256) void sparsw_kernel(const float* __restrict__ xn,
        const float* __restrict__ cs, float* __restrict__ sp)
{
    int row  = blockIdx.x * 8 + (threadIdx.x >> 5);
    int lane = threadIdx.x & 31;
    int b = row >> 11;
    const float4* xr = (const float4*)xn + (size_t)row*(DD/4);
    const float4* cr = (const float4*)cs + b*(DD/4);
    float dp = 0.f, de = 0.f, mp = 0.f, me = 0.f;
    #pragma unroll
    for (int j = 0; j < 4; j++) {
        float4 v = xr[lane + 32*j];
        float4 c = cr[lane + 32*j];
        float vv[4] = {v.x, v.y, v.z, v.w};
        float cc[4] = {c.x, c.y, c.z, c.w};
        #pragma unroll
        for (int e = 0; e < 4; e++) {
            float p = vv[e]*vv[e];
            de += fmaf(vv[e], vv[e], -p);
            dp += p;
            float q = vv[e]*cc[e];
            me += fmaf(vv[e], cc[e], -q);
            mp += q;
        }
    }
    double dd = (double)dp + (double)de;
    double dm = (double)mp + (double)me;
    #pragma unroll
    for (int o = 16; o > 0; o >>= 1) {
        dd += __shfl_xor_sync(0xffffffffu, dd, o);
        dm += __shfl_xor_sync(0xffffffffu, dm, o);
    }
    if (lane == 0)
        sp[row] = (float)((dd - dm * (1.0/SS)) * 0.04419417382415922);
}

// ---------------- top-39 ----------------
__global__ __launch_bounds__(256) void topk_kernel(const float* __restrict__ sp,
        int* __restrict__ tidx)
{
    int b = blockIdx.x;
    int t = threadIdx.x;
    __shared__ float sv[SS];
    __shared__ float rbv[8];
    __shared__ int   rbi[8];
    for (int i = t; i < SS; i += 256) sv[i] = sp[b*SS + i];
    __syncthreads();
    for (int sel = 0; sel < TOPQ; ++sel) {
        float bv = -3.0e38f; int bi = 0;
        for (int i = t; i < SS; i += 256) {
            float v = sv[i];
            if (v > bv || (v == bv && i < bi)) { bv = v; bi = i; }
        }
        #pragma unroll
        for (int o = 16; o > 0; o >>= 1) {
            float ov = __shfl_down_sync(0xffffffffu, bv, o);
            int   oi = __shfl_down_sync(0xffffffffu, bi, o);
            if (ov > bv || (ov == bv && oi < bi)) { bv = ov; bi = oi; }
        }
        if ((t & 31) == 0) { rbv[t >> 5] = bv; rbi[t >> 5] = bi; }
        __syncthreads();
        if (t == 0) {
            float fv = rbv[0]; int fi = rbi[0];
            #pragma unroll
            for (int w = 1; w < 8; w++)
                if (rbv[w] > fv || (rbv[w] == fv && rbi[w] < fi)) { fv = rbv[w]; fi = rbi[w]; }
            tidx[b*TOPQ + sel] = fi;
            sv[fi] = -3.4e38f;
        }
        __syncthreads();
    }
}

// ---------------- flash attention ----------------
__global__ __launch_bounds__(256) void ctxflash_kernel(
    const float* __restrict__ qs, const __half* __restrict__ kvh,
    float* __restrict__ part, float2* __restrict__ ml)
{
    int g = blockIdx.x, h = blockIdx.y, b = blockIdx.z;
    int tid = threadIdx.x, w = tid >> 5, lane = tid & 31;
    __shared__ __half Kt[64][66];
    __shared__ __half Vs[64][64];
    __shared__ float  Qt[64][40];
    __shared__ float  Pw[8][QPW][64];

    for (int i = tid; i < TOPQ*DH; i += 256) {
        int q = i >> 6, d = i & 63;
        Qt[d][q] = qs[((size_t)(b*TOPQ + q))*DD + h*DH + d];
    }
    float2 acc[QPW];
    float m_run[QPW], l_run[QPW];
    #pragma unroll
    for (int iq = 0; iq < QPW; iq++) {
        acc[iq] = make_float2(0.f, 0.f); m_run[iq] = -3.0e38f; l_run[iq] = 0.f;
    }
    __syncthreads();

    for (int t = 0; t < 8; t++) {
        int k0 = g*512 + t*64;
        for (int i = tid; i < 64*32; i += 256) {
            int k = i >> 5, dp = i & 31;
            const __half2* src = (const __half2*)(kvh + ((size_t)(b*SS + k0 + k))*(2*DD) + h*DH) + dp;
            __half2 kk = src[0];
            Kt[2*dp][k]   = __low2half(kk);
            Kt[2*dp+1][k] = __high2half(kk);
            *(__half2*)&Vs[k][2*dp] = src[DD/2];
        }
        __syncthreads();
        #pragma unroll
        for (int iq = 0; iq < QPW; iq++) {
            int q = w + 8*iq;
            if (q < TOPQ) {
                float s0 = 0.f, s1 = 0.f;
                #pragma unroll 8
                for (int d = 0; d < DH; d++) {
                    float qv = Qt[d][q];
                    float2 kk = __half22float2(*(const __half2*)&Kt[d][2*lane]);
                    s0 = fmaf(qv, kk.x, s0);
                    s1 = fmaf(qv, kk.y, s1);
                }
                s0 *= 0.125f; s1 *= 0.125f;
                float mt = fmaxf(s0, s1);
                #pragma unroll
                for (int o = 16; o > 0; o >>= 1)
                    mt = fmaxf(mt, __shfl_xor_sync(0xffffffffu, mt, o));
                float mnew = fmaxf(m_run[iq], mt);
                float p0 = __expf(s0 - mnew), p1 = __expf(s1 - mnew);
                float ps = p0 + p1;
                #pragma unroll
                for (int o = 16; o > 0; o >>= 1)
                    ps += __shfl_xor_sync(0xffffffffu, ps, o);
                float scale = __expf(m_run[iq] - mnew);
                l_run[iq] = l_run[iq]*scale + ps;
                m_run[iq] = mnew;
                Pw[w][iq][2*lane]   = p0;
                Pw[w][iq][2*lane+1] = p1;
                acc[iq].x *= scale; acc[iq].y *= scale;
                __syncwarp();
                #pragma unroll 8
                for (int k = 0; k < 64; k++) {
                    float pv = Pw[w][iq][k];
                    float2 vv = __half22float2(*(const __half2*)&Vs[k][2*lane]);
                    acc[iq].x = fmaf(pv, vv.x, acc[iq].x);
                    acc[iq].y = fmaf(pv, vv.y, acc[iq].y);
                }
            }
        }
        __syncthreads();
    }
    #pragma unroll
    for (int iq = 0; iq < QPW; iq++) {
        int q = w + 8*iq;
        if (q < TOPQ) {
            float* dst = part + (size_t)g*(BB*TOPQ*DD) + ((size_t)(b*TOPQ + q))*DD + h*DH + 2*lane;
            *(float2*)dst = acc[iq];
            if (lane == 0)
                ml[((size_t)(g*BB + b)*HH + h)*TOPQ + q] = make_float2(m_run[iq], l_run[iq]);
        }
    }
}

// ---------------- small projection: 8 rows x 128 cols per block -------------
__global__ __launch_bounds__(256) void sproj_kernel(const float* __restrict__ src,
        const int* __restrict__ gidx, const float* __restrict__ part,
        const float2* __restrict__ ml,
        const float* __restrict__ W, const float* __restrict__ bias,
        float* __restrict__ out)
{
    const int r0 = blockIdx.y * 8;
    const int tid = threadIdx.x;
    __shared__ float xr[8][DD];
    __shared__ float wt[8][HH][4];
    if (part) {
        if (tid < 64) {
            int row = tid >> 3, h = tid & 7;
            int r = r0 + row;
            int b = r / TOPQ, q = r % TOPQ;
            float m[4], l[4];
            #pragma unroll
            for (int g = 0; g < 4; g++) {
                float2 v = ml[((size_t)(g*BB + b)*HH + h)*TOPQ + q];
                m[g] = v.x; l[g] = v.y;
            }
            float M = fmaxf(fmaxf(m[0], m[1]), fmaxf(m[2], m[3]));
            float e[4], L = 0.f;
            #pragma unroll
            for (int g = 0; g < 4; g++) { e[g] = __expf(m[g] - M); L += l[g]*e[g]; }
            float invL = 1.0f / L;
            #pragma unroll
            for (int g = 0; g < 4; g++) wt[row][h][g] = e[g]*invL;
        }
        __syncthreads();
        const int N4 = BB*TOPQ*DD/4;
        const float4* p = (const float4*)part;
        for (int i = tid; i < 8*(DD/4); i += 256) {
            int row = i >> 7, c4 = i & 127;
            int h = c4 >> 4;
            size_t idx = (size_t)(r0 + row)*(DD/4) + c4;
            float4 a = p[idx], b4 = p[idx+N4], c = p[idx+2*N4], d = p[idx+3*N4];
            float w0 = wt[row][h][0], w1 = wt[row][h][1],
                  w2 = wt[row][h][2], w3 = wt[row][h][3];
            ((float4*)xr[row])[c4] = make_float4(
                a.x*w0 + b4.x*w1 + c.x*w2 + d.x*w3,
                a.y*w0 + b4.y*w1 + c.y*w2 + d.y*w3,
                a.z*w0 + b4.z*w1 + c.z*w2 + d.z*w3,
                a.w*w0 + b4.w*w1 + c.w*w2 + d.w*w3);
        }
    } else {
        for (int i = tid; i < 8*(DD/4); i += 256) {
            int row = i >> 7, c4 = i & 127;
            int r = r0 + row;
            int b = r / TOPQ;
            const float* srow = src + ((size_t)b*SS + gidx[r]) * DD;
            ((float4*)xr[row])[c4] = ((const float4*)srow)[c4];
        }
    }
    __syncthreads();
    const int jj = blockIdx.x * 128 + (tid & 127);
    const int rh = (tid >> 7) * 4;
    const float4* w4 = (const float4*)(W + (size_t)jj*DD);
    float a0 = 0.f, a1 = 0.f, a2 = 0.f, a3 = 0.f;
    #pragma unroll 4
    for (int k = 0; k < DD/4; k++) {
        float4 w = w4[k];
        float4 x0 = ((float4*)xr[rh+0])[k];
        float4 x1 = ((float4*)xr[rh+1])[k];
        float4 x2 = ((float4*)xr[rh+2])[k];
        float4 x3 = ((float4*)xr[rh+3])[k];
        a0 = fmaf(w.x, x0.x, fmaf(w.y, x0.y, fmaf(w.z, x0.z, fmaf(w.w, x0.w, a0))));
        a1 = fmaf(w.x, x1.x, fmaf(w.y, x1.y, fmaf(w.z, x1.z, fmaf(w.w, x1.w, a1))));
        a2 = fmaf(w.x, x2.x, fmaf(w.y, x2.y, fmaf(w.z, x2.z, fmaf(w.w, x2.w, a2))));
        a3 = fmaf(w.x, x3.x, fmaf(w.y, x3.y, fmaf(w.z, x3.z, fmaf(w.w, x3.w, a3))));
    }
    float bv = bias[jj];
    out[(size_t)(r0 + rh + 0)*DD + jj] = a0 + bv;
    out[(size_t)(r0 + rh + 1)*DD + jj] = a1 + bv;
    out[(size_t)(r0 + rh + 2)*DD + jj] = a2 + bv;
    out[(size_t)(r0 + rh + 3)*DD + jj] = a3 + bv;
}

// ---------------- ratio tail ----------------
__global__ void ratio_kernel(float* out, int out_size)
{
    int i = NROWS*DD + blockIdx.x*blockDim.x + threadIdx.x;
    if (i < out_size) out[i] = (float)TOPQ / (float)SS;
}

// ---------------- launch (multi-stream fork/join) ----------------
extern "C" void kernel_launch(void* const* d_in, const int* in_sizes, int n_in,
                              void* d_out, int out_size)
{
    const float* x    = (const float*)d_in[0];
    const float* ln1g = (const float*)d_in[1];
    const float* ln1b = (const float*)d_in[2];
    const float* in_w = (const float*)d_in[3];
    const float* in_b = (const float*)d_in[4];
    const float* outw = (const float*)d_in[5];
    const float* outb = (const float*)d_in[6];
    const float* ln2g = (const float*)d_in[7];
    const float* ln2b = (const float*)d_in[8];
    const float* w1   = (const float*)d_in[9];
    const float* b1   = (const float*)d_in[10];
    const float* w2   = (const float*)d_in[11];
    const float* b2   = (const float*)d_in[12];
    float* out = (float*)d_out;

    float *xn, *x2, *cs, *csp, *sp, *qs, *ctxp, *aout;
    float2 *ml;
    __half *kvh, *xn16, *xn2h, *h1h, *wkv16, *w1h, *w2h;
    int *tidx;
    cudaGetSymbolAddress((void**)&xn,    g_xn);
    cudaGetSymbolAddress((void**)&x2,    g_x2);
    cudaGetSymbolAddress((void**)&cs,    g_cs);
    cudaGetSymbolAddress((void**)&csp,   g_csp2);
    cudaGetSymbolAddress((void**)&sp,    g_sp);
    cudaGetSymbolAddress((void**)&qs,    g_qs);
    cudaGetSymbolAddress((void**)&ctxp,  g_ctxp);
    cudaGetSymbolAddress((void**)&ml,    g_ml);
    cudaGetSymbolAddress((void**)&aout,  g_aout);
    cudaGetSymbolAddress((void**)&tidx,  g_tidx);
    cudaGetSymbolAddress((void**)&kvh,   g_kvh);
    cudaGetSymbolAddress((void**)&xn16,  g_xn16);
    cudaGetSymbolAddress((void**)&xn2h,  g_xn2h);
    cudaGetSymbolAddress((void**)&h1h,   g_h1h);
    cudaGetSymbolAddress((void**)&wkv16, g_wkv16);
    cudaGetSymbolAddress((void**)&w1h,   g_w1h);
    cudaGetSymbolAddress((void**)&w2h,   g_w2h);

    cudaFuncSetAttribute(hgemm<0, __half>, cudaFuncAttributeMaxDynamicSharedMemorySize, HG_SMEM);
    cudaFuncSetAttribute(hgemm<1, __half>, cudaFuncAttributeMaxDynamicSharedMemorySize, HG_SMEM);
    cudaFuncSetAttribute(hgemm<2, float>,  cudaFuncAttributeMaxDynamicSharedMemorySize, HG_SMEM);

    static cudaStream_t sA = nullptr, sB = nullptr;
    static cudaEvent_t eFork = nullptr, eF2h = nullptr, eCs1 = nullptr, eRank = nullptr;
    if (!sA) {
        cudaStreamCreateWithFlags(&sA, cudaStreamNonBlocking);
        cudaStreamCreateWithFlags(&sB, cudaStreamNonBlocking);
        cudaEventCreateWithFlags(&eFork, cudaEventDisableTiming);
        cudaEventCreateWithFlags(&eF2h,  cudaEventDisableTiming);
        cudaEventCreateWithFlags(&eCs1,  cudaEventDisableTiming);
        cudaEventCreateWithFlags(&eRank, cudaEventDisableTiming);
    }
    cudaStream_t m = 0;

    cudaEventRecord(eFork, m);
    cudaStreamWaitEvent(sA, eFork, 0);

    // sideA: weight conversions + ratio tail (off critical path)
    {
        int na4 = 2*DD*DD/4, nb4 = FF_*DD/4, nc4 = DD*FF_/4;
        f2h3_kernel<<<(na4+nb4+nc4 + 255)/256, 256, 0, sA>>>(
            in_w + (size_t)DD*DD, wkv16, na4, w1, w1h, nb4, w2, w2h, nc4);
        if (out_size > NROWS*DD) {
            int tail = out_size - NROWS*DD;
            ratio_kernel<<<(tail + 255)/256, 256, 0, sA>>>(out, out_size);
        }
        cudaEventRecord(eF2h, sA);
    }

    // main: layernorm1 with fused column-sum partials
    lnw_kernel<<<NBLK, 256, 0, m>>>(x, ln1g, ln1b, xn, xn16, csp);
    cudaEventRecord(eCs1, m);

    // sideB: ranking chain
    cudaStreamWaitEvent(sB, eCs1, 0);
    colsum2_kernel<<<(BB*DD + 255)/256, 256, 0, sB>>>(csp, cs);
    sparsw_kernel<<<NROWS/8, 256, 0, sB>>>(xn, cs, sp);
    topk_kernel<<<BB, 256, 0, sB>>>(sp, tidx);
    sproj_kernel<<<dim3(DD/128, 39), 256, 0, sB>>>(xn, tidx, nullptr, nullptr, in_w, in_b, qs);
    cudaEventRecord(eRank, sB);

    // main: KV projection
    cudaStreamWaitEvent(m, eF2h, 0);
    hgemm<0, __half><<<dim3((2*DD)/128, NROWS/128), 128, HG_SMEM, m>>>(
        xn16, wkv16, in_b + DD, nullptr, kvh, 2*DD, DD);

    // join: attention
    cudaStreamWaitEvent(m, eRank, 0);
    ctxflash_kernel<<<dim3(4, HH, BB), 256, 0, m>>>(qs, kvh, ctxp, ml);
    sproj_kernel<<<dim3(DD/128, 39), 256, 0, m>>>(nullptr, nullptr, ctxp, ml, outw, outb, aout);
    lnfuse_kernel<<<NROWS/8, 256, 0, m>>>(x, cs, aout, tidx, ln2g, ln2b, x2, xn2h);
    // FFN
    hgemm<1, __half><<<dim3(FF_/128, NROWS/128), 128, HG_SMEM, m>>>(
        xn2h, w1h, b1, nullptr, h1h, FF_, DD);
    hgemm<2, float><<<dim3(DD/128, NROWS/128), 128, HG_SMEM, m>>>(
        h1h, w2h, b2, x2, out, DD, FF_);
}

// round 14
// speedup vs baseline: 1.6155x; 1.0077x over previous
#include <cuda_runtime.h>
#include <cuda_fp16.h>
#include <math.h>
#include <stdint.h>

#define BB 8
#define SS 2048
#define DD 512
#define FF_ 2048
#define HH 8
#define DH 64
#define TOPQ 39
#define QPW 5
#define GS 8            /* attention split-K slices */
#define NROWS (BB*SS)
#define NBLK (NROWS/8)

// ---------------- static scratch ----------------
__device__ float g_xn  [NROWS*DD];
__device__ float g_x2  [NROWS*DD];
__device__ float g_cs  [BB*DD];
__device__ float g_csp2[(size_t)NBLK*DD];
__device__ float g_sp  [BB*SS];
__device__ int   g_tidx[BB*TOPQ];
__device__ float g_qs  [BB*TOPQ*DD];
__device__ float g_ctxp[(size_t)GS*BB*TOPQ*DD];
__device__ float2 g_ml [(size_t)GS*BB*HH*TOPQ];
__device__ float g_aout[BB*TOPQ*DD];
// fp16 operands
__device__ __half g_kvh  [NROWS*2*DD];
__device__ __half g_xn16 [NROWS*DD];
__device__ __half g_xn2h [NROWS*DD];
__device__ __half g_h1h  [(size_t)NROWS*FF_];
__device__ __half g_wkv16[2*DD*DD];
__device__ __half g_w1h  [FF_*DD];
__device__ __half g_w2h  [DD*FF_];

// ---------------- helpers ----------------
__device__ __forceinline__ uint32_t s2u(const void* p) {
    uint32_t a;
    asm("{ .reg .u64 t; cvta.to.shared.u64 t, %1; cvt.u32.u64 %0, t; }" : "=r"(a) : "l"(p));
    return a;
}
__device__ __forceinline__ void mma_f16(float* d, const uint32_t* a, const uint32_t* b) {
    asm volatile("mma.sync.aligned.m16n8k16.row.col.f32.f16.f16.f32 "
        "{%0,%1,%2,%3}, {%4,%5,%6,%7}, {%8,%9}, {%0,%1,%2,%3};"
        : "+f"(d[0]), "+f"(d[1]), "+f"(d[2]), "+f"(d[3])
        : "r"(a[0]), "r"(a[1]), "r"(a[2]), "r"(a[3]), "r"(b[0]), "r"(b[1]));
}
__device__ __forceinline__ void ldsm4(uint32_t* r, uint32_t addr) {
    asm volatile("ldmatrix.sync.aligned.m8n8.x4.shared.b16 {%0,%1,%2,%3}, [%4];"
        : "=r"(r[0]), "=r"(r[1]), "=r"(r[2]), "=r"(r[3]) : "r"(addr));
}
__device__ __forceinline__ void cpa16(uint32_t dst, const void* src) {
    asm volatile("cp.async.cg.shared.global [%0], [%1], 16;" :: "r"(dst), "l"(src));
}
__device__ __forceinline__ void cpcommit() {
    asm volatile("cp.async.commit_group;" ::: "memory");
}
template<int N> __device__ __forceinline__ void cpwait() {
    asm volatile("cp.async.wait_group %0;" :: "n"(N) : "memory");
}
__device__ __forceinline__ float gelu_f(float x) {
    return 0.5f * x * (1.0f + erff(x * 0.7071067811865476f));
}

// ====================================================================
// fp16 GEMM (structure unchanged from R13)
// ====================================================================
#define HG_SMEM (4*16384)

template<int EPI, typename OutT>
__global__ __launch_bounds__(128, 2) void hgemm(
    const __half* __restrict__ A, const __half* __restrict__ W,
    const float* __restrict__ bias, const float* __restrict__ res,
    OutT* __restrict__ C, int N, int K)
{
    extern __shared__ __align__(16) char smh[];
    const int tid  = threadIdx.x;
    const int lane = tid & 31;
    const int wid  = tid >> 5;
    const int wm   = wid >> 1;
    const int wn   = wid & 1;
    const int bm = blockIdx.y * 128;
    const int bn = blockIdx.x * 128;
    const uint32_t sb = s2u(smh);

    const __half* Ab = A + (size_t)bm * K;
    const __half* Wb = W + (size_t)bn * K;

    const int crow0 = tid >> 2;
    const int cunit = tid & 3;

    auto ISSUE = [&](int buf, int kbase) {
        uint32_t base = sb + buf * 16384;
        #pragma unroll
        for (int i = 0; i < 4; i++) {
            int row = crow0 + i * 32;
            uint32_t off = row*64 + ((cunit ^ (row&3))*16);
            cpa16(base + off,        Ab + (size_t)row*K + kbase + cunit*8);
            cpa16(base + 8192 + off, Wb + (size_t)row*K + kbase + cunit*8);
        }
        cpcommit();
    };

    float acc[4][8][4];
    #pragma unroll
    for (int a = 0; a < 4; a++)
        #pragma unroll
        for (int b = 0; b < 8; b++)
            #pragma unroll
            for (int c = 0; c < 4; c++) acc[a][b][c] = 0.f;

    const int nk = K >> 5;
    const int lm = lane >> 3;
    const int lr = lane & 7;

    ISSUE(0, 0);
    ISSUE(1, 32);
    ISSUE(2, 64);

    for (int kt = 0; kt < nk; kt++) {
        cpwait<2>();
        __syncthreads();
        if (kt + 3 < nk) ISSUE((kt + 3) & 3, (kt + 3) << 5);
        else             cpcommit();

        int buf = kt & 3;
        uint32_t Abase = sb + buf*16384;
        uint32_t Bbase = Abase + 8192;
        uint32_t af[2][4][4];
        uint32_t bf[2][8][2];
        #pragma unroll
        for (int s = 0; s < 2; s++) {
            #pragma unroll
            for (int mt = 0; mt < 4; mt++) {
                int row = wm*64 + mt*16 + (lm&1)*8 + lr;
                int unit = s*2 + (lm>>1);
                ldsm4(af[s][mt], Abase + row*64 + ((unit ^ (row&3))*16));
            }
            #pragma unroll
            for (int np = 0; np < 4; np++) {
                int nr = wn*64 + (np*2 + (lm>>1))*8 + lr;
                int unit = s*2 + (lm&1);
                uint32_t r[4];
                ldsm4(r, Bbase + nr*64 + ((unit ^ (nr&3))*16));
                bf[s][np*2][0] = r[0]; bf[s][np*2][1] = r[1];
                bf[s][np*2+1][0] = r[2]; bf[s][np*2+1][1] = r[3];
            }
        }
        #pragma unroll
        for (int s = 0; s < 2; s++)
            #pragma unroll
            for (int mt = 0; mt < 4; mt++)
                #pragma unroll
                for (int nt = 0; nt < 8; nt++)
                    mma_f16(acc[mt][nt], af[s][mt], bf[s][nt]);
    }

    const int g = lane >> 2, t = lane & 3;
    #pragma unroll
    for (int mt = 0; mt < 4; mt++) {
        int row0 = bm + wm*64 + mt*16 + g;
        #pragma unroll
        for (int nt = 0; nt < 8; nt++) {
            int col = bn + wn*64 + nt*8 + 2*t;
            float b0 = bias[col], b1 = bias[col+1];
            float v0 = acc[mt][nt][0] + b0;
            float v1 = acc[mt][nt][1] + b1;
            float v2 = acc[mt][nt][2] + b0;
            float v3 = acc[mt][nt][3] + b1;
            if (EPI == 1) {
                v0 = gelu_f(v0); v1 = gelu_f(v1); v2 = gelu_f(v2); v3 = gelu_f(v3);
            }
            if (EPI == 2) {
                const float* r0 = res + (size_t)row0*N + col;
                const float* r1 = res + (size_t)(row0+8)*N + col;
                v0 += r0[0]; v1 += r0[1]; v2 += r1[0]; v3 += r1[1];
            }
            if constexpr (sizeof(OutT) == 2) {
                *(__half2*)&C[(size_t)row0*N + col]     = __floats2half2_rn(v0, v1);
                *(__half2*)&C[(size_t)(row0+8)*N + col] = __floats2half2_rn(v2, v3);
            } else {
                *(float2*)&C[(size_t)row0*N + col]     = make_float2(v0, v1);
                *(float2*)&C[(size_t)(row0+8)*N + col] = make_float2(v2, v3);
            }
        }
    }
}

// ---------------- fp32 -> fp16 bulk convert ----------------
__global__ void f2h3_kernel(const float* __restrict__ a, __half* __restrict__ da, int na4,
                            const float* __restrict__ b, __half* __restrict__ db, int nb4,
                            const float* __restrict__ c, __half* __restrict__ dc, int nc4)
{
    int i = blockIdx.x * 256 + threadIdx.x;
    const float* s; __half* d; int j = i;
    if (j < na4) { s = a; d = da; }
    else {
        j -= na4;
        if (j < nb4) { s = b; d = db; }
        else { j -= nb4; if (j >= nc4) return; s = c; d = dc; }
    }
    float4 v = ((const float4*)s)[j];
    ((__half2*)d)[2*j]   = __floats2half2_rn(v.x, v.y);
    ((__half2*)d)[2*j+1] = __floats2half2_rn(v.z, v.w);
}

// ---------------- layernorm1 + fused column partials ----------------
__global__ __launch_bounds__(256) void lnw_kernel(const float* __restrict__ x,
        const float* __restrict__ g, const float* __restrict__ bb,
        float* __restrict__ out, __half* __restrict__ out16,
        float* __restrict__ csp)
{
    int blk  = blockIdx.x;
    int row  = blk * 8 + (threadIdx.x >> 5);
    int lane = threadIdx.x & 31;
    __shared__ float cbuf[8][DD];
    const float4* xr = (const float4*)x + (size_t)row*(DD/4);
    float4 v[4];
    #pragma unroll
    for (int j = 0; j < 4; j++) v[j] = xr[lane + 32*j];
    float s = 0.f;
    #pragma unroll
    for (int j = 0; j < 4; j++) s += v[j].x + v[j].y + v[j].z + v[j].w;
    #pragma unroll
    for (int o = 16; o > 0; o >>= 1) s += __shfl_xor_sync(0xffffffffu, s, o);
    float mean = s * (1.0f/DD);
    float q = 0.f;
    #pragma unroll
    for (int j = 0; j < 4; j++) {
        float a = v[j].x-mean, b = v[j].y-mean, c = v[j].z-mean, d = v[j].w-mean;
        q += a*a + b*b + c*c + d*d;
    }
    #pragma unroll
    for (int o = 16; o > 0; o >>= 1) q += __shfl_xor_sync(0xffffffffu, q, o);
    float inv = rsqrtf(q * (1.0f/DD) + 1e-5f);
    #pragma unroll
    for (int j = 0; j < 4; j++) {
        float4 gg = ((const float4*)g)[lane + 32*j];
        float4 bv = ((const float4*)bb)[lane + 32*j];
        float4 o4 = make_float4(
            (v[j].x-mean)*inv*gg.x + bv.x, (v[j].y-mean)*inv*gg.y + bv.y,
            (v[j].z-mean)*inv*gg.z + bv.z, (v[j].w-mean)*inv*gg.w + bv.w);
        if (out) ((float4*)out)[(size_t)row*(DD/4) + lane + 32*j] = o4;
        if (out16) {
            int base = (int)(lane + 32*j);
            ((__half2*)(out16 + (size_t)row*DD))[2*base]   = __floats2half2_rn(o4.x, o4.y);
            ((__half2*)(out16 + (size_t)row*DD))[2*base+1] = __floats2half2_rn(o4.z, o4.w);
        }
        if (csp) ((float4*)cbuf[threadIdx.x >> 5])[lane + 32*j] = o4;
    }
    if (csp) {
        __syncthreads();
        #pragma unroll
        for (int cc = 0; cc < 2; cc++) {
            int col = threadIdx.x + cc * 256;
            float acc = cbuf[0][col];
            #pragma unroll
            for (int r2 = 1; r2 < 8; r2++) acc += cbuf[r2][col];
            csp[(size_t)blk*DD + col] = acc;
        }
    }
}

// ---------------- colsum2: 4 threads per column, deterministic tree --------
__global__ __launch_bounds__(256) void colsum2_kernel(const float* __restrict__ csp,
        float* __restrict__ cs)
{
    // grid 64 blocks; block handles 64 columns of BB*DD.
    int cloc = threadIdx.x >> 2;          // 0..63 column within block
    int t4   = threadIdx.x & 3;           // 0..3
    int i    = blockIdx.x * 64 + cloc;    // global (b,d) index
    int b = i >> 9, d = i & (DD-1);
    const float* p = csp + (size_t)(b*256)*DD + d;
    float s = 0.f;
    for (int k = t4; k < 256; k += 4) s += p[(size_t)k*DD];
    __shared__ float red[64][4];
    red[cloc][t4] = s;
    __syncthreads();
    if (t4 == 0)
        cs[i] = red[cloc][0] + red[cloc][1] + red[cloc][2] + red[cloc][3];
}

// ---------------- lnbase: residual with base everywhere + LN2 --------------
__global__ __launch_bounds__(256) void lnbase_kernel(const float* __restrict__ x,
        const float* __restrict__ cs,
        const float* __restrict__ g, const float* __restrict__ bb,
        float* __restrict__ x2, __half* __restrict__ out16)
{
    int row  = blockIdx.x * 8 + (threadIdx.x >> 5);
    int lane = threadIdx.x & 31;
    int b    = row >> 11;
    const float4* xr = (const float4*)x + (size_t)row*(DD/4);
    const float4* cr = (const float4*)cs + b*(DD/4);
    const float r = 1.0f / SS;
    float4 v[4];
    #pragma unroll
    for (int j = 0; j < 4; j++) {
        v[j] = xr[lane + 32*j];
        float4 c = cr[lane + 32*j];
        v[j].x += c.x*r; v[j].y += c.y*r; v[j].z += c.z*r; v[j].w += c.w*r;
    }
    #pragma unroll
    for (int j = 0; j < 4; j++)
        ((float4*)x2)[(size_t)row*(DD/4) + lane + 32*j] = v[j];
    float s = 0.f;
    #pragma unroll
    for (int j = 0; j < 4; j++) s += v[j].x + v[j].y + v[j].z + v[j].w;
    #pragma unroll
    for (int o = 16; o > 0; o >>= 1) s += __shfl_xor_sync(0xffffffffu, s, o);
    float mean = s * (1.0f/DD);
    float q = 0.f;
    #pragma unroll
    for (int j = 0; j < 4; j++) {
        float a = v[j].x-mean, bq = v[j].y-mean, c = v[j].z-mean, d = v[j].w-mean;
        q += a*a + bq*bq + c*c + d*d;
    }
    #pragma unroll
    for (int o = 16; o > 0; o >>= 1) q += __shfl_xor_sync(0xffffffffu, q, o);
    float inv = rsqrtf(q * (1.0f/DD) + 1e-5f);
    #pragma unroll
    for (int j = 0; j < 4; j++) {
        float4 gg = ((const float4*)g)[lane + 32*j];
        float4 bv = ((const float4*)bb)[lane + 32*j];
        float4 o4 = make_float4(
            (v[j].x-mean)*inv*gg.x + bv.x, (v[j].y-mean)*inv*gg.y + bv.y,
            (v[j].z-mean)*inv*gg.z + bv.z, (v[j].w-mean)*inv*gg.w + bv.w);
        int base = (int)(lane + 32*j);
        ((__half2*)(out16 + (size_t)row*DD))[2*base]   = __floats2half2_rn(o4.x, o4.y);
        ((__half2*)(out16 + (size_t)row*DD))[2*base+1] = __floats2half2_rn(o4.z, o4.w);
    }
}

// ---------------- lnfix: redo the 312 top-k rows with attn residual --------
__global__ __launch_bounds__(256) void lnfix_kernel(const float* __restrict__ x,
        const float* __restrict__ aout, const int* __restrict__ tidx,
        const float* __restrict__ g, const float* __restrict__ bb,
        float* __restrict__ x2, __half* __restrict__ out16)
{
    int r    = blockIdx.x * 8 + (threadIdx.x >> 5);   // 0..311
    int lane = threadIdx.x & 31;
    int b    = r / TOPQ;
    int row  = b*SS + tidx[r];
    const float4* xr = (const float4*)x + (size_t)row*(DD/4);
    const float4* ar = (const float4*)aout + (size_t)r*(DD/4);
    float4 v[4];
    #pragma unroll
    for (int j = 0; j < 4; j++) {
        v[j] = xr[lane + 32*j];
        float4 a = ar[lane + 32*j];
        v[j].x += a.x; v[j].y += a.y; v[j].z += a.z; v[j].w += a.w;
    }
    #pragma unroll
    for (int j = 0; j < 4; j++)
        ((float4*)x2)[(size_t)row*(DD/4) + lane + 32*j] = v[j];
    float s = 0.f;
    #pragma unroll
    for (int j = 0; j < 4; j++) s += v[j].x + v[j].y + v[j].z + v[j].w;
    #pragma unroll
    for (int o = 16; o > 0; o >>= 1) s += __shfl_xor_sync(0xffffffffu, s, o);
    float mean = s * (1.0f/DD);
    float q = 0.f;
    #pragma unroll
    for (int j = 0; j < 4; j++) {
        float a = v[j].x-mean, bq = v[j].y-mean, c = v[j].z-mean, d = v[j].w-mean;
        q += a*a + bq*bq + c*c + d*d;
    }
    #pragma unroll
    for (int o = 16; o > 0; o >>= 1) q += __shfl_xor_sync(0xffffffffu, q, o);
    float inv = rsqrtf(q * (1.0f/DD) + 1e-5f);
    #pragma unroll
    for (int j = 0; j < 4; j++) {
        float4 gg = ((const float4*)g)[lane + 32*j];
        float4 bv = ((const float4*)bb)[lane + 32*j];
        float4 o4 = make_float4(
            (v[j].x-mean)*inv*gg.x + bv.x, (v[j].y-mean)*inv*gg.y + bv.y,
            (v[j].z-mean)*inv*gg.z + bv.z, (v[j].w-mean)*inv*gg.w + bv.w);
        int base = (int)(lane + 32*j);
        ((__half2*)(out16 + (size_t)row*DD))[2*base]   = __floats2half2_rn(o4.x, o4.y);
        ((__half2*)(out16 + (size_t)row*DD))[2*base+1] = __floats2half2_rn(o4.z, o4.w);
    }
}

// ---------------- sparsity ----------------
__global__ __launch_bounds__(256) void sparsw_kernel(const float* __restrict__ xn,
        const float* __restrict__ cs, float* __restrict__ sp)
{
    int row  = blockIdx.x * 8 + (threadIdx.x >> 5);
    int lane = threadIdx.x & 31;
    int b = row >> 11;
    const float4* xr = (const float4*)xn + (size_t)row*(DD/4);
    const float4* cr = (const float4*)cs + b*(DD/4);
    float dp = 0.f, de = 0.f, mp = 0.f, me = 0.f;
    #pragma unroll
    for (int j = 0; j < 4; j++) {
        float4 v = xr[lane + 32*j];
        float4 c = cr[lane + 32*j];
        float vv[4] = {v.x, v.y, v.z, v.w};
        float cc[4] = {c.x, c.y, c.z, c.w};
        #pragma unroll
        for (int e = 0; e < 4; e++) {
            float p = vv[e]*vv[e];
            de += fmaf(vv[e], vv[e], -p);
            dp += p;
            float q = vv[e]*cc[e];
            me += fmaf(vv[e], cc[e], -q);
            mp += q;
        }
    }
    double dd = (double)dp + (double)de;
    double dm = (double)mp + (double)me;
    #pragma unroll
    for (int o = 16; o > 0; o >>= 1) {
        dd += __shfl_xor_sync(0xffffffffu, dd, o);
        dm += __shfl_xor_sync(0xffffffffu, dm, o);
    }
    if (lane == 0)
        sp[row] = (float)((dd - dm * (1.0/SS)) * 0.04419417382415922);
}

// ---------------- top-39 ----------------
__global__ __launch_bounds__(256) void topk_kernel(const float* __restrict__ sp,
        int* __restrict__ tidx)
{
    int b = blockIdx.x;
    int t = threadIdx.x;
    __shared__ float sv[SS];
    __shared__ float rbv[8];
    __shared__ int   rbi[8];
    for (int i = t; i < SS; i += 256) sv[i] = sp[b*SS + i];
    __syncthreads();
    for (int sel = 0; sel < TOPQ; ++sel) {
        float bv = -3.0e38f; int bi = 0;
        for (int i = t; i < SS; i += 256) {
            float v = sv[i];
            if (v > bv || (v == bv && i < bi)) { bv = v; bi = i; }
        }
        #pragma unroll
        for (int o = 16; o > 0; o >>= 1) {
            float ov = __shfl_down_sync(0xffffffffu, bv, o);
            int   oi = __shfl_down_sync(0xffffffffu, bi, o);
            if (ov > bv || (ov == bv && oi < bi)) { bv = ov; bi = oi; }
        }
        if ((t & 31) == 0) { rbv[t >> 5] = bv; rbi[t >> 5] = bi; }
        __syncthreads();
        if (t == 0) {
            float fv = rbv[0]; int fi = rbi[0];
            #pragma unroll
            for (int w = 1; w < 8; w++)
                if (rbv[w] > fv || (rbv[w] == fv && rbi[w] < fi)) { fv = rbv[w]; fi = rbi[w]; }
            tidx[b*TOPQ + sel] = fi;
            sv[fi] = -3.4e38f;
        }
        __syncthreads();
    }
}

// ---------------- flash attention: GS split-K slices ----------------
__global__ __launch_bounds__(256) void ctxflash_kernel(
    const float* __restrict__ qs, const __half* __restrict__ kvh,
    float* __restrict__ part, float2* __restrict__ ml)
{
    int g = blockIdx.x, h = blockIdx.y, b = blockIdx.z;
    int tid = threadIdx.x, w = tid >> 5, lane = tid & 31;
    __shared__ __half Kt[64][66];
    __shared__ __half Vs[64][64];
    __shared__ float  Qt[64][40];
    __shared__ float  Pw[8][QPW][64];

    for (int i = tid; i < TOPQ*DH; i += 256) {
        int q = i >> 6, d = i & 63;
        Qt[d][q] = qs[((size_t)(b*TOPQ + q))*DD + h*DH + d];
    }
    float2 acc[QPW];
    float m_run[QPW], l_run[QPW];
    #pragma unroll
    for (int iq = 0; iq < QPW; iq++) {
        acc[iq] = make_float2(0.f, 0.f); m_run[iq] = -3.0e38f; l_run[iq] = 0.f;
    }
    __syncthreads();

    const int TS = SS / GS / 64;    // 4 t-iterations per slice
    for (int t = 0; t < TS; t++) {
        int k0 = g*(SS/GS) + t*64;
        for (int i = tid; i < 64*32; i += 256) {
            int k = i >> 5, dp = i & 31;
            const __half2* src = (const __half2*)(kvh + ((size_t)(b*SS + k0 + k))*(2*DD) + h*DH) + dp;
            __half2 kk = src[0];
            Kt[2*dp][k]   = __low2half(kk);
            Kt[2*dp+1][k] = __high2half(kk);
            *(__half2*)&Vs[k][2*dp] = src[DD/2];
        }
        __syncthreads();
        #pragma unroll
        for (int iq = 0; iq < QPW; iq++) {
            int q = w + 8*iq;
            if (q < TOPQ) {
                float s0 = 0.f, s1 = 0.f;
                #pragma unroll 8
                for (int d = 0; d < DH; d++) {
                    float qv = Qt[d][q];
                    float2 kk = __half22float2(*(const __half2*)&Kt[d][2*lane]);
                    s0 = fmaf(qv, kk.x, s0);
                    s1 = fmaf(qv, kk.y, s1);
                }
                s0 *= 0.125f; s1 *= 0.125f;
                float mt = fmaxf(s0, s1);
                #pragma unroll
                for (int o = 16; o > 0; o >>= 1)
                    mt = fmaxf(mt, __shfl_xor_sync(0xffffffffu, mt, o));
                float mnew = fmaxf(m_run[iq], mt);
                float p0 = __expf(s0 - mnew), p1 = __expf(s1 - mnew);
                float ps = p0 + p1;
                #pragma unroll
                for (int o = 16; o > 0; o >>= 1)
                    ps += __shfl_xor_sync(0xffffffffu, ps, o);
                float scale = __expf(m_run[iq] - mnew);
                l_run[iq] = l_run[iq]*scale + ps;
                m_run[iq] = mnew;
                Pw[w][iq][2*lane]   = p0;
                Pw[w][iq][2*lane+1] = p1;
                acc[iq].x *= scale; acc[iq].y *= scale;
                __syncwarp();
                #pragma unroll 8
                for (int k = 0; k < 64; k++) {
                    float pv = Pw[w][iq][k];
                    float2 vv = __half22float2(*(const __half2*)&Vs[k][2*lane]);
                    acc[iq].x = fmaf(pv, vv.x, acc[iq].x);
                    acc[iq].y = fmaf(pv, vv.y, acc[iq].y);
                }
            }
        }
        __syncthreads();
    }
    #pragma unroll
    for (int iq = 0; iq < QPW; iq++) {
        int q = w + 8*iq;
        if (q < TOPQ) {
            float* dst = part + (size_t)g*(BB*TOPQ*DD) + ((size_t)(b*TOPQ + q))*DD + h*DH + 2*lane;
            *(float2*)dst = acc[iq];
            if (lane == 0)
                ml[((size_t)(g*BB + b)*HH + h)*TOPQ + q] = make_float2(m_run[iq], l_run[iq]);
        }
    }
}

// ---------------- small projection (gather / GS-way flash-combine) ---------
__global__ __launch_bounds__(256) void sproj_kernel(const float* __restrict__ src,
        const int* __restrict__ gidx, const float* __restrict__ part,
        const float2* __restrict__ ml,
        const float* __restrict__ W, const float* __restrict__ bias,
        float* __restrict__ out)
{
    const int r0 = blockIdx.y * 8;
    const int tid = threadIdx.x;
    __shared__ float xr[8][DD];
    __shared__ float wt[8][HH][GS];
    if (part) {
        if (tid < 64) {
            int row = tid >> 3, h = tid & 7;
            int r = r0 + row;
            int b = r / TOPQ, q = r % TOPQ;
            float m[GS], l[GS];
            #pragma unroll
            for (int g = 0; g < GS; g++) {
                float2 v = ml[((size_t)(g*BB + b)*HH + h)*TOPQ + q];
                m[g] = v.x; l[g] = v.y;
            }
            float M = m[0];
            #pragma unroll
            for (int g = 1; g < GS; g++) M = fmaxf(M, m[g]);
            float e[GS], L = 0.f;
            #pragma unroll
            for (int g = 0; g < GS; g++) { e[g] = __expf(m[g] - M); L += l[g]*e[g]; }
            float invL = 1.0f / L;
            #pragma unroll
            for (int g = 0; g < GS; g++) wt[row][h][g] = e[g]*invL;
        }
        __syncthreads();
        const int N4 = BB*TOPQ*DD/4;
        const float4* p = (const float4*)part;
        for (int i = tid; i < 8*(DD/4); i += 256) {
            int row = i >> 7, c4 = i & 127;
            int h = c4 >> 4;
            size_t idx = (size_t)(r0 + row)*(DD/4) + c4;
            float4 o4 = make_float4(0.f, 0.f, 0.f, 0.f);
            #pragma unroll
            for (int g = 0; g < GS; g++) {
                float4 a = p[idx + (size_t)g*N4];
                float wg = wt[row][h][g];
                o4.x = fmaf(a.x, wg, o4.x);
                o4.y = fmaf(a.y, wg, o4.y);
                o4.z = fmaf(a.z, wg, o4.z);
                o4.w = fmaf(a.w, wg, o4.w);
            }
            ((float4*)xr[row])[c4] = o4;
        }
    } else {
        for (int i = tid; i < 8*(DD/4); i += 256) {
            int row = i >> 7, c4 = i & 127;
            int r = r0 + row;
            int b = r / TOPQ;
            const float* srow = src + ((size_t)b*SS + gidx[r]) * DD;
            ((float4*)xr[row])[c4] = ((const float4*)srow)[c4];
        }
    }
    __syncthreads();
    const int jj = blockIdx.x * 128 + (tid & 127);
    const int rh = (tid >> 7) * 4;
    const float4* w4 = (const float4*)(W + (size_t)jj*DD);
    float a0 = 0.f, a1 = 0.f, a2 = 0.f, a3 = 0.f;
    #pragma unroll 4
    for (int k = 0; k < DD/4; k++) {
        float4 w = w4[k];
        float4 x0 = ((float4*)xr[rh+0])[k];
        float4 x1 = ((float4*)xr[rh+1])[k];
        float4 x2 = ((float4*)xr[rh+2])[k];
        float4 x3 = ((float4*)xr[rh+3])[k];
        a0 = fmaf(w.x, x0.x, fmaf(w.y, x0.y, fmaf(w.z, x0.z, fmaf(w.w, x0.w, a0))));
        a1 = fmaf(w.x, x1.x, fmaf(w.y, x1.y, fmaf(w.z, x1.z, fmaf(w.w, x1.w, a1))));
        a2 = fmaf(w.x, x2.x, fmaf(w.y, x2.y, fmaf(w.z, x2.z, fmaf(w.w, x2.w, a2))));
        a3 = fmaf(w.x, x3.x, fmaf(w.y, x3.y, fmaf(w.z, x3.z, fmaf(w.w, x3.w, a3))));
    }
    float bv = bias[jj];
    out[(size_t)(r0 + rh + 0)*DD + jj] = a0 + bv;
    out[(size_t)(r0 + rh + 1)*DD + jj] = a1 + bv;
    out[(size_t)(r0 + rh + 2)*DD + jj] = a2 + bv;
    out[(size_t)(r0 + rh + 3)*DD + jj] = a3 + bv;
}

// ---------------- ratio tail ----------------
__global__ void ratio_kernel(float* out, int out_size)
{
    int i = NROWS*DD + blockIdx.x*blockDim.x + threadIdx.x;
    if (i < out_size) out[i] = (float)TOPQ / (float)SS;
}

// ---------------- launch ----------------
extern "C" void kernel_launch(void* const* d_in, const int* in_sizes, int n_in,
                              void* d_out, int out_size)
{
    const float* x    = (const float*)d_in[0];
    const float* ln1g = (const float*)d_in[1];
    const float* ln1b = (const float*)d_in[2];
    const float* in_w = (const float*)d_in[3];
    const float* in_b = (const float*)d_in[4];
    const float* outw = (const float*)d_in[5];
    const float* outb = (const float*)d_in[6];
    const float* ln2g = (const float*)d_in[7];
    const float* ln2b = (const float*)d_in[8];
    const float* w1   = (const float*)d_in[9];
    const float* b1   = (const float*)d_in[10];
    const float* w2   = (const float*)d_in[11];
    const float* b2   = (const float*)d_in[12];
    float* out = (float*)d_out;

    float *xn, *x2, *cs, *csp, *sp, *qs, *ctxp, *aout;
    float2 *ml;
    __half *kvh, *xn16, *xn2h, *h1h, *wkv16, *w1h, *w2h;
    int *tidx;
    cudaGetSymbolAddress((void**)&xn,    g_xn);
    cudaGetSymbolAddress((void**)&x2,    g_x2);
    cudaGetSymbolAddress((void**)&cs,    g_cs);
    cudaGetSymbolAddress((void**)&csp,   g_csp2);
    cudaGetSymbolAddress((void**)&sp,    g_sp);
    cudaGetSymbolAddress((void**)&qs,    g_qs);
    cudaGetSymbolAddress((void**)&ctxp,  g_ctxp);
    cudaGetSymbolAddress((void**)&ml,    g_ml);
    cudaGetSymbolAddress((void**)&aout,  g_aout);
    cudaGetSymbolAddress((void**)&tidx,  g_tidx);
    cudaGetSymbolAddress((void**)&kvh,   g_kvh);
    cudaGetSymbolAddress((void**)&xn16,  g_xn16);
    cudaGetSymbolAddress((void**)&xn2h,  g_xn2h);
    cudaGetSymbolAddress((void**)&h1h,   g_h1h);
    cudaGetSymbolAddress((void**)&wkv16, g_wkv16);
    cudaGetSymbolAddress((void**)&w1h,   g_w1h);
    cudaGetSymbolAddress((void**)&w2h,   g_w2h);

    cudaFuncSetAttribute(hgemm<0, __half>, cudaFuncAttributeMaxDynamicSharedMemorySize, HG_SMEM);
    cudaFuncSetAttribute(hgemm<1, __half>, cudaFuncAttributeMaxDynamicSharedMemorySize, HG_SMEM);
    cudaFuncSetAttribute(hgemm<2, float>,  cudaFuncAttributeMaxDynamicSharedMemorySize, HG_SMEM);

    static cudaStream_t sA = nullptr, sB = nullptr;
    static cudaEvent_t eFork = nullptr, eF2h = nullptr, eCs1 = nullptr,
                       eCs2 = nullptr, eRank = nullptr, eBase = nullptr;
    if (!sA) {
        cudaStreamCreateWithFlags(&sA, cudaStreamNonBlocking);
        cudaStreamCreateWithFlags(&sB, cudaStreamNonBlocking);
        cudaEventCreateWithFlags(&eFork, cudaEventDisableTiming);
        cudaEventCreateWithFlags(&eF2h,  cudaEventDisableTiming);
        cudaEventCreateWithFlags(&eCs1,  cudaEventDisableTiming);
        cudaEventCreateWithFlags(&eCs2,  cudaEventDisableTiming);
        cudaEventCreateWithFlags(&eRank, cudaEventDisableTiming);
        cudaEventCreateWithFlags(&eBase, cudaEventDisableTiming);
    }
    cudaStream_t m = 0;

    cudaEventRecord(eFork, m);
    cudaStreamWaitEvent(sA, eFork, 0);

    // sideA: weight conversions + ratio (off critical path)
    {
        int na4 = 2*DD*DD/4, nb4 = FF_*DD/4, nc4 = DD*FF_/4;
        f2h3_kernel<<<(na4+nb4+nc4 + 255)/256, 256, 0, sA>>>(
            in_w + (size_t)DD*DD, wkv16, na4, w1, w1h, nb4, w2, w2h, nc4);
        if (out_size > NROWS*DD) {
            int tail = out_size - NROWS*DD;
            ratio_kernel<<<(tail + 255)/256, 256, 0, sA>>>(out, out_size);
        }
        cudaEventRecord(eF2h, sA);
    }

    // main: layernorm1 with fused column partials
    lnw_kernel<<<NBLK, 256, 0, m>>>(x, ln1g, ln1b, xn, xn16, csp);
    cudaEventRecord(eCs1, m);

    // sideB: ranking chain
    cudaStreamWaitEvent(sB, eCs1, 0);
    colsum2_kernel<<<64, 256, 0, sB>>>(csp, cs);
    cudaEventRecord(eCs2, sB);
    sparsw_kernel<<<NROWS/8, 256, 0, sB>>>(xn, cs, sp);
    topk_kernel<<<BB, 256, 0, sB>>>(sp, tidx);
    sproj_kernel<<<dim3(DD/128, 39), 256, 0, sB>>>(xn, tidx, nullptr, nullptr, in_w, in_b, qs);
    cudaEventRecord(eRank, sB);

    // sideA (continued): base residual + LN2 for all rows (needs cs)
    cudaStreamWaitEvent(sA, eCs2, 0);
    lnbase_kernel<<<NROWS/8, 256, 0, sA>>>(x, cs, ln2g, ln2b, x2, xn2h);
    cudaEventRecord(eBase, sA);

    // main: KV projection
    cudaStreamWaitEvent(m, eF2h, 0);
    hgemm<0, __half><<<dim3((2*DD)/128, NROWS/128), 128, HG_SMEM, m>>>(
        xn16, wkv16, in_b + DD, nullptr, kvh, 2*DD, DD);

    // join: attention
    cudaStreamWaitEvent(m, eRank, 0);
    ctxflash_kernel<<<dim3(GS, HH, BB), 256, 0, m>>>(qs, kvh, ctxp, ml);
    sproj_kernel<<<dim3(DD/128, 39), 256, 0, m>>>(nullptr, nullptr, ctxp, ml, outw, outb, aout);
    // fix the 312 top-k rows (312 = 39 blocks x 8 warps)
    lnfix_kernel<<<39, 256, 0, m>>>(x, aout, tidx, ln2g, ln2b, x2, xn2h);
    // FFN (needs lnbase done too)
    cudaStreamWaitEvent(m, eBase, 0);
    hgemm<1, __half><<<dim3(FF_/128, NROWS/128), 128, HG_SMEM, m>>>(
        xn2h, w1h, b1, nullptr, h1h, FF_, DD);
    hgemm<2, float><<<dim3(DD/128, NROWS/128), 128, HG_SMEM, m>>>(
        h1h, w2h, b2, x2, out, DD, FF_);
}